// round 1
// baseline (speedup 1.0000x reference)
#include <cuda_runtime.h>
#include <math_constants.h>

#define Bq  4
#define Tt  2048
#define Dd  2048
#define Hh  16
#define DHd 128
#define Mm  (Bq * Tt)        // 8192
#define SCALE 0.08838834764831845f  // DH^-0.5

// Scratch (allocation-free rule: __device__ globals)
__device__ __align__(256) float g_q[Bq * Hh * Tt * DHd];
__device__ __align__(256) float g_k[Bq * Hh * Tt * DHd];
__device__ __align__(256) float g_v[Bq * Hh * Tt * DHd];
__device__ __align__(256) float g_att[Bq * Tt * Dd];

// ---------------------------------------------------------------------------
// Tiled fp32 GEMM: C[M,N] = A[M,K] * W[K,N] + bias
// MODE 0/1/2: write into g_q/g_k/g_v with [B,H,T,DH] head-split layout
// MODE 3:     write plain row-major into Cout
// BM=BN=64, BK=16, 256 threads, 4x4 micro-tile per thread.
// ---------------------------------------------------------------------------
template <int MODE>
__global__ __launch_bounds__(256)
void gemm64(const float* __restrict__ A, const float* __restrict__ W,
            const float* __restrict__ bias, float* __restrict__ Cout)
{
    const int N = Dd, K = Dd;
    __shared__ float As[16][68];   // k-major: As[kk][row]
    __shared__ float Bs[16][68];   // Bs[kk][col]

    const int n0 = blockIdx.x * 64;
    const int m0 = blockIdx.y * 64;
    const int tid = threadIdx.x;
    const int tx = tid & 15;
    const int ty = tid >> 4;

    float acc[4][4];
#pragma unroll
    for (int i = 0; i < 4; i++)
#pragma unroll
        for (int j = 0; j < 4; j++) acc[i][j] = 0.f;

    for (int k0 = 0; k0 < K; k0 += 16) {
        // Load A tile 64x16 (transposed into smem)
#pragma unroll
        for (int l = 0; l < 4; l++) {
            int e = tid + l * 256;
            int r = e >> 4, c = e & 15;
            As[c][r] = A[(m0 + r) * K + k0 + c];
        }
        // Load W tile 16x64
#pragma unroll
        for (int l = 0; l < 4; l++) {
            int e = tid + l * 256;
            int r = e >> 6, c = e & 63;
            Bs[r][c] = W[(k0 + r) * N + n0 + c];
        }
        __syncthreads();

#pragma unroll
        for (int kk = 0; kk < 16; kk++) {
            float4 a4 = *(const float4*)&As[kk][ty * 4];
            float4 b4 = *(const float4*)&Bs[kk][tx * 4];
            float av[4] = {a4.x, a4.y, a4.z, a4.w};
            float bv[4] = {b4.x, b4.y, b4.z, b4.w};
#pragma unroll
            for (int i = 0; i < 4; i++)
#pragma unroll
                for (int j = 0; j < 4; j++)
                    acc[i][j] = fmaf(av[i], bv[j], acc[i][j]);
        }
        __syncthreads();
    }

    // bias (columns n0 + tx*4 .. +3)
    float4 bb = *(const float4*)&bias[n0 + tx * 4];
    float bcol[4] = {bb.x, bb.y, bb.z, bb.w};

    if (MODE == 3) {
#pragma unroll
        for (int i = 0; i < 4; i++) {
            int m = m0 + ty * 4 + i;
            float4 v;
            v.x = acc[i][0] + bcol[0];
            v.y = acc[i][1] + bcol[1];
            v.z = acc[i][2] + bcol[2];
            v.w = acc[i][3] + bcol[3];
            *(float4*)&Cout[m * N + n0 + tx * 4] = v;
        }
    } else {
        float* dst = (MODE == 0) ? g_q : (MODE == 1) ? g_k : g_v;
        const int h = n0 >> 7;                 // 64-col tile never crosses a head
        const int d0 = (n0 & 127) + tx * 4;
#pragma unroll
        for (int i = 0; i < 4; i++) {
            int m = m0 + ty * 4 + i;
            int b = m >> 11;                   // m / T
            int t = m & 2047;                  // m % T
            float4 v;
            v.x = acc[i][0] + bcol[0];
            v.y = acc[i][1] + bcol[1];
            v.z = acc[i][2] + bcol[2];
            v.w = acc[i][3] + bcol[3];
            *(float4*)&dst[(((b * Hh + h) * Tt) + t) * DHd + d0] = v;
        }
    }
}

// ---------------------------------------------------------------------------
// Flash attention (causal), fp32. One CTA per (b, h, 64-query block).
// BM=BN=64, DH=128. 256 threads. Online softmax.
// Output written in [B, T, D] layout into g_att.
// ---------------------------------------------------------------------------
__global__ __launch_bounds__(256)
void flash_kernel()
{
    extern __shared__ float sm[];
    float* Qs   = sm;                    // [128][68] (d-major, transposed)
    float* Ks   = Qs + 128 * 68;         // [128][68]
    float* Vs   = Ks + 128 * 68;         // [64][132]
    float* Ss   = Vs + 64 * 132;         // [64][68]
    float* mrow = Ss + 64 * 68;          // [64]
    float* lrow = mrow + 64;             // [64]
    float* arow = lrow + 64;             // [64]

    const int qb = blockIdx.x;
    const int h  = blockIdx.y;
    const int b  = blockIdx.z;
    const int q0 = qb * 64;

    const int tid  = threadIdx.x;
    const int tx   = tid & 15;
    const int ty   = tid >> 4;
    const int w    = tid >> 5;
    const int lane = tid & 31;

    const float* qp = g_q + ((b * Hh + h) * Tt + q0) * DHd;

    // Load Q tile transposed: Qs[d][r]
#pragma unroll
    for (int l = 0; l < 32; l++) {
        int e = tid + l * 256;           // 0..8191
        int r = e >> 7, d = e & 127;
        Qs[d * 68 + r] = qp[r * 128 + d];
    }
    if (tid < 64) { mrow[tid] = -CUDART_INF_F; lrow[tid] = 0.f; }

    float o[4][8];
#pragma unroll
    for (int i = 0; i < 4; i++)
#pragma unroll
        for (int j = 0; j < 8; j++) o[i][j] = 0.f;

    __syncthreads();

    const int nkt = qb + 1;              // causal: key tiles 0..qb
    for (int kt = 0; kt < nkt; kt++) {
        const int k0 = kt * 64;
        const float* kp = g_k + ((b * Hh + h) * Tt + k0) * DHd;
        const float* vp = g_v + ((b * Hh + h) * Tt + k0) * DHd;

        // Load K transposed + V natural
#pragma unroll
        for (int l = 0; l < 32; l++) {
            int e = tid + l * 256;
            int r = e >> 7, d = e & 127;
            Ks[d * 68 + r]  = kp[r * 128 + d];
            Vs[r * 132 + d] = vp[r * 128 + d];
        }
        __syncthreads();

        // S = Q K^T
        float s_[4][4];
#pragma unroll
        for (int i = 0; i < 4; i++)
#pragma unroll
            for (int j = 0; j < 4; j++) s_[i][j] = 0.f;

#pragma unroll 8
        for (int k = 0; k < 128; k++) {
            float4 a4 = *(const float4*)&Qs[k * 68 + ty * 4];
            float4 b4 = *(const float4*)&Ks[k * 68 + tx * 4];
            float av[4] = {a4.x, a4.y, a4.z, a4.w};
            float bv[4] = {b4.x, b4.y, b4.z, b4.w};
#pragma unroll
            for (int i = 0; i < 4; i++)
#pragma unroll
                for (int j = 0; j < 4; j++)
                    s_[i][j] = fmaf(av[i], bv[j], s_[i][j]);
        }

        const bool diag = (kt == qb);
#pragma unroll
        for (int i = 0; i < 4; i++) {
            int gr = q0 + ty * 4 + i;
#pragma unroll
            for (int j = 0; j < 4; j++) {
                int gc = k0 + tx * 4 + j;
                float v = s_[i][j] * SCALE;
                if (diag && gc > gr) v = -CUDART_INF_F;
                Ss[(ty * 4 + i) * 68 + tx * 4 + j] = v;
            }
        }
        __syncthreads();

        // Online softmax: warp w owns rows {w, w+8, ..., w+56}
#pragma unroll
        for (int j = 0; j < 8; j++) {
            int r = w + j * 8;
            float v0 = Ss[r * 68 + lane];
            float v1 = Ss[r * 68 + lane + 32];
            float mx = fmaxf(v0, v1);
#pragma unroll
            for (int off = 16; off; off >>= 1)
                mx = fmaxf(mx, __shfl_xor_sync(0xffffffffu, mx, off));
            float mold = mrow[r];
            float mnew = fmaxf(mold, mx);
            float p0 = __expf(v0 - mnew);
            float p1 = __expf(v1 - mnew);
            Ss[r * 68 + lane]      = p0;
            Ss[r * 68 + lane + 32] = p1;
            float s = p0 + p1;
#pragma unroll
            for (int off = 16; off; off >>= 1)
                s += __shfl_xor_sync(0xffffffffu, s, off);
            if (lane == 0) {
                float al = __expf(mold - mnew);
                arow[r] = al;
                lrow[r] = lrow[r] * al + s;
                mrow[r] = mnew;
            }
        }
        __syncthreads();

        // O = O*alpha + P @ V   (thread tile: 4 rows x 8 cols; cols = tx*8..)
        float al[4];
#pragma unroll
        for (int i = 0; i < 4; i++) al[i] = arow[ty * 4 + i];
#pragma unroll
        for (int i = 0; i < 4; i++)
#pragma unroll
            for (int j = 0; j < 8; j++) o[i][j] *= al[i];

#pragma unroll 4
        for (int kk = 0; kk < 64; kk++) {
            float p[4];
#pragma unroll
            for (int i = 0; i < 4; i++) p[i] = Ss[(ty * 4 + i) * 68 + kk];
            float4 vA = *(const float4*)&Vs[kk * 132 + tx * 8];
            float4 vB = *(const float4*)&Vs[kk * 132 + tx * 8 + 4];
            float vv[8] = {vA.x, vA.y, vA.z, vA.w, vB.x, vB.y, vB.z, vB.w};
#pragma unroll
            for (int i = 0; i < 4; i++)
#pragma unroll
                for (int j = 0; j < 8; j++)
                    o[i][j] = fmaf(p[i], vv[j], o[i][j]);
        }
        __syncthreads();
    }

    // Epilogue: divide by l, write [B, T, D]
#pragma unroll
    for (int i = 0; i < 4; i++) {
        int r = ty * 4 + i;
        float inv = 1.0f / lrow[r];
        int trow = q0 + r;
        float* op = g_att + (b * Tt + trow) * Dd + h * DHd + tx * 8;
        float4 u, v;
        u.x = o[i][0] * inv; u.y = o[i][1] * inv;
        u.z = o[i][2] * inv; u.w = o[i][3] * inv;
        v.x = o[i][4] * inv; v.y = o[i][5] * inv;
        v.z = o[i][6] * inv; v.w = o[i][7] * inv;
        *(float4*)op       = u;
        *(float4*)(op + 4) = v;
    }
}

// ---------------------------------------------------------------------------
extern "C" void kernel_launch(void* const* d_in, const int* in_sizes, int n_in,
                              void* d_out, int out_size)
{
    const float* x  = (const float*)d_in[0];
    const float* Wq = (const float*)d_in[1];
    const float* bq = (const float*)d_in[2];
    const float* Wk = (const float*)d_in[3];
    const float* bk = (const float*)d_in[4];
    const float* Wv = (const float*)d_in[5];
    const float* bv = (const float*)d_in[6];
    const float* Wo = (const float*)d_in[7];
    const float* bo = (const float*)d_in[8];
    float* out = (float*)d_out;

    dim3 ggrid(Dd / 64, Mm / 64);
    dim3 gblk(256);

    gemm64<0><<<ggrid, gblk>>>(x, Wq, bq, nullptr);
    gemm64<1><<<ggrid, gblk>>>(x, Wk, bk, nullptr);
    gemm64<2><<<ggrid, gblk>>>(x, Wv, bv, nullptr);

    const int flash_smem = (2 * 128 * 68 + 64 * 132 + 64 * 68 + 3 * 64) * (int)sizeof(float); // 121600
    cudaFuncSetAttribute(flash_kernel, cudaFuncAttributeMaxDynamicSharedMemorySize, flash_smem);
    dim3 fgrid(Tt / 64, Hh, Bq);
    flash_kernel<<<fgrid, 256, flash_smem>>>();

    // g_att (device global) as A operand of the final GEMM
    float* att_ptr = nullptr;
    cudaGetSymbolAddress((void**)&att_ptr, g_att);
    gemm64<3><<<ggrid, gblk>>>(att_ptr, Wo, bo, out);
}

// round 4
// speedup vs baseline: 1.3602x; 1.3602x over previous
#include <cuda_runtime.h>
#include <math_constants.h>
#include <cstdint>

#define Bq  4
#define Tt  2048
#define Dd  2048
#define Hh  16
#define DHd 128
#define Mm  (Bq * Tt)        // 8192
#define SCALE 0.08838834764831845f  // DH^-0.5

// Scratch (allocation-free rule: __device__ globals)
__device__ __align__(256) float g_q[Bq * Hh * Tt * DHd];
__device__ __align__(256) float g_k[Bq * Hh * Tt * DHd];
__device__ __align__(256) float g_v[Bq * Hh * Tt * DHd];
__device__ __align__(256) float g_att[Bq * Tt * Dd];

// ===========================================================================
// Helpers (sm_80-era instructions only — NO tcgen05/TMEM/mbarrier)
// ===========================================================================
__device__ __forceinline__ uint32_t smem_u32(const void* p) {
    uint32_t a;
    asm("{ .reg .u64 t; cvta.to.shared.u64 t, %1; cvt.u32.u64 %0, t; }" : "=r"(a) : "l"(p));
    return a;
}
__device__ __forceinline__ void cp16(uint32_t dst, const void* src) {
    asm volatile("cp.async.cg.shared.global [%0], [%1], 16;" :: "r"(dst), "l"(src));
}
#define CP_COMMIT() asm volatile("cp.async.commit_group;" ::: "memory")
#define CP_WAIT0()  asm volatile("cp.async.wait_group 0;" ::: "memory")

// m16n8k8 tf32 MMA
__device__ __forceinline__ void mma_tf32(float* c, const uint32_t* a,
                                         uint32_t b0, uint32_t b1) {
    asm volatile(
        "mma.sync.aligned.m16n8k8.row.col.f32.tf32.tf32.f32 "
        "{%0,%1,%2,%3}, {%4,%5,%6,%7}, {%8,%9}, {%0,%1,%2,%3};"
        : "+f"(c[0]), "+f"(c[1]), "+f"(c[2]), "+f"(c[3])
        : "r"(a[0]), "r"(a[1]), "r"(a[2]), "r"(a[3]), "r"(b0), "r"(b1));
}

// Split fp32 -> (tf32 hi rounded-to-nearest, fp32 residual lo)
__device__ __forceinline__ void tf32_split(float v, uint32_t& hi, uint32_t& lo) {
    uint32_t h;
    asm("cvt.rna.tf32.f32 %0, %1;" : "=r"(h) : "f"(v));
    hi = h;
    lo = __float_as_uint(v - __uint_as_float(h));
}

// ===========================================================================
// 3xTF32 tensor-core GEMM: C[M,N] = A[M,K] @ W[K,N] + bias (fp32 accuracy)
// BM=128, BN=128, BK=32, 256 threads (8 warps, 2x4), warp tile 64x32.
// Double-buffered cp.async pipeline.
// MODE 0/1/2 -> head-split write to g_q/g_k/g_v; MODE 3 -> row-major Cout.
// ===========================================================================
#define GBM 128
#define GBN 128
#define GBK 32
#define APITCH 36      // floats per A smem row (pad: conflict-free frags)
#define BPITCH 136     // floats per B smem row
#define A_BYTES (GBM * APITCH * 4)               // 18432
#define B_BYTES (GBK * BPITCH * 4)               // 17408
#define STAGE_BYTES (A_BYTES + B_BYTES)          // 35840
#define GEMM_SMEM (2 * STAGE_BYTES)              // 71680

__device__ __forceinline__ void load_stage(uint32_t sdst,
                                           const float* __restrict__ A,
                                           const float* __restrict__ W,
                                           int m0, int n0, int k0) {
    const int tid = threadIdx.x;
#pragma unroll
    for (int l = 0; l < 4; l++) {
        int e = tid + 256 * l;
        int r = e >> 3, c = e & 7;
        cp16(sdst + r * (APITCH * 4) + c * 16,
             A + (size_t)(m0 + r) * Dd + k0 + c * 4);
    }
#pragma unroll
    for (int l = 0; l < 4; l++) {
        int e = tid + 256 * l;
        int r = e >> 5, c = e & 31;
        cp16(sdst + A_BYTES + r * (BPITCH * 4) + c * 16,
             W + (size_t)(k0 + r) * Dd + n0 + c * 4);
    }
}

template <int MODE>
__global__ __launch_bounds__(256, 1)
void gemm_tc(const float* __restrict__ A, const float* __restrict__ W,
             const float* __restrict__ bias, float* __restrict__ Cout)
{
    extern __shared__ char smem[];
    const uint32_t sbase = smem_u32(smem);
    const int tid  = threadIdx.x;
    const int wid  = tid >> 5;
    const int lane = tid & 31;
    const int wm   = wid >> 2;      // 0..1
    const int wn   = wid & 3;       // 0..3
    const int m0   = blockIdx.y * GBM;
    const int n0   = blockIdx.x * GBN;

    float acc[4][4][4];
#pragma unroll
    for (int i = 0; i < 4; i++)
#pragma unroll
        for (int j = 0; j < 4; j++)
#pragma unroll
            for (int r = 0; r < 4; r++) acc[i][j][r] = 0.f;

    load_stage(sbase, A, W, m0, n0, 0);
    CP_COMMIT();

    const int NITER = Dd / GBK;     // 64
    for (int it = 0; it < NITER; it++) {
        CP_WAIT0();
        __syncthreads();
        const char* buf = smem + (it & 1) * STAGE_BYTES;
        if (it + 1 < NITER) {
            load_stage(sbase + ((it + 1) & 1) * STAGE_BYTES, A, W, m0, n0,
                       (it + 1) * GBK);
            CP_COMMIT();
        }
        const float* As = (const float*)buf;
        const float* Bs = (const float*)(buf + A_BYTES);

#pragma unroll
        for (int ks = 0; ks < 4; ks++) {
            const int kf = ks * 8 + (lane & 3);
            uint32_t ah[4][4], al[4][4];
#pragma unroll
            for (int i = 0; i < 4; i++) {
                int m = wm * 64 + i * 16 + (lane >> 2);
                tf32_split(As[m * APITCH + kf],           ah[i][0], al[i][0]);
                tf32_split(As[(m + 8) * APITCH + kf],     ah[i][1], al[i][1]);
                tf32_split(As[m * APITCH + kf + 4],       ah[i][2], al[i][2]);
                tf32_split(As[(m + 8) * APITCH + kf + 4], ah[i][3], al[i][3]);
            }
#pragma unroll
            for (int j = 0; j < 4; j++) {
                int nn = wn * 32 + j * 8 + (lane >> 2);
                uint32_t b0h, b0l, b1h, b1l;
                tf32_split(Bs[kf * BPITCH + nn],       b0h, b0l);
                tf32_split(Bs[(kf + 4) * BPITCH + nn], b1h, b1l);
#pragma unroll
                for (int i = 0; i < 4; i++) {
                    mma_tf32(acc[i][j], ah[i], b0h, b1h);   // hi*hi
                    mma_tf32(acc[i][j], al[i], b0h, b1h);   // lo*hi
                    mma_tf32(acc[i][j], ah[i], b0l, b1l);   // hi*lo
                }
            }
        }
        // single barrier per iter: protects buf[(it+1)&1] overwrite next iter
    }

    // Epilogue: bias + store (float2 per fragment half)
    const int mbase = m0 + wm * 64;
#pragma unroll
    for (int j = 0; j < 4; j++) {
        const int nc = wn * 32 + j * 8 + 2 * (lane & 3);   // 0..127 within tile
        const float bx = bias[n0 + nc];
        const float by = bias[n0 + nc + 1];
#pragma unroll
        for (int i = 0; i < 4; i++) {
            const int r0 = mbase + i * 16 + (lane >> 2);
#pragma unroll
            for (int half = 0; half < 2; half++) {
                const int m = r0 + half * 8;
                float2 val;
                val.x = acc[i][j][half * 2]     + bx;
                val.y = acc[i][j][half * 2 + 1] + by;
                if (MODE == 3) {
                    *(float2*)(Cout + (size_t)m * Dd + n0 + nc) = val;
                } else {
                    float* dst = (MODE == 0) ? g_q : (MODE == 1) ? g_k : g_v;
                    const int h = n0 >> 7;
                    const int b = m >> 11;
                    const int t = m & 2047;
                    *(float2*)(dst + (size_t)(((b * Hh + h) * Tt) + t) * DHd + nc) = val;
                }
            }
        }
    }
}

// ===========================================================================
// Flash attention (causal), fp32 SIMT (unchanged — passing since round 1)
// ===========================================================================
__global__ __launch_bounds__(256)
void flash_kernel()
{
    extern __shared__ float sm[];
    float* Qs   = sm;                    // [128][68]
    float* Ks   = Qs + 128 * 68;         // [128][68]
    float* Vs   = Ks + 128 * 68;         // [64][132]
    float* Ss   = Vs + 64 * 132;         // [64][68]
    float* mrow = Ss + 64 * 68;
    float* lrow = mrow + 64;
    float* arow = lrow + 64;

    const int qb = blockIdx.x;
    const int h  = blockIdx.y;
    const int b  = blockIdx.z;
    const int q0 = qb * 64;

    const int tid  = threadIdx.x;
    const int tx   = tid & 15;
    const int ty   = tid >> 4;
    const int w    = tid >> 5;
    const int lane = tid & 31;

    const float* qp = g_q + ((b * Hh + h) * Tt + q0) * DHd;

#pragma unroll
    for (int l = 0; l < 32; l++) {
        int e = tid + l * 256;
        int r = e >> 7, d = e & 127;
        Qs[d * 68 + r] = qp[r * 128 + d];
    }
    if (tid < 64) { mrow[tid] = -CUDART_INF_F; lrow[tid] = 0.f; }

    float o[4][8];
#pragma unroll
    for (int i = 0; i < 4; i++)
#pragma unroll
        for (int j = 0; j < 8; j++) o[i][j] = 0.f;

    __syncthreads();

    const int nkt = qb + 1;
    for (int kt = 0; kt < nkt; kt++) {
        const int k0 = kt * 64;
        const float* kp = g_k + ((b * Hh + h) * Tt + k0) * DHd;
        const float* vp = g_v + ((b * Hh + h) * Tt + k0) * DHd;

#pragma unroll
        for (int l = 0; l < 32; l++) {
            int e = tid + l * 256;
            int r = e >> 7, d = e & 127;
            Ks[d * 68 + r]  = kp[r * 128 + d];
            Vs[r * 132 + d] = vp[r * 128 + d];
        }
        __syncthreads();

        float s_[4][4];
#pragma unroll
        for (int i = 0; i < 4; i++)
#pragma unroll
            for (int j = 0; j < 4; j++) s_[i][j] = 0.f;

#pragma unroll 8
        for (int k = 0; k < 128; k++) {
            float4 a4 = *(const float4*)&Qs[k * 68 + ty * 4];
            float4 b4 = *(const float4*)&Ks[k * 68 + tx * 4];
            float av[4] = {a4.x, a4.y, a4.z, a4.w};
            float bv[4] = {b4.x, b4.y, b4.z, b4.w};
#pragma unroll
            for (int i = 0; i < 4; i++)
#pragma unroll
                for (int j = 0; j < 4; j++)
                    s_[i][j] = fmaf(av[i], bv[j], s_[i][j]);
        }

        const bool diag = (kt == qb);
#pragma unroll
        for (int i = 0; i < 4; i++) {
            int gr = q0 + ty * 4 + i;
#pragma unroll
            for (int j = 0; j < 4; j++) {
                int gc = k0 + tx * 4 + j;
                float v = s_[i][j] * SCALE;
                if (diag && gc > gr) v = -CUDART_INF_F;
                Ss[(ty * 4 + i) * 68 + tx * 4 + j] = v;
            }
        }
        __syncthreads();

#pragma unroll
        for (int j = 0; j < 8; j++) {
            int r = w + j * 8;
            float v0 = Ss[r * 68 + lane];
            float v1 = Ss[r * 68 + lane + 32];
            float mx = fmaxf(v0, v1);
#pragma unroll
            for (int off = 16; off; off >>= 1)
                mx = fmaxf(mx, __shfl_xor_sync(0xffffffffu, mx, off));
            float mold = mrow[r];
            float mnew = fmaxf(mold, mx);
            float p0 = __expf(v0 - mnew);
            float p1 = __expf(v1 - mnew);
            Ss[r * 68 + lane]      = p0;
            Ss[r * 68 + lane + 32] = p1;
            float s = p0 + p1;
#pragma unroll
            for (int off = 16; off; off >>= 1)
                s += __shfl_xor_sync(0xffffffffu, s, off);
            if (lane == 0) {
                float al = __expf(mold - mnew);
                arow[r] = al;
                lrow[r] = lrow[r] * al + s;
                mrow[r] = mnew;
            }
        }
        __syncthreads();

        float al[4];
#pragma unroll
        for (int i = 0; i < 4; i++) al[i] = arow[ty * 4 + i];
#pragma unroll
        for (int i = 0; i < 4; i++)
#pragma unroll
            for (int j = 0; j < 8; j++) o[i][j] *= al[i];

#pragma unroll 4
        for (int kk = 0; kk < 64; kk++) {
            float p[4];
#pragma unroll
            for (int i = 0; i < 4; i++) p[i] = Ss[(ty * 4 + i) * 68 + kk];
            float4 vA = *(const float4*)&Vs[kk * 132 + tx * 8];
            float4 vB = *(const float4*)&Vs[kk * 132 + tx * 8 + 4];
            float vv[8] = {vA.x, vA.y, vA.z, vA.w, vB.x, vB.y, vB.z, vB.w};
#pragma unroll
            for (int i = 0; i < 4; i++)
#pragma unroll
                for (int j = 0; j < 8; j++)
                    o[i][j] = fmaf(p[i], vv[j], o[i][j]);
        }
        __syncthreads();
    }

#pragma unroll
    for (int i = 0; i < 4; i++) {
        int r = ty * 4 + i;
        float inv = 1.0f / lrow[r];
        int trow = q0 + r;
        float* op = g_att + (b * Tt + trow) * Dd + h * DHd + tx * 8;
        float4 u, v;
        u.x = o[i][0] * inv; u.y = o[i][1] * inv;
        u.z = o[i][2] * inv; u.w = o[i][3] * inv;
        v.x = o[i][4] * inv; v.y = o[i][5] * inv;
        v.z = o[i][6] * inv; v.w = o[i][7] * inv;
        *(float4*)op       = u;
        *(float4*)(op + 4) = v;
    }
}

// ===========================================================================
extern "C" void kernel_launch(void* const* d_in, const int* in_sizes, int n_in,
                              void* d_out, int out_size)
{
    const float* x  = (const float*)d_in[0];
    const float* Wq = (const float*)d_in[1];
    const float* bq = (const float*)d_in[2];
    const float* Wk = (const float*)d_in[3];
    const float* bk = (const float*)d_in[4];
    const float* Wv = (const float*)d_in[5];
    const float* bv = (const float*)d_in[6];
    const float* Wo = (const float*)d_in[7];
    const float* bo = (const float*)d_in[8];
    float* out = (float*)d_out;

    float* att_ptr = nullptr;
    cudaGetSymbolAddress((void**)&att_ptr, g_att);

    cudaFuncSetAttribute(gemm_tc<0>, cudaFuncAttributeMaxDynamicSharedMemorySize, GEMM_SMEM);
    cudaFuncSetAttribute(gemm_tc<1>, cudaFuncAttributeMaxDynamicSharedMemorySize, GEMM_SMEM);
    cudaFuncSetAttribute(gemm_tc<2>, cudaFuncAttributeMaxDynamicSharedMemorySize, GEMM_SMEM);
    cudaFuncSetAttribute(gemm_tc<3>, cudaFuncAttributeMaxDynamicSharedMemorySize, GEMM_SMEM);

    dim3 ggrid(Dd / GBN, Mm / GBM);   // (16, 64)
    gemm_tc<0><<<ggrid, 256, GEMM_SMEM>>>(x, Wq, bq, nullptr);
    gemm_tc<1><<<ggrid, 256, GEMM_SMEM>>>(x, Wk, bk, nullptr);
    gemm_tc<2><<<ggrid, 256, GEMM_SMEM>>>(x, Wv, bv, nullptr);

    const int flash_smem = (2 * 128 * 68 + 64 * 132 + 64 * 68 + 3 * 64) * (int)sizeof(float);
    cudaFuncSetAttribute(flash_kernel, cudaFuncAttributeMaxDynamicSharedMemorySize, flash_smem);
    dim3 fgrid(Tt / 64, Hh, Bq);
    flash_kernel<<<fgrid, 256, flash_smem>>>();

    gemm_tc<3><<<ggrid, 256, GEMM_SMEM>>>(att_ptr, Wo, bo, out);
}

// round 5
// speedup vs baseline: 1.7487x; 1.2857x over previous
#include <cuda_runtime.h>
#include <math_constants.h>
#include <cstdint>

#define Bq  4
#define Tt  2048
#define Dd  2048
#define Hh  16
#define DHd 128
#define Mm  (Bq * Tt)        // 8192
#define SCALE 0.08838834764831845f  // DH^-0.5

// Scratch (allocation-free rule: __device__ globals)
__device__ __align__(256) float g_q[Bq * Hh * Tt * DHd];
__device__ __align__(256) float g_k[Bq * Hh * Tt * DHd];
__device__ __align__(256) float g_v[Bq * Hh * Tt * DHd];
__device__ __align__(256) float g_att[Bq * Tt * Dd];

// ===========================================================================
// Helpers (sm_80-era instructions only)
// ===========================================================================
__device__ __forceinline__ uint32_t smem_u32(const void* p) {
    uint32_t a;
    asm("{ .reg .u64 t; cvta.to.shared.u64 t, %1; cvt.u32.u64 %0, t; }" : "=r"(a) : "l"(p));
    return a;
}
__device__ __forceinline__ void cp16(uint32_t dst, const void* src) {
    asm volatile("cp.async.cg.shared.global [%0], [%1], 16;" :: "r"(dst), "l"(src));
}
#define CP_COMMIT() asm volatile("cp.async.commit_group;" ::: "memory")
#define CP_WAIT0()  asm volatile("cp.async.wait_group 0;" ::: "memory")
#define CP_WAIT1()  asm volatile("cp.async.wait_group 1;" ::: "memory")

// m16n8k8 tf32 MMA
__device__ __forceinline__ void mma_tf32(float* c, const uint32_t* a,
                                         uint32_t b0, uint32_t b1) {
    asm volatile(
        "mma.sync.aligned.m16n8k8.row.col.f32.tf32.tf32.f32 "
        "{%0,%1,%2,%3}, {%4,%5,%6,%7}, {%8,%9}, {%0,%1,%2,%3};"
        : "+f"(c[0]), "+f"(c[1]), "+f"(c[2]), "+f"(c[3])
        : "r"(a[0]), "r"(a[1]), "r"(a[2]), "r"(a[3]), "r"(b0), "r"(b1));
}

// Split fp32 -> (tf32 hi rounded-to-nearest, fp32 residual lo)
__device__ __forceinline__ void tf32_split(float v, uint32_t& hi, uint32_t& lo) {
    uint32_t h;
    asm("cvt.rna.tf32.f32 %0, %1;" : "=r"(h) : "f"(v));
    hi = h;
    lo = __float_as_uint(v - __uint_as_float(h));
}

// ===========================================================================
// 3xTF32 tensor-core GEMM (unchanged from round 4 — passing)
// ===========================================================================
#define GBM 128
#define GBN 128
#define GBK 32
#define APITCH 36
#define BPITCH 136
#define A_BYTES (GBM * APITCH * 4)
#define B_BYTES (GBK * BPITCH * 4)
#define STAGE_BYTES (A_BYTES + B_BYTES)
#define GEMM_SMEM (2 * STAGE_BYTES)

__device__ __forceinline__ void load_stage(uint32_t sdst,
                                           const float* __restrict__ A,
                                           const float* __restrict__ W,
                                           int m0, int n0, int k0) {
    const int tid = threadIdx.x;
#pragma unroll
    for (int l = 0; l < 4; l++) {
        int e = tid + 256 * l;
        int r = e >> 3, c = e & 7;
        cp16(sdst + r * (APITCH * 4) + c * 16,
             A + (size_t)(m0 + r) * Dd + k0 + c * 4);
    }
#pragma unroll
    for (int l = 0; l < 4; l++) {
        int e = tid + 256 * l;
        int r = e >> 5, c = e & 31;
        cp16(sdst + A_BYTES + r * (BPITCH * 4) + c * 16,
             W + (size_t)(k0 + r) * Dd + n0 + c * 4);
    }
}

template <int MODE>
__global__ __launch_bounds__(256, 1)
void gemm_tc(const float* __restrict__ A, const float* __restrict__ W,
             const float* __restrict__ bias, float* __restrict__ Cout)
{
    extern __shared__ char smem[];
    const uint32_t sbase = smem_u32(smem);
    const int tid  = threadIdx.x;
    const int wid  = tid >> 5;
    const int lane = tid & 31;
    const int wm   = wid >> 2;
    const int wn   = wid & 3;
    const int m0   = blockIdx.y * GBM;
    const int n0   = blockIdx.x * GBN;

    float acc[4][4][4];
#pragma unroll
    for (int i = 0; i < 4; i++)
#pragma unroll
        for (int j = 0; j < 4; j++)
#pragma unroll
            for (int r = 0; r < 4; r++) acc[i][j][r] = 0.f;

    load_stage(sbase, A, W, m0, n0, 0);
    CP_COMMIT();

    const int NITER = Dd / GBK;
    for (int it = 0; it < NITER; it++) {
        CP_WAIT0();
        __syncthreads();
        const char* buf = smem + (it & 1) * STAGE_BYTES;
        if (it + 1 < NITER) {
            load_stage(sbase + ((it + 1) & 1) * STAGE_BYTES, A, W, m0, n0,
                       (it + 1) * GBK);
            CP_COMMIT();
        }
        const float* As = (const float*)buf;
        const float* Bs = (const float*)(buf + A_BYTES);

#pragma unroll
        for (int ks = 0; ks < 4; ks++) {
            const int kf = ks * 8 + (lane & 3);
            uint32_t ah[4][4], al[4][4];
#pragma unroll
            for (int i = 0; i < 4; i++) {
                int m = wm * 64 + i * 16 + (lane >> 2);
                tf32_split(As[m * APITCH + kf],           ah[i][0], al[i][0]);
                tf32_split(As[(m + 8) * APITCH + kf],     ah[i][1], al[i][1]);
                tf32_split(As[m * APITCH + kf + 4],       ah[i][2], al[i][2]);
                tf32_split(As[(m + 8) * APITCH + kf + 4], ah[i][3], al[i][3]);
            }
#pragma unroll
            for (int j = 0; j < 4; j++) {
                int nn = wn * 32 + j * 8 + (lane >> 2);
                uint32_t b0h, b0l, b1h, b1l;
                tf32_split(Bs[kf * BPITCH + nn],       b0h, b0l);
                tf32_split(Bs[(kf + 4) * BPITCH + nn], b1h, b1l);
#pragma unroll
                for (int i = 0; i < 4; i++) {
                    mma_tf32(acc[i][j], ah[i], b0h, b1h);
                    mma_tf32(acc[i][j], al[i], b0h, b1h);
                    mma_tf32(acc[i][j], ah[i], b0l, b1l);
                }
            }
        }
    }

    const int mbase = m0 + wm * 64;
#pragma unroll
    for (int j = 0; j < 4; j++) {
        const int nc = wn * 32 + j * 8 + 2 * (lane & 3);
        const float bx = bias[n0 + nc];
        const float by = bias[n0 + nc + 1];
#pragma unroll
        for (int i = 0; i < 4; i++) {
            const int r0 = mbase + i * 16 + (lane >> 2);
#pragma unroll
            for (int half = 0; half < 2; half++) {
                const int m = r0 + half * 8;
                float2 val;
                val.x = acc[i][j][half * 2]     + bx;
                val.y = acc[i][j][half * 2 + 1] + by;
                if (MODE == 3) {
                    *(float2*)(Cout + (size_t)m * Dd + n0 + nc) = val;
                } else {
                    float* dst = (MODE == 0) ? g_q : (MODE == 1) ? g_k : g_v;
                    const int h = n0 >> 7;
                    const int b = m >> 11;
                    const int t = m & 2047;
                    *(float2*)(dst + (size_t)(((b * Hh + h) * Tt) + t) * DHd + nc) = val;
                }
            }
        }
    }
}

// ===========================================================================
// Flash attention (causal) on tensor cores, 3xTF32, online softmax.
// BM=128 (8 warps x 16 rows), BN=64, DH=128. 256 threads.
// smem (floats): Qs[128][132] | K0[64][132] | K1[64][132] | Vs[64][136] | Ps[128][68]
// ===========================================================================
#define FBM 128
#define FBN 64
#define QPITCH 132
#define KPITCH 132
#define VPITCH 136
#define PPITCH 68
#define F_OQ  0
#define F_OK0 (FBM * QPITCH)                    // 16896
#define F_OK1 (F_OK0 + FBN * KPITCH)            // 25344
#define F_OV  (F_OK1 + FBN * KPITCH)            // 33792
#define F_OP  (F_OV + FBN * VPITCH)             // 42496
#define FLASH_FLOATS (F_OP + FBM * PPITCH)      // 51200
#define FLASH_SMEM (FLASH_FLOATS * 4)           // 204800

__device__ __forceinline__ void flash_load_k(uint32_t sdst, const float* __restrict__ src) {
    const int tid = threadIdx.x;
#pragma unroll
    for (int l = 0; l < 8; l++) {
        int e = tid + l * 256;
        int r = e >> 5, c = e & 31;
        cp16(sdst + (uint32_t)(r * KPITCH + c * 4) * 4, src + r * 128 + c * 4);
    }
}
__device__ __forceinline__ void flash_load_v(uint32_t sdst, const float* __restrict__ src) {
    const int tid = threadIdx.x;
#pragma unroll
    for (int l = 0; l < 8; l++) {
        int e = tid + l * 256;
        int r = e >> 5, c = e & 31;
        cp16(sdst + (uint32_t)(r * VPITCH + c * 4) * 4, src + r * 128 + c * 4);
    }
}

__global__ __launch_bounds__(256, 1)
void flash_tc()
{
    extern __shared__ float sm[];
    const uint32_t sb = smem_u32(sm);
    const int qb = blockIdx.x;
    const int h  = blockIdx.y;
    const int b  = blockIdx.z;
    const int q0 = qb * FBM;
    const int tid  = threadIdx.x;
    const int w    = tid >> 5;
    const int lane = tid & 31;
    const int q4   = lane & 3;
    const int rl   = lane >> 2;

    float* Qs = sm;
    float* Kb[2] = {sm + F_OK0, sm + F_OK1};
    float* Vs = sm + F_OV;
    float* Ps = sm + F_OP;
    const uint32_t kOff[2] = {sb + F_OK0 * 4, sb + F_OK1 * 4};
    const uint32_t vOff = sb + F_OV * 4;

    const size_t bh = (size_t)(b * Hh + h) * Tt;
    const float* qp    = g_q + (bh + q0) * DHd;
    const float* kbase = g_k + bh * DHd;
    const float* vbase = g_v + bh * DHd;

    // Load Q (scaled) into smem
#pragma unroll
    for (int l = 0; l < 16; l++) {
        int e = tid + l * 256;          // float4 units, 0..4095
        int r = e >> 5, c = e & 31;
        float4 v = *(const float4*)(qp + r * 128 + c * 4);
        float* d = Qs + r * QPITCH + c * 4;
        d[0] = v.x * SCALE; d[1] = v.y * SCALE;
        d[2] = v.z * SCALE; d[3] = v.w * SCALE;
    }

    flash_load_k(kOff[0], kbase);
    CP_COMMIT();
    flash_load_v(vOff, vbase);
    CP_COMMIT();

    // Per-row softmax state (rows rl and rl+8 of this warp's 16-row block)
    float m_lo = -1e30f, m_hi = -1e30f, l_lo = 0.f, l_hi = 0.f;
    float o[16][4];
#pragma unroll
    for (int nt = 0; nt < 16; nt++)
#pragma unroll
        for (int r = 0; r < 4; r++) o[nt][r] = 0.f;

    const int rowbase = q0 + w * 16;      // this warp's first global row
    const int nkt = 2 * qb + 2;

    for (int t = 0; t < nkt; t++) {
        const int k0 = t * FBN;
        const bool active = (k0 <= rowbase + 15);   // any unmasked element?
        CP_WAIT1();            // K_t ready
        __syncthreads();

        float sacc[8][4];
        if (active) {
            const float* Ks = Kb[t & 1];
#pragma unroll
            for (int j = 0; j < 8; j++)
#pragma unroll
                for (int r = 0; r < 4; r++) sacc[j][r] = 0.f;

#pragma unroll
            for (int ks = 0; ks < 16; ks++) {
                const int kc = ks * 8 + q4;
                const float* qrow = Qs + (w * 16 + rl) * QPITCH;
                uint32_t ah[4], al[4];
                tf32_split(qrow[kc],                ah[0], al[0]);
                tf32_split(qrow[8 * QPITCH + kc],   ah[1], al[1]);
                tf32_split(qrow[kc + 4],            ah[2], al[2]);
                tf32_split(qrow[8 * QPITCH + kc + 4], ah[3], al[3]);
#pragma unroll
                for (int j = 0; j < 8; j++) {
                    const float* kr = Ks + (j * 8 + rl) * KPITCH;
                    uint32_t b0h, b0l, b1h, b1l;
                    tf32_split(kr[kc],     b0h, b0l);
                    tf32_split(kr[kc + 4], b1h, b1l);
                    mma_tf32(sacc[j], ah, b0h, b1h);
                    mma_tf32(sacc[j], al, b0h, b1h);
                    mma_tf32(sacc[j], ah, b0l, b1l);
                }
            }
        }

        if (t + 1 < nkt) {
            flash_load_k(kOff[(t + 1) & 1], kbase + (size_t)(t + 1) * FBN * 128);
            CP_COMMIT();
            CP_WAIT1();        // V_t ready
        } else {
            CP_WAIT0();        // V_t ready (last)
        }
        __syncthreads();

        if (active) {
            // Causal mask + online softmax (warp-local)
            const int R_lo = rowbase + rl;
            const int R_hi = R_lo + 8;
            const bool needmask = (k0 + FBN - 1) > rowbase;   // tile touches diag
            float tl = -1e30f, th = -1e30f;
#pragma unroll
            for (int j = 0; j < 8; j++) {
                if (needmask) {
                    const int C = k0 + j * 8 + 2 * q4;
                    if (C > R_lo)     sacc[j][0] = -1e30f;
                    if (C + 1 > R_lo) sacc[j][1] = -1e30f;
                    if (C > R_hi)     sacc[j][2] = -1e30f;
                    if (C + 1 > R_hi) sacc[j][3] = -1e30f;
                }
                tl = fmaxf(tl, fmaxf(sacc[j][0], sacc[j][1]));
                th = fmaxf(th, fmaxf(sacc[j][2], sacc[j][3]));
            }
            tl = fmaxf(tl, __shfl_xor_sync(0xffffffffu, tl, 1));
            tl = fmaxf(tl, __shfl_xor_sync(0xffffffffu, tl, 2));
            th = fmaxf(th, __shfl_xor_sync(0xffffffffu, th, 1));
            th = fmaxf(th, __shfl_xor_sync(0xffffffffu, th, 2));

            const float mn_lo = fmaxf(m_lo, tl);
            const float mn_hi = fmaxf(m_hi, th);
            const float a_lo = __expf(m_lo - mn_lo);
            const float a_hi = __expf(m_hi - mn_hi);
            m_lo = mn_lo; m_hi = mn_hi;

            float sum_lo = 0.f, sum_hi = 0.f;
            float* prow_lo = Ps + (w * 16 + rl) * PPITCH;
            float* prow_hi = prow_lo + 8 * PPITCH;
#pragma unroll
            for (int j = 0; j < 8; j++) {
                float p0 = __expf(sacc[j][0] - mn_lo);
                float p1 = __expf(sacc[j][1] - mn_lo);
                float p2 = __expf(sacc[j][2] - mn_hi);
                float p3 = __expf(sacc[j][3] - mn_hi);
                sum_lo += p0 + p1;
                sum_hi += p2 + p3;
                *(float2*)(prow_lo + j * 8 + 2 * q4) = make_float2(p0, p1);
                *(float2*)(prow_hi + j * 8 + 2 * q4) = make_float2(p2, p3);
            }
            sum_lo += __shfl_xor_sync(0xffffffffu, sum_lo, 1);
            sum_lo += __shfl_xor_sync(0xffffffffu, sum_lo, 2);
            sum_hi += __shfl_xor_sync(0xffffffffu, sum_hi, 1);
            sum_hi += __shfl_xor_sync(0xffffffffu, sum_hi, 2);
            l_lo = l_lo * a_lo + sum_lo;
            l_hi = l_hi * a_hi + sum_hi;

#pragma unroll
            for (int nt = 0; nt < 16; nt++) {
                o[nt][0] *= a_lo; o[nt][1] *= a_lo;
                o[nt][2] *= a_hi; o[nt][3] *= a_hi;
            }
            __syncwarp();

            // O += P @ V  (3xTF32)
#pragma unroll
            for (int ks = 0; ks < 8; ks++) {
                const int kc = ks * 8 + q4;
                uint32_t ph[4], pl[4];
                tf32_split(prow_lo[kc],     ph[0], pl[0]);
                tf32_split(prow_hi[kc],     ph[1], pl[1]);
                tf32_split(prow_lo[kc + 4], ph[2], pl[2]);
                tf32_split(prow_hi[kc + 4], ph[3], pl[3]);
#pragma unroll
                for (int nt = 0; nt < 16; nt++) {
                    uint32_t b0h, b0l, b1h, b1l;
                    tf32_split(Vs[kc * VPITCH + nt * 8 + rl],       b0h, b0l);
                    tf32_split(Vs[(kc + 4) * VPITCH + nt * 8 + rl], b1h, b1l);
                    mma_tf32(o[nt], ph, b0h, b1h);
                    mma_tf32(o[nt], pl, b0h, b1h);
                    mma_tf32(o[nt], ph, b0l, b1l);
                }
            }
        }
        __syncthreads();

        if (t + 1 < nkt) {
            flash_load_v(vOff, vbase + (size_t)(t + 1) * FBN * 128);
            CP_COMMIT();
        }
    }

    // Epilogue: divide by l, write [B,T,D]
    const float il_lo = 1.f / l_lo;
    const float il_hi = 1.f / l_hi;
    float* ob = g_att + (size_t)(b * Tt + rowbase) * Dd + h * DHd;
#pragma unroll
    for (int nt = 0; nt < 16; nt++) {
        *(float2*)(ob + (size_t)rl * Dd + nt * 8 + 2 * q4) =
            make_float2(o[nt][0] * il_lo, o[nt][1] * il_lo);
        *(float2*)(ob + (size_t)(rl + 8) * Dd + nt * 8 + 2 * q4) =
            make_float2(o[nt][2] * il_hi, o[nt][3] * il_hi);
    }
}

// ===========================================================================
extern "C" void kernel_launch(void* const* d_in, const int* in_sizes, int n_in,
                              void* d_out, int out_size)
{
    const float* x  = (const float*)d_in[0];
    const float* Wq = (const float*)d_in[1];
    const float* bq = (const float*)d_in[2];
    const float* Wk = (const float*)d_in[3];
    const float* bk = (const float*)d_in[4];
    const float* Wv = (const float*)d_in[5];
    const float* bv = (const float*)d_in[6];
    const float* Wo = (const float*)d_in[7];
    const float* bo = (const float*)d_in[8];
    float* out = (float*)d_out;

    float* att_ptr = nullptr;
    cudaGetSymbolAddress((void**)&att_ptr, g_att);

    cudaFuncSetAttribute(gemm_tc<0>, cudaFuncAttributeMaxDynamicSharedMemorySize, GEMM_SMEM);
    cudaFuncSetAttribute(gemm_tc<1>, cudaFuncAttributeMaxDynamicSharedMemorySize, GEMM_SMEM);
    cudaFuncSetAttribute(gemm_tc<2>, cudaFuncAttributeMaxDynamicSharedMemorySize, GEMM_SMEM);
    cudaFuncSetAttribute(gemm_tc<3>, cudaFuncAttributeMaxDynamicSharedMemorySize, GEMM_SMEM);

    dim3 ggrid(Dd / GBN, Mm / GBM);   // (16, 64)
    gemm_tc<0><<<ggrid, 256, GEMM_SMEM>>>(x, Wq, bq, nullptr);
    gemm_tc<1><<<ggrid, 256, GEMM_SMEM>>>(x, Wk, bk, nullptr);
    gemm_tc<2><<<ggrid, 256, GEMM_SMEM>>>(x, Wv, bv, nullptr);

    cudaFuncSetAttribute(flash_tc, cudaFuncAttributeMaxDynamicSharedMemorySize, FLASH_SMEM);
    dim3 fgrid(Tt / FBM, Hh, Bq);     // (16, 16, 4)
    flash_tc<<<fgrid, 256, FLASH_SMEM>>>();

    gemm_tc<3><<<ggrid, 256, GEMM_SMEM>>>(att_ptr, Wo, bo, out);
}

// round 6
// speedup vs baseline: 2.7920x; 1.5966x over previous
#include <cuda_runtime.h>
#include <math_constants.h>
#include <cstdint>

#define Bq  4
#define Tt  2048
#define Dd  2048
#define Hh  16
#define DHd 128
#define Mm  (Bq * Tt)        // 8192
#define SCALE 0.08838834764831845f  // DH^-0.5

// Scratch (allocation-free rule: __device__ globals)
__device__ __align__(256) float g_q[Bq * Hh * Tt * DHd];
__device__ __align__(256) float g_k[Bq * Hh * Tt * DHd];
__device__ __align__(256) float g_v[Bq * Hh * Tt * DHd];
__device__ __align__(256) float g_att[Bq * Tt * Dd];

// ===========================================================================
// Helpers (sm_80-era instructions only)
// ===========================================================================
__device__ __forceinline__ uint32_t smem_u32(const void* p) {
    uint32_t a;
    asm("{ .reg .u64 t; cvta.to.shared.u64 t, %1; cvt.u32.u64 %0, t; }" : "=r"(a) : "l"(p));
    return a;
}
__device__ __forceinline__ void cp16(uint32_t dst, const void* src) {
    asm volatile("cp.async.cg.shared.global [%0], [%1], 16;" :: "r"(dst), "l"(src));
}
#define CP_COMMIT() asm volatile("cp.async.commit_group;" ::: "memory")
#define CP_WAIT0()  asm volatile("cp.async.wait_group 0;" ::: "memory")
#define CP_WAIT1()  asm volatile("cp.async.wait_group 1;" ::: "memory")

// m16n8k16 bf16 MMA
__device__ __forceinline__ void mma_bf16(float* c, const uint32_t* a,
                                         uint32_t b0, uint32_t b1) {
    asm volatile(
        "mma.sync.aligned.m16n8k16.row.col.f32.bf16.bf16.f32 "
        "{%0,%1,%2,%3}, {%4,%5,%6,%7}, {%8,%9}, {%0,%1,%2,%3};"
        : "+f"(c[0]), "+f"(c[1]), "+f"(c[2]), "+f"(c[3])
        : "r"(a[0]), "r"(a[1]), "r"(a[2]), "r"(a[3]), "r"(b0), "r"(b1));
}

// Split a pair of fp32 into packed bf16x2 (hi) + packed bf16x2 residual (lo).
// reg layout: lower 16 bits = v0 (smaller k), upper = v1.
__device__ __forceinline__ void bf16_split2(float v0, float v1,
                                            uint32_t& hi, uint32_t& lo) {
    uint32_t h;
    asm("cvt.rn.bf16x2.f32 %0, %1, %2;" : "=r"(h) : "f"(v1), "f"(v0));
    float f0 = __uint_as_float(h << 16);
    float f1 = __uint_as_float(h & 0xffff0000u);
    float r0 = v0 - f0;
    float r1 = v1 - f1;
    asm("cvt.rn.bf16x2.f32 %0, %1, %2;" : "=r"(lo) : "f"(r1), "f"(r0));
    hi = h;
}

// ===========================================================================
// 3xBF16 tensor-core GEMM: C[M,N] = A[M,K] @ W[K,N] + bias (fp32-class accuracy)
// BM=128, BN=128, BK=32, 256 threads (8 warps, 2x4), warp tile 64x32.
// Double-buffered cp.async pipeline.
// ===========================================================================
#define GBM 128
#define GBN 128
#define GBK 32
#define APITCH 40      // == 8 mod 32: conflict-free float2 A-frag loads
#define BPITCH 132     // == 4 mod 32: conflict-free scalar B-frag loads
#define A_BYTES (GBM * APITCH * 4)               // 20480
#define B_BYTES (GBK * BPITCH * 4)               // 16896
#define STAGE_BYTES (A_BYTES + B_BYTES)          // 37376
#define GEMM_SMEM (2 * STAGE_BYTES)              // 74752

__device__ __forceinline__ void load_stage(uint32_t sdst,
                                           const float* __restrict__ A,
                                           const float* __restrict__ W,
                                           int m0, int n0, int k0) {
    const int tid = threadIdx.x;
#pragma unroll
    for (int l = 0; l < 4; l++) {
        int e = tid + 256 * l;
        int r = e >> 3, c = e & 7;
        cp16(sdst + r * (APITCH * 4) + c * 16,
             A + (size_t)(m0 + r) * Dd + k0 + c * 4);
    }
#pragma unroll
    for (int l = 0; l < 4; l++) {
        int e = tid + 256 * l;
        int r = e >> 5, c = e & 31;
        cp16(sdst + A_BYTES + r * (BPITCH * 4) + c * 16,
             W + (size_t)(k0 + r) * Dd + n0 + c * 4);
    }
}

template <int MODE>
__global__ __launch_bounds__(256, 1)
void gemm_tc(const float* __restrict__ A, const float* __restrict__ W,
             const float* __restrict__ bias, float* __restrict__ Cout)
{
    extern __shared__ char smem[];
    const uint32_t sbase = smem_u32(smem);
    const int tid  = threadIdx.x;
    const int wid  = tid >> 5;
    const int lane = tid & 31;
    const int q4   = lane & 3;
    const int g8   = lane >> 2;
    const int wm   = wid >> 2;
    const int wn   = wid & 3;
    const int m0   = blockIdx.y * GBM;
    const int n0   = blockIdx.x * GBN;

    float acc[4][4][4];
#pragma unroll
    for (int i = 0; i < 4; i++)
#pragma unroll
        for (int j = 0; j < 4; j++)
#pragma unroll
            for (int r = 0; r < 4; r++) acc[i][j][r] = 0.f;

    load_stage(sbase, A, W, m0, n0, 0);
    CP_COMMIT();

    const int NITER = Dd / GBK;
    for (int it = 0; it < NITER; it++) {
        CP_WAIT0();
        __syncthreads();
        const char* buf = smem + (it & 1) * STAGE_BYTES;
        if (it + 1 < NITER) {
            load_stage(sbase + ((it + 1) & 1) * STAGE_BYTES, A, W, m0, n0,
                       (it + 1) * GBK);
            CP_COMMIT();
        }
        const float* As = (const float*)buf;
        const float* Bs = (const float*)(buf + A_BYTES);

#pragma unroll
        for (int ks = 0; ks < 2; ks++) {
            const int kc = ks * 16 + 2 * q4;
            uint32_t ah[4][4], al[4][4];
#pragma unroll
            for (int i = 0; i < 4; i++) {
                const float* r0 = As + (wm * 64 + i * 16 + g8) * APITCH + kc;
                const float* r1 = r0 + 8 * APITCH;
                float2 p00 = *(const float2*)r0;
                float2 p10 = *(const float2*)r1;
                float2 p01 = *(const float2*)(r0 + 8);
                float2 p11 = *(const float2*)(r1 + 8);
                bf16_split2(p00.x, p00.y, ah[i][0], al[i][0]);
                bf16_split2(p10.x, p10.y, ah[i][1], al[i][1]);
                bf16_split2(p01.x, p01.y, ah[i][2], al[i][2]);
                bf16_split2(p11.x, p11.y, ah[i][3], al[i][3]);
            }
#pragma unroll
            for (int j = 0; j < 4; j++) {
                const int nn = wn * 32 + j * 8 + g8;
                const float* bc = Bs + (ks * 16 + 2 * q4) * BPITCH + nn;
                uint32_t b0h, b0l, b1h, b1l;
                bf16_split2(bc[0], bc[BPITCH], b0h, b0l);
                bf16_split2(bc[8 * BPITCH], bc[9 * BPITCH], b1h, b1l);
#pragma unroll
                for (int i = 0; i < 4; i++) {
                    mma_bf16(acc[i][j], ah[i], b0h, b1h);
                    mma_bf16(acc[i][j], al[i], b0h, b1h);
                    mma_bf16(acc[i][j], ah[i], b0l, b1l);
                }
            }
        }
    }

    const int mbase = m0 + wm * 64;
#pragma unroll
    for (int j = 0; j < 4; j++) {
        const int nc = wn * 32 + j * 8 + 2 * q4;
        const float bx = bias[n0 + nc];
        const float by = bias[n0 + nc + 1];
#pragma unroll
        for (int i = 0; i < 4; i++) {
            const int r0 = mbase + i * 16 + g8;
#pragma unroll
            for (int half = 0; half < 2; half++) {
                const int m = r0 + half * 8;
                float2 val;
                val.x = acc[i][j][half * 2]     + bx;
                val.y = acc[i][j][half * 2 + 1] + by;
                if (MODE == 3) {
                    *(float2*)(Cout + (size_t)m * Dd + n0 + nc) = val;
                } else {
                    float* dst = (MODE == 0) ? g_q : (MODE == 1) ? g_k : g_v;
                    const int h = n0 >> 7;
                    const int b = m >> 11;
                    const int t = m & 2047;
                    *(float2*)(dst + (size_t)(((b * Hh + h) * Tt) + t) * DHd + nc) = val;
                }
            }
        }
    }
}

// ===========================================================================
// Flash attention (causal) on tensor cores, 3xBF16, online softmax.
// BM=128 (8 warps x 16 rows), BN=64, DH=128. 256 threads.
// ===========================================================================
#define FBM 128
#define FBN 64
#define QPITCH 136     // == 8 mod 32 (float2 A-frag loads)
#define KPITCH 136     // == 8 mod 32 (float2 B-frag loads from key rows)
#define VPITCH 132     // == 4 mod 32 (scalar B-frag loads, d-major cols)
#define PPITCH 72      // == 8 mod 32 (float2 A-frag loads)
#define F_OQ  0
#define F_OK0 (FBM * QPITCH)                    // 17408
#define F_OK1 (F_OK0 + FBN * KPITCH)            // 26112
#define F_OV  (F_OK1 + FBN * KPITCH)            // 34816
#define F_OP  (F_OV + FBN * VPITCH)             // 43264
#define FLASH_FLOATS (F_OP + FBM * PPITCH)      // 52480
#define FLASH_SMEM (FLASH_FLOATS * 4)           // 209920

__device__ __forceinline__ void flash_load_k(uint32_t sdst, const float* __restrict__ src) {
    const int tid = threadIdx.x;
#pragma unroll
    for (int l = 0; l < 8; l++) {
        int e = tid + l * 256;
        int r = e >> 5, c = e & 31;
        cp16(sdst + (uint32_t)(r * KPITCH + c * 4) * 4, src + r * 128 + c * 4);
    }
}
__device__ __forceinline__ void flash_load_v(uint32_t sdst, const float* __restrict__ src) {
    const int tid = threadIdx.x;
#pragma unroll
    for (int l = 0; l < 8; l++) {
        int e = tid + l * 256;
        int r = e >> 5, c = e & 31;
        cp16(sdst + (uint32_t)(r * VPITCH + c * 4) * 4, src + r * 128 + c * 4);
    }
}

__global__ __launch_bounds__(256, 1)
void flash_tc()
{
    extern __shared__ float sm[];
    const uint32_t sb = smem_u32(sm);
    const int qb = blockIdx.x;
    const int h  = blockIdx.y;
    const int b  = blockIdx.z;
    const int q0 = qb * FBM;
    const int tid  = threadIdx.x;
    const int w    = tid >> 5;
    const int lane = tid & 31;
    const int q4   = lane & 3;
    const int rl   = lane >> 2;

    float* Qs = sm;
    float* Kb[2] = {sm + F_OK0, sm + F_OK1};
    float* Vs = sm + F_OV;
    float* Ps = sm + F_OP;
    const uint32_t kOff[2] = {sb + F_OK0 * 4, sb + F_OK1 * 4};
    const uint32_t vOff = sb + F_OV * 4;

    const size_t bh = (size_t)(b * Hh + h) * Tt;
    const float* qp    = g_q + (bh + q0) * DHd;
    const float* kbase = g_k + bh * DHd;
    const float* vbase = g_v + bh * DHd;

    // Load Q (scaled) into smem
#pragma unroll
    for (int l = 0; l < 16; l++) {
        int e = tid + l * 256;          // float4 units
        int r = e >> 5, c = e & 31;
        float4 v = *(const float4*)(qp + r * 128 + c * 4);
        float* d = Qs + r * QPITCH + c * 4;
        d[0] = v.x * SCALE; d[1] = v.y * SCALE;
        d[2] = v.z * SCALE; d[3] = v.w * SCALE;
    }

    flash_load_k(kOff[0], kbase);
    CP_COMMIT();
    flash_load_v(vOff, vbase);
    CP_COMMIT();

    float m_lo = -1e30f, m_hi = -1e30f, l_lo = 0.f, l_hi = 0.f;
    float o[16][4];
#pragma unroll
    for (int nt = 0; nt < 16; nt++)
#pragma unroll
        for (int r = 0; r < 4; r++) o[nt][r] = 0.f;

    const int rowbase = q0 + w * 16;
    const int nkt = 2 * qb + 2;

    for (int t = 0; t < nkt; t++) {
        const int k0 = t * FBN;
        const bool active = (k0 <= rowbase + 15);
        CP_WAIT1();            // K_t ready
        __syncthreads();

        float sacc[8][4];
        if (active) {
            const float* Ks = Kb[t & 1];
#pragma unroll
            for (int j = 0; j < 8; j++)
#pragma unroll
                for (int r = 0; r < 4; r++) sacc[j][r] = 0.f;

#pragma unroll
            for (int ks = 0; ks < 8; ks++) {
                const int kc = ks * 16 + 2 * q4;
                const float* qrow = Qs + (w * 16 + rl) * QPITCH + kc;
                float2 p00 = *(const float2*)qrow;
                float2 p10 = *(const float2*)(qrow + 8 * QPITCH);
                float2 p01 = *(const float2*)(qrow + 8);
                float2 p11 = *(const float2*)(qrow + 8 * QPITCH + 8);
                uint32_t ah[4], al[4];
                bf16_split2(p00.x, p00.y, ah[0], al[0]);
                bf16_split2(p10.x, p10.y, ah[1], al[1]);
                bf16_split2(p01.x, p01.y, ah[2], al[2]);
                bf16_split2(p11.x, p11.y, ah[3], al[3]);
#pragma unroll
                for (int j = 0; j < 8; j++) {
                    const float* kr = Ks + (j * 8 + rl) * KPITCH + kc;
                    float2 k0p = *(const float2*)kr;
                    float2 k1p = *(const float2*)(kr + 8);
                    uint32_t b0h, b0l, b1h, b1l;
                    bf16_split2(k0p.x, k0p.y, b0h, b0l);
                    bf16_split2(k1p.x, k1p.y, b1h, b1l);
                    mma_bf16(sacc[j], ah, b0h, b1h);
                    mma_bf16(sacc[j], al, b0h, b1h);
                    mma_bf16(sacc[j], ah, b0l, b1l);
                }
            }
        }

        if (t + 1 < nkt) {
            flash_load_k(kOff[(t + 1) & 1], kbase + (size_t)(t + 1) * FBN * 128);
            CP_COMMIT();
            CP_WAIT1();        // V_t ready
        } else {
            CP_WAIT0();
        }
        __syncthreads();

        if (active) {
            const int R_lo = rowbase + rl;
            const int R_hi = R_lo + 8;
            const bool needmask = (k0 + FBN - 1) > rowbase;
            float tl = -1e30f, th = -1e30f;
#pragma unroll
            for (int j = 0; j < 8; j++) {
                if (needmask) {
                    const int C = k0 + j * 8 + 2 * q4;
                    if (C > R_lo)     sacc[j][0] = -1e30f;
                    if (C + 1 > R_lo) sacc[j][1] = -1e30f;
                    if (C > R_hi)     sacc[j][2] = -1e30f;
                    if (C + 1 > R_hi) sacc[j][3] = -1e30f;
                }
                tl = fmaxf(tl, fmaxf(sacc[j][0], sacc[j][1]));
                th = fmaxf(th, fmaxf(sacc[j][2], sacc[j][3]));
            }
            tl = fmaxf(tl, __shfl_xor_sync(0xffffffffu, tl, 1));
            tl = fmaxf(tl, __shfl_xor_sync(0xffffffffu, tl, 2));
            th = fmaxf(th, __shfl_xor_sync(0xffffffffu, th, 1));
            th = fmaxf(th, __shfl_xor_sync(0xffffffffu, th, 2));

            const float mn_lo = fmaxf(m_lo, tl);
            const float mn_hi = fmaxf(m_hi, th);
            const float a_lo = __expf(m_lo - mn_lo);
            const float a_hi = __expf(m_hi - mn_hi);
            m_lo = mn_lo; m_hi = mn_hi;

            float sum_lo = 0.f, sum_hi = 0.f;
            float* prow_lo = Ps + (w * 16 + rl) * PPITCH;
            float* prow_hi = prow_lo + 8 * PPITCH;
#pragma unroll
            for (int j = 0; j < 8; j++) {
                float p0 = __expf(sacc[j][0] - mn_lo);
                float p1 = __expf(sacc[j][1] - mn_lo);
                float p2 = __expf(sacc[j][2] - mn_hi);
                float p3 = __expf(sacc[j][3] - mn_hi);
                sum_lo += p0 + p1;
                sum_hi += p2 + p3;
                *(float2*)(prow_lo + j * 8 + 2 * q4) = make_float2(p0, p1);
                *(float2*)(prow_hi + j * 8 + 2 * q4) = make_float2(p2, p3);
            }
            sum_lo += __shfl_xor_sync(0xffffffffu, sum_lo, 1);
            sum_lo += __shfl_xor_sync(0xffffffffu, sum_lo, 2);
            sum_hi += __shfl_xor_sync(0xffffffffu, sum_hi, 1);
            sum_hi += __shfl_xor_sync(0xffffffffu, sum_hi, 2);
            l_lo = l_lo * a_lo + sum_lo;
            l_hi = l_hi * a_hi + sum_hi;

#pragma unroll
            for (int nt = 0; nt < 16; nt++) {
                o[nt][0] *= a_lo; o[nt][1] *= a_lo;
                o[nt][2] *= a_hi; o[nt][3] *= a_hi;
            }
            __syncwarp();

            // O += P @ V  (3xBF16)
#pragma unroll
            for (int ks = 0; ks < 4; ks++) {
                const int kc = ks * 16 + 2 * q4;
                const float* prow = Ps + (w * 16 + rl) * PPITCH + kc;
                float2 p00 = *(const float2*)prow;
                float2 p10 = *(const float2*)(prow + 8 * PPITCH);
                float2 p01 = *(const float2*)(prow + 8);
                float2 p11 = *(const float2*)(prow + 8 * PPITCH + 8);
                uint32_t ph[4], pl[4];
                bf16_split2(p00.x, p00.y, ph[0], pl[0]);
                bf16_split2(p10.x, p10.y, ph[1], pl[1]);
                bf16_split2(p01.x, p01.y, ph[2], pl[2]);
                bf16_split2(p11.x, p11.y, ph[3], pl[3]);
#pragma unroll
                for (int nt = 0; nt < 16; nt++) {
                    const float* vc = Vs + kc * VPITCH + nt * 8 + rl;
                    uint32_t b0h, b0l, b1h, b1l;
                    bf16_split2(vc[0], vc[VPITCH], b0h, b0l);
                    bf16_split2(vc[8 * VPITCH], vc[9 * VPITCH], b1h, b1l);
                    mma_bf16(o[nt], ph, b0h, b1h);
                    mma_bf16(o[nt], pl, b0h, b1h);
                    mma_bf16(o[nt], ph, b0l, b1l);
                }
            }
        }
        __syncthreads();

        if (t + 1 < nkt) {
            flash_load_v(vOff, vbase + (size_t)(t + 1) * FBN * 128);
            CP_COMMIT();
        }
    }

    // Epilogue: divide by l, write [B,T,D]
    const float il_lo = 1.f / l_lo;
    const float il_hi = 1.f / l_hi;
    float* ob = g_att + (size_t)(b * Tt + rowbase) * Dd + h * DHd;
#pragma unroll
    for (int nt = 0; nt < 16; nt++) {
        *(float2*)(ob + (size_t)rl * Dd + nt * 8 + 2 * q4) =
            make_float2(o[nt][0] * il_lo, o[nt][1] * il_lo);
        *(float2*)(ob + (size_t)(rl + 8) * Dd + nt * 8 + 2 * q4) =
            make_float2(o[nt][2] * il_hi, o[nt][3] * il_hi);
    }
}

// ===========================================================================
extern "C" void kernel_launch(void* const* d_in, const int* in_sizes, int n_in,
                              void* d_out, int out_size)
{
    const float* x  = (const float*)d_in[0];
    const float* Wq = (const float*)d_in[1];
    const float* bq = (const float*)d_in[2];
    const float* Wk = (const float*)d_in[3];
    const float* bk = (const float*)d_in[4];
    const float* Wv = (const float*)d_in[5];
    const float* bv = (const float*)d_in[6];
    const float* Wo = (const float*)d_in[7];
    const float* bo = (const float*)d_in[8];
    float* out = (float*)d_out;

    float* att_ptr = nullptr;
    cudaGetSymbolAddress((void**)&att_ptr, g_att);

    cudaFuncSetAttribute(gemm_tc<0>, cudaFuncAttributeMaxDynamicSharedMemorySize, GEMM_SMEM);
    cudaFuncSetAttribute(gemm_tc<1>, cudaFuncAttributeMaxDynamicSharedMemorySize, GEMM_SMEM);
    cudaFuncSetAttribute(gemm_tc<2>, cudaFuncAttributeMaxDynamicSharedMemorySize, GEMM_SMEM);
    cudaFuncSetAttribute(gemm_tc<3>, cudaFuncAttributeMaxDynamicSharedMemorySize, GEMM_SMEM);

    dim3 ggrid(Dd / GBN, Mm / GBM);   // (16, 64)
    gemm_tc<0><<<ggrid, 256, GEMM_SMEM>>>(x, Wq, bq, nullptr);
    gemm_tc<1><<<ggrid, 256, GEMM_SMEM>>>(x, Wk, bk, nullptr);
    gemm_tc<2><<<ggrid, 256, GEMM_SMEM>>>(x, Wv, bv, nullptr);

    cudaFuncSetAttribute(flash_tc, cudaFuncAttributeMaxDynamicSharedMemorySize, FLASH_SMEM);
    dim3 fgrid(Tt / FBM, Hh, Bq);     // (16, 16, 4)
    flash_tc<<<fgrid, 256, FLASH_SMEM>>>();

    gemm_tc<3><<<ggrid, 256, GEMM_SMEM>>>(att_ptr, Wo, bo, out);
}

// round 7
// speedup vs baseline: 2.9400x; 1.0530x over previous
#include <cuda_runtime.h>
#include <cuda_bf16.h>
#include <math_constants.h>
#include <cstdint>

#define Bq  4
#define Tt  2048
#define Dd  2048
#define Hh  16
#define DHd 128
#define Mm  (Bq * Tt)        // 8192
#define SCALE 0.08838834764831845f  // DH^-0.5

// ---------------------------------------------------------------------------
// Persistent bf16 hi/lo tensors (allocation-free rule: __device__ globals)
// ---------------------------------------------------------------------------
__device__ __align__(256) __nv_bfloat16 g_xh[Mm * Dd];
__device__ __align__(256) __nv_bfloat16 g_xl[Mm * Dd];
__device__ __align__(256) __nv_bfloat16 g_wth[4][Dd * Dd];   // W^T hi, [N][K]
__device__ __align__(256) __nv_bfloat16 g_wtl[4][Dd * Dd];   // W^T lo
__device__ __align__(256) __nv_bfloat16 g_qh[Bq * Hh * Tt * DHd];
__device__ __align__(256) __nv_bfloat16 g_ql[Bq * Hh * Tt * DHd];
__device__ __align__(256) __nv_bfloat16 g_kh[Bq * Hh * Tt * DHd];
__device__ __align__(256) __nv_bfloat16 g_kl[Bq * Hh * Tt * DHd];
__device__ __align__(256) __nv_bfloat16 g_vth[Bq * Hh * DHd * Tt];  // [b,h,d,t]
__device__ __align__(256) __nv_bfloat16 g_vtl[Bq * Hh * DHd * Tt];
__device__ __align__(256) __nv_bfloat16 g_atth[Bq * Tt * Dd];
__device__ __align__(256) __nv_bfloat16 g_attl[Bq * Tt * Dd];

// ===========================================================================
// Helpers
// ===========================================================================
__device__ __forceinline__ uint32_t smem_u32(const void* p) {
    uint32_t a;
    asm("{ .reg .u64 t; cvta.to.shared.u64 t, %1; cvt.u32.u64 %0, t; }" : "=r"(a) : "l"(p));
    return a;
}
__device__ __forceinline__ void cp16(uint32_t dst, const void* src) {
    asm volatile("cp.async.cg.shared.global [%0], [%1], 16;" :: "r"(dst), "l"(src));
}
#define CP_COMMIT() asm volatile("cp.async.commit_group;" ::: "memory")
#define CP_WAIT0()  asm volatile("cp.async.wait_group 0;" ::: "memory")
#define CP_WAIT1()  asm volatile("cp.async.wait_group 1;" ::: "memory")

__device__ __forceinline__ void mma_bf16(float* c, const uint32_t* a,
                                         uint32_t b0, uint32_t b1) {
    asm volatile(
        "mma.sync.aligned.m16n8k16.row.col.f32.bf16.bf16.f32 "
        "{%0,%1,%2,%3}, {%4,%5,%6,%7}, {%8,%9}, {%0,%1,%2,%3};"
        : "+f"(c[0]), "+f"(c[1]), "+f"(c[2]), "+f"(c[3])
        : "r"(a[0]), "r"(a[1]), "r"(a[2]), "r"(a[3]), "r"(b0), "r"(b1));
}
__device__ __forceinline__ uint32_t pack_bf16(float v0, float v1) {
    uint32_t h;
    asm("cvt.rn.bf16x2.f32 %0, %1, %2;" : "=r"(h) : "f"(v1), "f"(v0));
    return h;
}
// Split pair of fp32 into bf16x2 hi + bf16x2 residual (lower 16 bits = v0)
__device__ __forceinline__ void bf16_split2(float v0, float v1,
                                            uint32_t& hi, uint32_t& lo) {
    uint32_t h = pack_bf16(v0, v1);
    float f0 = __uint_as_float(h << 16);
    float f1 = __uint_as_float(h & 0xffff0000u);
    lo = pack_bf16(v0 - f0, v1 - f1);
    hi = h;
}

// ===========================================================================
// Conversion kernels
// ===========================================================================
__global__ __launch_bounds__(256)
void conv_x_kernel(const float* __restrict__ src,
                   __nv_bfloat16* __restrict__ hi, __nv_bfloat16* __restrict__ lo)
{
    const size_t i4 = ((size_t)blockIdx.x * 256 + threadIdx.x) * 4;
    float4 v = *(const float4*)(src + i4);
    uint32_t h0, l0, h1, l1;
    bf16_split2(v.x, v.y, h0, l0);
    bf16_split2(v.z, v.w, h1, l1);
    *(uint2*)(hi + i4) = make_uint2(h0, h1);
    *(uint2*)(lo + i4) = make_uint2(l0, l1);
}

// Transpose W [K][N] -> W^T [N][K] and split to bf16 hi/lo
__global__ __launch_bounds__(256)
void conv_w_kernel(const float* __restrict__ W,
                   __nv_bfloat16* __restrict__ Th, __nv_bfloat16* __restrict__ Tl)
{
    __shared__ float tile[32][33];
    int x = blockIdx.x * 32 + threadIdx.x;   // N index on read
    int y = blockIdx.y * 32 + threadIdx.y;   // K index on read
#pragma unroll
    for (int j = 0; j < 32; j += 8)
        tile[threadIdx.y + j][threadIdx.x] = W[(size_t)(y + j) * Dd + x];
    __syncthreads();
    int n = blockIdx.x * 32 + threadIdx.y;   // output row (N)
    int k = blockIdx.y * 32 + threadIdx.x;   // output col (K)
#pragma unroll
    for (int j = 0; j < 32; j += 8) {
        float v = tile[threadIdx.x][threadIdx.y + j];
        __nv_bfloat16 h = __float2bfloat16(v);
        __nv_bfloat16 l = __float2bfloat16(v - __bfloat162float(h));
        Th[(size_t)(n + j) * Dd + k] = h;
        Tl[(size_t)(n + j) * Dd + k] = l;
    }
}

// ===========================================================================
// bf16 hi/lo tensor-core GEMM: C[M,N] = A @ W + bias, 3-pass compensation.
// BM=BN=128, BK=32, 256 threads (8 warps 2x4), warp tile 64x32.
// 3-stage cp.async ring. Operands are pre-split bf16 (Ah,Al) + (Bth,Btl [N][K]).
// MODE 0 -> q (hi/lo head-split), 1 -> k, 2 -> v transposed [b,h,d,t],
// MODE 3 -> fp32 row-major Cout.
// ===========================================================================
#define GBM 128
#define GBN 128
#define GBK 32
#define GP32 20                       // u32 pitch of each tile row (40 bf16)
#define TILE_BYTES (128 * GP32 * 4)   // 10240
#define STAGE_BYTES (4 * TILE_BYTES)  // 40960: Ah|Al|Bh|Bl
#define GEMM_SMEM (3 * STAGE_BYTES)   // 122880

__device__ __forceinline__ void load_stage(uint32_t sdst,
        const __nv_bfloat16* __restrict__ Ah, const __nv_bfloat16* __restrict__ Al,
        const __nv_bfloat16* __restrict__ Bh, const __nv_bfloat16* __restrict__ Bl,
        int m0, int n0, int k0)
{
    const int tid = threadIdx.x;
#pragma unroll
    for (int l = 0; l < 2; l++) {
        int e = tid + 256 * l;
        int r = e >> 2, c = e & 3;
        uint32_t doff = (uint32_t)(r * 80 + c * 16);
        size_t soff = (size_t)(m0 + r) * Dd + k0 + c * 8;
        cp16(sdst + doff, Ah + soff);
        cp16(sdst + TILE_BYTES + doff, Al + soff);
    }
#pragma unroll
    for (int l = 0; l < 2; l++) {
        int e = tid + 256 * l;
        int r = e >> 2, c = e & 3;
        uint32_t doff = (uint32_t)(r * 80 + c * 16);
        size_t soff = (size_t)(n0 + r) * Dd + k0 + c * 8;
        cp16(sdst + 2 * TILE_BYTES + doff, Bh + soff);
        cp16(sdst + 3 * TILE_BYTES + doff, Bl + soff);
    }
}

template <int MODE>
__global__ __launch_bounds__(256, 1)
void gemm_bf(const __nv_bfloat16* __restrict__ Ah, const __nv_bfloat16* __restrict__ Al,
             const __nv_bfloat16* __restrict__ Bth, const __nv_bfloat16* __restrict__ Btl,
             const float* __restrict__ bias, float* __restrict__ Cout)
{
    extern __shared__ char smem[];
    const uint32_t sbase = smem_u32(smem);
    const int tid  = threadIdx.x;
    const int wid  = tid >> 5;
    const int lane = tid & 31;
    const int q4   = lane & 3;
    const int g8   = lane >> 2;
    const int wm   = wid >> 2;
    const int wn   = wid & 3;
    const int m0   = blockIdx.y * GBM;
    const int n0   = blockIdx.x * GBN;

    float acc[4][4][4];
#pragma unroll
    for (int i = 0; i < 4; i++)
#pragma unroll
        for (int j = 0; j < 4; j++)
#pragma unroll
            for (int r = 0; r < 4; r++) acc[i][j][r] = 0.f;

    load_stage(sbase, Ah, Al, Bth, Btl, m0, n0, 0);
    CP_COMMIT();
    load_stage(sbase + STAGE_BYTES, Ah, Al, Bth, Btl, m0, n0, GBK);
    CP_COMMIT();

    const int NITER = Dd / GBK;   // 64
    int stage = 0;
    for (int it = 0; it < NITER; it++) {
        CP_WAIT1();
        __syncthreads();
        if (it + 2 < NITER) {
            int ns = stage + 2; if (ns >= 3) ns -= 3;
            load_stage(sbase + (uint32_t)ns * STAGE_BYTES, Ah, Al, Bth, Btl,
                       m0, n0, (it + 2) * GBK);
            CP_COMMIT();
        }
        const uint32_t* S = (const uint32_t*)(smem + stage * STAGE_BYTES);
        const uint32_t* As_h = S;
        const uint32_t* As_l = S + TILE_BYTES / 4;
        const uint32_t* Bs_h = S + 2 * (TILE_BYTES / 4);
        const uint32_t* Bs_l = S + 3 * (TILE_BYTES / 4);

#pragma unroll
        for (int ks = 0; ks < 2; ks++) {
            const int base = ks * 8 + q4;
            uint32_t ah[4][4], al[4][4];
#pragma unroll
            for (int i = 0; i < 4; i++) {
                const uint32_t* p = As_h + (wm * 64 + i * 16 + g8) * GP32 + base;
                const uint32_t* q = As_l + (wm * 64 + i * 16 + g8) * GP32 + base;
                ah[i][0] = p[0]; ah[i][1] = p[8 * GP32]; ah[i][2] = p[4]; ah[i][3] = p[8 * GP32 + 4];
                al[i][0] = q[0]; al[i][1] = q[8 * GP32]; al[i][2] = q[4]; al[i][3] = q[8 * GP32 + 4];
            }
#pragma unroll
            for (int j = 0; j < 4; j++) {
                const uint32_t* bp = Bs_h + (wn * 32 + j * 8 + g8) * GP32 + base;
                const uint32_t* bq = Bs_l + (wn * 32 + j * 8 + g8) * GP32 + base;
                uint32_t b0h = bp[0], b1h = bp[4];
                uint32_t b0l = bq[0], b1l = bq[4];
#pragma unroll
                for (int i = 0; i < 4; i++) {
                    mma_bf16(acc[i][j], ah[i], b0h, b1h);
                    mma_bf16(acc[i][j], al[i], b0h, b1h);
                    mma_bf16(acc[i][j], ah[i], b0l, b1l);
                }
            }
        }
        stage++; if (stage >= 3) stage = 0;
    }

    // Epilogue
    const int mbase = m0 + wm * 64;
#pragma unroll
    for (int j = 0; j < 4; j++) {
        const int nc = wn * 32 + j * 8 + 2 * q4;
        const float bx = bias[n0 + nc];
        const float by = bias[n0 + nc + 1];
#pragma unroll
        for (int i = 0; i < 4; i++) {
#pragma unroll
            for (int half = 0; half < 2; half++) {
                const int m = mbase + i * 16 + g8 + half * 8;
                float vx = acc[i][j][half * 2]     + bx;
                float vy = acc[i][j][half * 2 + 1] + by;
                if (MODE == 3) {
                    *(float2*)(Cout + (size_t)m * Dd + n0 + nc) = make_float2(vx, vy);
                } else {
                    const int h = n0 >> 7;
                    const int b = m >> 11;
                    const int t = m & 2047;
                    if (MODE == 2) {
                        // v: transposed [b,h,d,t] hi/lo
                        size_t base = ((size_t)(b * Hh + h) * DHd + nc) * Tt + t;
                        __nv_bfloat16 h0 = __float2bfloat16(vx);
                        __nv_bfloat16 h1 = __float2bfloat16(vy);
                        g_vth[base]       = h0;
                        g_vth[base + Tt]  = h1;
                        g_vtl[base]       = __float2bfloat16(vx - __bfloat162float(h0));
                        g_vtl[base + Tt]  = __float2bfloat16(vy - __bfloat162float(h1));
                    } else {
                        __nv_bfloat16* dh = (MODE == 0) ? g_qh : g_kh;
                        __nv_bfloat16* dl = (MODE == 0) ? g_ql : g_kl;
                        size_t base = ((size_t)((b * Hh + h) * Tt) + t) * DHd + nc;
                        uint32_t hh, ll;
                        bf16_split2(vx, vy, hh, ll);
                        *(uint32_t*)(dh + base) = hh;
                        *(uint32_t*)(dl + base) = ll;
                    }
                }
            }
        }
    }
}

// ===========================================================================
// Flash attention (causal), bf16 hi/lo operands, 3-pass MMA, online softmax.
// BM=128 (8 warps x 16 rows), BN=64, DH=128. 256 threads.
// smem (bytes): Qh|Ql (pitch 272B, 128 rows) | K0h|K0l|K1h|K1l (272B, 64 rows)
//               | Vth|Vtl (144B, 128 rows) | Ph|Pl (144B, 128 rows)
// ===========================================================================
#define FBM 128
#define FBN 64
#define QP32 68     // u32 pitch (136 bf16, 272B)
#define KP32 68
#define VP32 36     // 72 bf16, 144B
#define PP32 36
#define F_QH  0u
#define F_QL  34816u
#define F_K0H 69632u
#define F_K0L 87040u
#define F_K1H 104448u
#define F_K1L 121856u
#define F_VH  139264u
#define F_VL  157696u
#define F_PH  176128u
#define F_PL  194560u
#define FLASH_SMEM 212992

__device__ __forceinline__ void flash_load_q(uint32_t sb,
        const __nv_bfloat16* __restrict__ qh, const __nv_bfloat16* __restrict__ ql) {
    const int tid = threadIdx.x;
#pragma unroll
    for (int l = 0; l < 8; l++) {
        int e = tid + l * 256;
        int r = e >> 4, c = e & 15;
        uint32_t doff = (uint32_t)(r * 272 + c * 16);
        cp16(sb + F_QH + doff, qh + r * 128 + c * 8);
        cp16(sb + F_QL + doff, ql + r * 128 + c * 8);
    }
}
__device__ __forceinline__ void flash_load_k(uint32_t dsth, uint32_t dstl,
        const __nv_bfloat16* __restrict__ kh, const __nv_bfloat16* __restrict__ kl) {
    const int tid = threadIdx.x;
#pragma unroll
    for (int l = 0; l < 4; l++) {
        int e = tid + l * 256;
        int r = e >> 4, c = e & 15;
        uint32_t doff = (uint32_t)(r * 272 + c * 16);
        cp16(dsth + doff, kh + r * 128 + c * 8);
        cp16(dstl + doff, kl + r * 128 + c * 8);
    }
}
__device__ __forceinline__ void flash_load_v(uint32_t sb,
        const __nv_bfloat16* __restrict__ vh, const __nv_bfloat16* __restrict__ vl) {
    const int tid = threadIdx.x;
#pragma unroll
    for (int l = 0; l < 4; l++) {
        int e = tid + l * 256;
        int r = e >> 3, c = e & 7;
        uint32_t doff = (uint32_t)(r * 144 + c * 16);
        cp16(sb + F_VH + doff, vh + (size_t)r * Tt + c * 8);
        cp16(sb + F_VL + doff, vl + (size_t)r * Tt + c * 8);
    }
}

__global__ __launch_bounds__(256, 1)
void flash_tc()
{
    extern __shared__ char smc[];
    const uint32_t sb = smem_u32(smc);
    const int qb = blockIdx.x;
    const int h  = blockIdx.y;
    const int b  = blockIdx.z;
    const int q0 = qb * FBM;
    const int tid  = threadIdx.x;
    const int w    = tid >> 5;
    const int lane = tid & 31;
    const int q4   = lane & 3;
    const int rl   = lane >> 2;

    const uint32_t* Qh32 = (const uint32_t*)(smc + F_QH);
    const uint32_t* Ql32 = (const uint32_t*)(smc + F_QL);
    const uint32_t* Vh32 = (const uint32_t*)(smc + F_VH);
    const uint32_t* Vl32 = (const uint32_t*)(smc + F_VL);
    uint32_t* Ph32 = (uint32_t*)(smc + F_PH);
    uint32_t* Pl32 = (uint32_t*)(smc + F_PL);
    const uint32_t kH[2] = {sb + F_K0H, sb + F_K1H};
    const uint32_t kL[2] = {sb + F_K0L, sb + F_K1L};

    const size_t bh = (size_t)(b * Hh + h) * Tt;
    const __nv_bfloat16* kbh = g_kh + bh * DHd;
    const __nv_bfloat16* kbl = g_kl + bh * DHd;
    const __nv_bfloat16* vbh = g_vth + (size_t)(b * Hh + h) * DHd * Tt;
    const __nv_bfloat16* vbl = g_vtl + (size_t)(b * Hh + h) * DHd * Tt;

    flash_load_q(sb, g_qh + (bh + q0) * DHd, g_ql + (bh + q0) * DHd);
    flash_load_k(kH[0], kL[0], kbh, kbl);
    CP_COMMIT();
    flash_load_v(sb, vbh, vbl);
    CP_COMMIT();

    float m_lo = -1e30f, m_hi = -1e30f, l_lo = 0.f, l_hi = 0.f;
    float o[16][4];
#pragma unroll
    for (int nt = 0; nt < 16; nt++)
#pragma unroll
        for (int r = 0; r < 4; r++) o[nt][r] = 0.f;

    const int rowbase = q0 + w * 16;
    const int nkt = 2 * qb + 2;

    for (int t = 0; t < nkt; t++) {
        const int k0 = t * FBN;
        const bool active = (k0 <= rowbase + 15);
        CP_WAIT1();            // Q + K_t ready
        __syncthreads();

        float sacc[8][4];
        if (active) {
            const uint32_t* Kh32 = (const uint32_t*)(smc + (kH[t & 1] - sb));
            const uint32_t* Kl32 = (const uint32_t*)(smc + (kL[t & 1] - sb));
#pragma unroll
            for (int j = 0; j < 8; j++)
#pragma unroll
                for (int r = 0; r < 4; r++) sacc[j][r] = 0.f;

#pragma unroll
            for (int ks = 0; ks < 8; ks++) {
                const int base = ks * 8 + q4;
                const uint32_t* qh = Qh32 + (w * 16 + rl) * QP32 + base;
                const uint32_t* ql = Ql32 + (w * 16 + rl) * QP32 + base;
                uint32_t ah[4], al[4];
                ah[0] = qh[0]; ah[1] = qh[8 * QP32]; ah[2] = qh[4]; ah[3] = qh[8 * QP32 + 4];
                al[0] = ql[0]; al[1] = ql[8 * QP32]; al[2] = ql[4]; al[3] = ql[8 * QP32 + 4];
#pragma unroll
                for (int j = 0; j < 8; j++) {
                    const uint32_t* kh = Kh32 + (j * 8 + rl) * KP32 + base;
                    const uint32_t* kl = Kl32 + (j * 8 + rl) * KP32 + base;
                    uint32_t b0h = kh[0], b1h = kh[4];
                    uint32_t b0l = kl[0], b1l = kl[4];
                    mma_bf16(sacc[j], ah, b0h, b1h);
                    mma_bf16(sacc[j], al, b0h, b1h);
                    mma_bf16(sacc[j], ah, b0l, b1l);
                }
            }
        }

        if (t + 1 < nkt) {
            flash_load_k(kH[(t + 1) & 1], kL[(t + 1) & 1],
                         kbh + (size_t)(t + 1) * FBN * DHd,
                         kbl + (size_t)(t + 1) * FBN * DHd);
            CP_COMMIT();
            CP_WAIT1();        // V_t ready
        } else {
            CP_WAIT0();
        }
        __syncthreads();

        if (active) {
            const int R_lo = rowbase + rl;
            const int R_hi = R_lo + 8;
            const bool needmask = (k0 + FBN - 1) > rowbase;
            float tl = -1e30f, th = -1e30f;
#pragma unroll
            for (int j = 0; j < 8; j++) {
#pragma unroll
                for (int r = 0; r < 4; r++) sacc[j][r] *= SCALE;
                if (needmask) {
                    const int C = k0 + j * 8 + 2 * q4;
                    if (C > R_lo)     sacc[j][0] = -1e30f;
                    if (C + 1 > R_lo) sacc[j][1] = -1e30f;
                    if (C > R_hi)     sacc[j][2] = -1e30f;
                    if (C + 1 > R_hi) sacc[j][3] = -1e30f;
                }
                tl = fmaxf(tl, fmaxf(sacc[j][0], sacc[j][1]));
                th = fmaxf(th, fmaxf(sacc[j][2], sacc[j][3]));
            }
            tl = fmaxf(tl, __shfl_xor_sync(0xffffffffu, tl, 1));
            tl = fmaxf(tl, __shfl_xor_sync(0xffffffffu, tl, 2));
            th = fmaxf(th, __shfl_xor_sync(0xffffffffu, th, 1));
            th = fmaxf(th, __shfl_xor_sync(0xffffffffu, th, 2));

            const float mn_lo = fmaxf(m_lo, tl);
            const float mn_hi = fmaxf(m_hi, th);
            const float a_lo = __expf(m_lo - mn_lo);
            const float a_hi = __expf(m_hi - mn_hi);
            m_lo = mn_lo; m_hi = mn_hi;

            float sum_lo = 0.f, sum_hi = 0.f;
            uint32_t* prl_h = Ph32 + (w * 16 + rl) * PP32;
            uint32_t* prl_l = Pl32 + (w * 16 + rl) * PP32;
#pragma unroll
            for (int j = 0; j < 8; j++) {
                float p0 = __expf(sacc[j][0] - mn_lo);
                float p1 = __expf(sacc[j][1] - mn_lo);
                float p2 = __expf(sacc[j][2] - mn_hi);
                float p3 = __expf(sacc[j][3] - mn_hi);
                sum_lo += p0 + p1;
                sum_hi += p2 + p3;
                uint32_t hh, ll;
                bf16_split2(p0, p1, hh, ll);
                prl_h[j * 4 + q4] = hh;
                prl_l[j * 4 + q4] = ll;
                bf16_split2(p2, p3, hh, ll);
                prl_h[8 * PP32 + j * 4 + q4] = hh;
                prl_l[8 * PP32 + j * 4 + q4] = ll;
            }
            sum_lo += __shfl_xor_sync(0xffffffffu, sum_lo, 1);
            sum_lo += __shfl_xor_sync(0xffffffffu, sum_lo, 2);
            sum_hi += __shfl_xor_sync(0xffffffffu, sum_hi, 1);
            sum_hi += __shfl_xor_sync(0xffffffffu, sum_hi, 2);
            l_lo = l_lo * a_lo + sum_lo;
            l_hi = l_hi * a_hi + sum_hi;

#pragma unroll
            for (int nt = 0; nt < 16; nt++) {
                o[nt][0] *= a_lo; o[nt][1] *= a_lo;
                o[nt][2] *= a_hi; o[nt][3] *= a_hi;
            }
            __syncwarp();

            // O += P @ V  (3-pass bf16)
#pragma unroll
            for (int ks = 0; ks < 4; ks++) {
                const int base = ks * 8 + q4;
                const uint32_t* ph_ = Ph32 + (w * 16 + rl) * PP32 + base;
                const uint32_t* pl_ = Pl32 + (w * 16 + rl) * PP32 + base;
                uint32_t ph[4], pl[4];
                ph[0] = ph_[0]; ph[1] = ph_[8 * PP32]; ph[2] = ph_[4]; ph[3] = ph_[8 * PP32 + 4];
                pl[0] = pl_[0]; pl[1] = pl_[8 * PP32]; pl[2] = pl_[4]; pl[3] = pl_[8 * PP32 + 4];
#pragma unroll
                for (int nt = 0; nt < 16; nt++) {
                    const uint32_t* vh = Vh32 + (nt * 8 + rl) * VP32 + base;
                    const uint32_t* vl = Vl32 + (nt * 8 + rl) * VP32 + base;
                    uint32_t b0h = vh[0], b1h = vh[4];
                    uint32_t b0l = vl[0], b1l = vl[4];
                    mma_bf16(o[nt], ph, b0h, b1h);
                    mma_bf16(o[nt], pl, b0h, b1h);
                    mma_bf16(o[nt], ph, b0l, b1l);
                }
            }
        }
        __syncthreads();

        if (t + 1 < nkt) {
            flash_load_v(sb, vbh + (size_t)(t + 1) * FBN, vbl + (size_t)(t + 1) * FBN);
            CP_COMMIT();
        }
    }

    // Epilogue: divide by l, split, write att hi/lo [B,T,D]
    const float il_lo = 1.f / l_lo;
    const float il_hi = 1.f / l_hi;
    __nv_bfloat16* oh = g_atth + ((size_t)(b * Tt + rowbase)) * Dd + h * DHd;
    __nv_bfloat16* ol = g_attl + ((size_t)(b * Tt + rowbase)) * Dd + h * DHd;
#pragma unroll
    for (int nt = 0; nt < 16; nt++) {
        uint32_t hh, ll;
        size_t idx0 = (size_t)rl * Dd + nt * 8 + 2 * q4;
        bf16_split2(o[nt][0] * il_lo, o[nt][1] * il_lo, hh, ll);
        *(uint32_t*)(oh + idx0) = hh;
        *(uint32_t*)(ol + idx0) = ll;
        size_t idx1 = (size_t)(rl + 8) * Dd + nt * 8 + 2 * q4;
        bf16_split2(o[nt][2] * il_hi, o[nt][3] * il_hi, hh, ll);
        *(uint32_t*)(oh + idx1) = hh;
        *(uint32_t*)(ol + idx1) = ll;
    }
}

// ===========================================================================
extern "C" void kernel_launch(void* const* d_in, const int* in_sizes, int n_in,
                              void* d_out, int out_size)
{
    const float* x  = (const float*)d_in[0];
    const float* Wq = (const float*)d_in[1];
    const float* bq = (const float*)d_in[2];
    const float* Wk = (const float*)d_in[3];
    const float* bk = (const float*)d_in[4];
    const float* Wv = (const float*)d_in[5];
    const float* bv = (const float*)d_in[6];
    const float* Wo = (const float*)d_in[7];
    const float* bo = (const float*)d_in[8];
    float* out = (float*)d_out;

    __nv_bfloat16 *xh, *xl, *wth, *wtl, *atth, *attl;
    cudaGetSymbolAddress((void**)&xh,   g_xh);
    cudaGetSymbolAddress((void**)&xl,   g_xl);
    cudaGetSymbolAddress((void**)&wth,  g_wth);
    cudaGetSymbolAddress((void**)&wtl,  g_wtl);
    cudaGetSymbolAddress((void**)&atth, g_atth);
    cudaGetSymbolAddress((void**)&attl, g_attl);

    // 1) Convert inputs to bf16 hi/lo (x natural, W transposed)
    conv_x_kernel<<<(Mm * Dd) / 1024, 256>>>(x, xh, xl);
    dim3 tgrid(Dd / 32, Dd / 32), tblk(32, 8);
    conv_w_kernel<<<tgrid, tblk>>>(Wq, wth + 0 * (size_t)Dd * Dd, wtl + 0 * (size_t)Dd * Dd);
    conv_w_kernel<<<tgrid, tblk>>>(Wk, wth + 1 * (size_t)Dd * Dd, wtl + 1 * (size_t)Dd * Dd);
    conv_w_kernel<<<tgrid, tblk>>>(Wv, wth + 2 * (size_t)Dd * Dd, wtl + 2 * (size_t)Dd * Dd);
    conv_w_kernel<<<tgrid, tblk>>>(Wo, wth + 3 * (size_t)Dd * Dd, wtl + 3 * (size_t)Dd * Dd);

    cudaFuncSetAttribute(gemm_bf<0>, cudaFuncAttributeMaxDynamicSharedMemorySize, GEMM_SMEM);
    cudaFuncSetAttribute(gemm_bf<1>, cudaFuncAttributeMaxDynamicSharedMemorySize, GEMM_SMEM);
    cudaFuncSetAttribute(gemm_bf<2>, cudaFuncAttributeMaxDynamicSharedMemorySize, GEMM_SMEM);
    cudaFuncSetAttribute(gemm_bf<3>, cudaFuncAttributeMaxDynamicSharedMemorySize, GEMM_SMEM);

    // 2) QKV projections
    dim3 ggrid(Dd / GBN, Mm / GBM);   // (16, 64)
    gemm_bf<0><<<ggrid, 256, GEMM_SMEM>>>(xh, xl, wth + 0 * (size_t)Dd * Dd, wtl + 0 * (size_t)Dd * Dd, bq, nullptr);
    gemm_bf<1><<<ggrid, 256, GEMM_SMEM>>>(xh, xl, wth + 1 * (size_t)Dd * Dd, wtl + 1 * (size_t)Dd * Dd, bk, nullptr);
    gemm_bf<2><<<ggrid, 256, GEMM_SMEM>>>(xh, xl, wth + 2 * (size_t)Dd * Dd, wtl + 2 * (size_t)Dd * Dd, bv, nullptr);

    // 3) Flash attention
    cudaFuncSetAttribute(flash_tc, cudaFuncAttributeMaxDynamicSharedMemorySize, FLASH_SMEM);
    dim3 fgrid(Tt / FBM, Hh, Bq);     // (16, 16, 4)
    flash_tc<<<fgrid, 256, FLASH_SMEM>>>();

    // 4) Output projection (fp32 out)
    gemm_bf<3><<<ggrid, 256, GEMM_SMEM>>>(atth, attl, wth + 3 * (size_t)Dd * Dd, wtl + 3 * (size_t)Dd * Dd, bo, out);
}

// round 8
// speedup vs baseline: 3.2164x; 1.0940x over previous
#include <cuda_runtime.h>
#include <cuda_bf16.h>
#include <math_constants.h>
#include <cstdint>

#define Bq  4
#define Tt  2048
#define Dd  2048
#define Hh  16
#define DHd 128
#define Mm  (Bq * Tt)        // 8192
#define SCALE 0.08838834764831845f  // DH^-0.5

// ---------------------------------------------------------------------------
// Persistent bf16 hi/lo tensors (allocation-free rule: __device__ globals)
// ---------------------------------------------------------------------------
__device__ __align__(256) __nv_bfloat16 g_xh[Mm * Dd];
__device__ __align__(256) __nv_bfloat16 g_xl[Mm * Dd];
__device__ __align__(256) __nv_bfloat16 g_wth[4][Dd * Dd];   // W^T hi, [N][K]
__device__ __align__(256) __nv_bfloat16 g_wtl[4][Dd * Dd];   // W^T lo
__device__ __align__(256) __nv_bfloat16 g_qh[Bq * Hh * Tt * DHd];
__device__ __align__(256) __nv_bfloat16 g_ql[Bq * Hh * Tt * DHd];
__device__ __align__(256) __nv_bfloat16 g_kh[Bq * Hh * Tt * DHd];
__device__ __align__(256) __nv_bfloat16 g_kl[Bq * Hh * Tt * DHd];
__device__ __align__(256) __nv_bfloat16 g_vth[Bq * Hh * DHd * Tt];  // [b,h,d,t]
__device__ __align__(256) __nv_bfloat16 g_vtl[Bq * Hh * DHd * Tt];
__device__ __align__(256) __nv_bfloat16 g_atth[Bq * Tt * Dd];
__device__ __align__(256) __nv_bfloat16 g_attl[Bq * Tt * Dd];

// ===========================================================================
// Helpers
// ===========================================================================
__device__ __forceinline__ uint32_t smem_u32(const void* p) {
    uint32_t a;
    asm("{ .reg .u64 t; cvta.to.shared.u64 t, %1; cvt.u32.u64 %0, t; }" : "=r"(a) : "l"(p));
    return a;
}
__device__ __forceinline__ void cp16(uint32_t dst, const void* src) {
    asm volatile("cp.async.cg.shared.global [%0], [%1], 16;" :: "r"(dst), "l"(src));
}
#define CP_COMMIT() asm volatile("cp.async.commit_group;" ::: "memory")
#define CP_WAIT0()  asm volatile("cp.async.wait_group 0;" ::: "memory")
#define CP_WAIT1()  asm volatile("cp.async.wait_group 1;" ::: "memory")

__device__ __forceinline__ void mma_bf16(float* c, const uint32_t* a,
                                         uint32_t b0, uint32_t b1) {
    asm volatile(
        "mma.sync.aligned.m16n8k16.row.col.f32.bf16.bf16.f32 "
        "{%0,%1,%2,%3}, {%4,%5,%6,%7}, {%8,%9}, {%0,%1,%2,%3};"
        : "+f"(c[0]), "+f"(c[1]), "+f"(c[2]), "+f"(c[3])
        : "r"(a[0]), "r"(a[1]), "r"(a[2]), "r"(a[3]), "r"(b0), "r"(b1));
}
__device__ __forceinline__ uint32_t pack_bf16(float v0, float v1) {
    uint32_t h;
    asm("cvt.rn.bf16x2.f32 %0, %1, %2;" : "=r"(h) : "f"(v1), "f"(v0));
    return h;
}
// Split pair of fp32 into bf16x2 hi + bf16x2 residual (lower 16 bits = v0)
__device__ __forceinline__ void bf16_split2(float v0, float v1,
                                            uint32_t& hi, uint32_t& lo) {
    uint32_t h = pack_bf16(v0, v1);
    float f0 = __uint_as_float(h << 16);
    float f1 = __uint_as_float(h & 0xffff0000u);
    lo = pack_bf16(v0 - f0, v1 - f1);
    hi = h;
}

// ===========================================================================
// Conversion kernels
// ===========================================================================
__global__ __launch_bounds__(256)
void conv_x_kernel(const float* __restrict__ src,
                   __nv_bfloat16* __restrict__ hi, __nv_bfloat16* __restrict__ lo)
{
    const size_t i4 = ((size_t)blockIdx.x * 256 + threadIdx.x) * 4;
    float4 v = *(const float4*)(src + i4);
    uint32_t h0, l0, h1, l1;
    bf16_split2(v.x, v.y, h0, l0);
    bf16_split2(v.z, v.w, h1, l1);
    *(uint2*)(hi + i4) = make_uint2(h0, h1);
    *(uint2*)(lo + i4) = make_uint2(l0, l1);
}

// Transpose W [K][N] -> W^T [N][K] and split to bf16 hi/lo
__global__ __launch_bounds__(256)
void conv_w_kernel(const float* __restrict__ W,
                   __nv_bfloat16* __restrict__ Th, __nv_bfloat16* __restrict__ Tl)
{
    __shared__ float tile[32][33];
    int x = blockIdx.x * 32 + threadIdx.x;   // N index on read
    int y = blockIdx.y * 32 + threadIdx.y;   // K index on read
#pragma unroll
    for (int j = 0; j < 32; j += 8)
        tile[threadIdx.y + j][threadIdx.x] = W[(size_t)(y + j) * Dd + x];
    __syncthreads();
    int n = blockIdx.x * 32 + threadIdx.y;   // output row (N)
    int k = blockIdx.y * 32 + threadIdx.x;   // output col (K)
#pragma unroll
    for (int j = 0; j < 32; j += 8) {
        float v = tile[threadIdx.x][threadIdx.y + j];
        __nv_bfloat16 h = __float2bfloat16(v);
        __nv_bfloat16 l = __float2bfloat16(v - __bfloat162float(h));
        Th[(size_t)(n + j) * Dd + k] = h;
        Tl[(size_t)(n + j) * Dd + k] = l;
    }
}

// ===========================================================================
// bf16 hi/lo tensor-core GEMM: C[M,N] = A @ W + bias, 3-pass compensation.
// BM=BN=128, BK=32, 256 threads (8 warps 2x4), warp tile 64x32.
// 2-stage cp.async double buffer (80KB smem) -> 2 CTAs/SM.
// MODE 0 -> q, 1 -> k, 2 -> v transposed [b,h,d,t], 3 -> fp32 Cout.
// ===========================================================================
#define GBM 128
#define GBN 128
#define GBK 32
#define GP32 20                       // u32 pitch of each tile row (40 bf16)
#define TILE_BYTES (128 * GP32 * 4)   // 10240
#define STAGE_BYTES (4 * TILE_BYTES)  // 40960: Ah|Al|Bh|Bl
#define GEMM_SMEM (2 * STAGE_BYTES)   // 81920  (<=114KB -> 2 CTAs/SM)

__device__ __forceinline__ void load_stage(uint32_t sdst,
        const __nv_bfloat16* __restrict__ Ah, const __nv_bfloat16* __restrict__ Al,
        const __nv_bfloat16* __restrict__ Bh, const __nv_bfloat16* __restrict__ Bl,
        int m0, int n0, int k0)
{
    const int tid = threadIdx.x;
#pragma unroll
    for (int l = 0; l < 2; l++) {
        int e = tid + 256 * l;
        int r = e >> 2, c = e & 3;
        uint32_t doff = (uint32_t)(r * 80 + c * 16);
        size_t soff = (size_t)(m0 + r) * Dd + k0 + c * 8;
        cp16(sdst + doff, Ah + soff);
        cp16(sdst + TILE_BYTES + doff, Al + soff);
    }
#pragma unroll
    for (int l = 0; l < 2; l++) {
        int e = tid + 256 * l;
        int r = e >> 2, c = e & 3;
        uint32_t doff = (uint32_t)(r * 80 + c * 16);
        size_t soff = (size_t)(n0 + r) * Dd + k0 + c * 8;
        cp16(sdst + 2 * TILE_BYTES + doff, Bh + soff);
        cp16(sdst + 3 * TILE_BYTES + doff, Bl + soff);
    }
}

template <int MODE>
__global__ __launch_bounds__(256, 2)
void gemm_bf(const __nv_bfloat16* __restrict__ Ah, const __nv_bfloat16* __restrict__ Al,
             const __nv_bfloat16* __restrict__ Bth, const __nv_bfloat16* __restrict__ Btl,
             const float* __restrict__ bias, float* __restrict__ Cout)
{
    extern __shared__ char smem[];
    const uint32_t sbase = smem_u32(smem);
    const int tid  = threadIdx.x;
    const int wid  = tid >> 5;
    const int lane = tid & 31;
    const int q4   = lane & 3;
    const int g8   = lane >> 2;
    const int wm   = wid >> 2;
    const int wn   = wid & 3;
    const int m0   = blockIdx.y * GBM;
    const int n0   = blockIdx.x * GBN;

    float acc[4][4][4];
#pragma unroll
    for (int i = 0; i < 4; i++)
#pragma unroll
        for (int j = 0; j < 4; j++)
#pragma unroll
            for (int r = 0; r < 4; r++) acc[i][j][r] = 0.f;

    load_stage(sbase, Ah, Al, Bth, Btl, m0, n0, 0);
    CP_COMMIT();

    const int NITER = Dd / GBK;   // 64
    for (int it = 0; it < NITER; it++) {
        CP_WAIT0();
        __syncthreads();
        const uint32_t* S = (const uint32_t*)(smem + (it & 1) * STAGE_BYTES);
        if (it + 1 < NITER) {
            load_stage(sbase + (uint32_t)((it + 1) & 1) * STAGE_BYTES,
                       Ah, Al, Bth, Btl, m0, n0, (it + 1) * GBK);
            CP_COMMIT();
        }
        const uint32_t* As_h = S;
        const uint32_t* As_l = S + TILE_BYTES / 4;
        const uint32_t* Bs_h = S + 2 * (TILE_BYTES / 4);
        const uint32_t* Bs_l = S + 3 * (TILE_BYTES / 4);

#pragma unroll
        for (int ks = 0; ks < 2; ks++) {
            const int base = ks * 8 + q4;
            uint32_t ah[4][4], al[4][4];
#pragma unroll
            for (int i = 0; i < 4; i++) {
                const uint32_t* p = As_h + (wm * 64 + i * 16 + g8) * GP32 + base;
                const uint32_t* q = As_l + (wm * 64 + i * 16 + g8) * GP32 + base;
                ah[i][0] = p[0]; ah[i][1] = p[8 * GP32]; ah[i][2] = p[4]; ah[i][3] = p[8 * GP32 + 4];
                al[i][0] = q[0]; al[i][1] = q[8 * GP32]; al[i][2] = q[4]; al[i][3] = q[8 * GP32 + 4];
            }
#pragma unroll
            for (int j = 0; j < 4; j++) {
                const uint32_t* bp = Bs_h + (wn * 32 + j * 8 + g8) * GP32 + base;
                const uint32_t* bq = Bs_l + (wn * 32 + j * 8 + g8) * GP32 + base;
                uint32_t b0h = bp[0], b1h = bp[4];
                uint32_t b0l = bq[0], b1l = bq[4];
#pragma unroll
                for (int i = 0; i < 4; i++) {
                    mma_bf16(acc[i][j], ah[i], b0h, b1h);
                    mma_bf16(acc[i][j], al[i], b0h, b1h);
                    mma_bf16(acc[i][j], ah[i], b0l, b1l);
                }
            }
        }
    }

    // Epilogue
    const int mbase = m0 + wm * 64;
#pragma unroll
    for (int j = 0; j < 4; j++) {
        const int nc = wn * 32 + j * 8 + 2 * q4;
        const float bx = bias[n0 + nc];
        const float by = bias[n0 + nc + 1];
#pragma unroll
        for (int i = 0; i < 4; i++) {
#pragma unroll
            for (int half = 0; half < 2; half++) {
                const int m = mbase + i * 16 + g8 + half * 8;
                float vx = acc[i][j][half * 2]     + bx;
                float vy = acc[i][j][half * 2 + 1] + by;
                if (MODE == 3) {
                    *(float2*)(Cout + (size_t)m * Dd + n0 + nc) = make_float2(vx, vy);
                } else {
                    const int h = n0 >> 7;
                    const int b = m >> 11;
                    const int t = m & 2047;
                    if (MODE == 2) {
                        // v: transposed [b,h,d,t] hi/lo
                        size_t base = ((size_t)(b * Hh + h) * DHd + nc) * Tt + t;
                        __nv_bfloat16 h0 = __float2bfloat16(vx);
                        __nv_bfloat16 h1 = __float2bfloat16(vy);
                        g_vth[base]       = h0;
                        g_vth[base + Tt]  = h1;
                        g_vtl[base]       = __float2bfloat16(vx - __bfloat162float(h0));
                        g_vtl[base + Tt]  = __float2bfloat16(vy - __bfloat162float(h1));
                    } else {
                        __nv_bfloat16* dh = (MODE == 0) ? g_qh : g_kh;
                        __nv_bfloat16* dl = (MODE == 0) ? g_ql : g_kl;
                        size_t base = ((size_t)((b * Hh + h) * Tt) + t) * DHd + nc;
                        uint32_t hh, ll;
                        bf16_split2(vx, vy, hh, ll);
                        *(uint32_t*)(dh + base) = hh;
                        *(uint32_t*)(dl + base) = ll;
                    }
                }
            }
        }
    }
}

// ===========================================================================
// Flash attention (causal), bf16 hi/lo operands, 3-pass MMA, online softmax.
// BM=128 (8 warps x 16 rows), BN=64, DH=128. 256 threads. (unchanged)
// ===========================================================================
#define FBM 128
#define FBN 64
#define QP32 68     // u32 pitch (136 bf16, 272B)
#define KP32 68
#define VP32 36     // 72 bf16, 144B
#define PP32 36
#define F_QH  0u
#define F_QL  34816u
#define F_K0H 69632u
#define F_K0L 87040u
#define F_K1H 104448u
#define F_K1L 121856u
#define F_VH  139264u
#define F_VL  157696u
#define F_PH  176128u
#define F_PL  194560u
#define FLASH_SMEM 212992

__device__ __forceinline__ void flash_load_q(uint32_t sb,
        const __nv_bfloat16* __restrict__ qh, const __nv_bfloat16* __restrict__ ql) {
    const int tid = threadIdx.x;
#pragma unroll
    for (int l = 0; l < 8; l++) {
        int e = tid + l * 256;
        int r = e >> 4, c = e & 15;
        uint32_t doff = (uint32_t)(r * 272 + c * 16);
        cp16(sb + F_QH + doff, qh + r * 128 + c * 8);
        cp16(sb + F_QL + doff, ql + r * 128 + c * 8);
    }
}
__device__ __forceinline__ void flash_load_k(uint32_t dsth, uint32_t dstl,
        const __nv_bfloat16* __restrict__ kh, const __nv_bfloat16* __restrict__ kl) {
    const int tid = threadIdx.x;
#pragma unroll
    for (int l = 0; l < 4; l++) {
        int e = tid + l * 256;
        int r = e >> 4, c = e & 15;
        uint32_t doff = (uint32_t)(r * 272 + c * 16);
        cp16(dsth + doff, kh + r * 128 + c * 8);
        cp16(dstl + doff, kl + r * 128 + c * 8);
    }
}
__device__ __forceinline__ void flash_load_v(uint32_t sb,
        const __nv_bfloat16* __restrict__ vh, const __nv_bfloat16* __restrict__ vl) {
    const int tid = threadIdx.x;
#pragma unroll
    for (int l = 0; l < 4; l++) {
        int e = tid + l * 256;
        int r = e >> 3, c = e & 7;
        uint32_t doff = (uint32_t)(r * 144 + c * 16);
        cp16(sb + F_VH + doff, vh + (size_t)r * Tt + c * 8);
        cp16(sb + F_VL + doff, vl + (size_t)r * Tt + c * 8);
    }
}

__global__ __launch_bounds__(256, 1)
void flash_tc()
{
    extern __shared__ char smc[];
    const uint32_t sb = smem_u32(smc);
    const int qb = blockIdx.x;
    const int h  = blockIdx.y;
    const int b  = blockIdx.z;
    const int q0 = qb * FBM;
    const int tid  = threadIdx.x;
    const int w    = tid >> 5;
    const int lane = tid & 31;
    const int q4   = lane & 3;
    const int rl   = lane >> 2;

    const uint32_t* Qh32 = (const uint32_t*)(smc + F_QH);
    const uint32_t* Ql32 = (const uint32_t*)(smc + F_QL);
    const uint32_t* Vh32 = (const uint32_t*)(smc + F_VH);
    const uint32_t* Vl32 = (const uint32_t*)(smc + F_VL);
    uint32_t* Ph32 = (uint32_t*)(smc + F_PH);
    uint32_t* Pl32 = (uint32_t*)(smc + F_PL);
    const uint32_t kH[2] = {sb + F_K0H, sb + F_K1H};
    const uint32_t kL[2] = {sb + F_K0L, sb + F_K1L};

    const size_t bh = (size_t)(b * Hh + h) * Tt;
    const __nv_bfloat16* kbh = g_kh + bh * DHd;
    const __nv_bfloat16* kbl = g_kl + bh * DHd;
    const __nv_bfloat16* vbh = g_vth + (size_t)(b * Hh + h) * DHd * Tt;
    const __nv_bfloat16* vbl = g_vtl + (size_t)(b * Hh + h) * DHd * Tt;

    flash_load_q(sb, g_qh + (bh + q0) * DHd, g_ql + (bh + q0) * DHd);
    flash_load_k(kH[0], kL[0], kbh, kbl);
    CP_COMMIT();
    flash_load_v(sb, vbh, vbl);
    CP_COMMIT();

    float m_lo = -1e30f, m_hi = -1e30f, l_lo = 0.f, l_hi = 0.f;
    float o[16][4];
#pragma unroll
    for (int nt = 0; nt < 16; nt++)
#pragma unroll
        for (int r = 0; r < 4; r++) o[nt][r] = 0.f;

    const int rowbase = q0 + w * 16;
    const int nkt = 2 * qb + 2;

    for (int t = 0; t < nkt; t++) {
        const int k0 = t * FBN;
        const bool active = (k0 <= rowbase + 15);
        CP_WAIT1();            // Q + K_t ready
        __syncthreads();

        float sacc[8][4];
        if (active) {
            const uint32_t* Kh32 = (const uint32_t*)(smc + (kH[t & 1] - sb));
            const uint32_t* Kl32 = (const uint32_t*)(smc + (kL[t & 1] - sb));
#pragma unroll
            for (int j = 0; j < 8; j++)
#pragma unroll
                for (int r = 0; r < 4; r++) sacc[j][r] = 0.f;

#pragma unroll
            for (int ks = 0; ks < 8; ks++) {
                const int base = ks * 8 + q4;
                const uint32_t* qh = Qh32 + (w * 16 + rl) * QP32 + base;
                const uint32_t* ql = Ql32 + (w * 16 + rl) * QP32 + base;
                uint32_t ah[4], al[4];
                ah[0] = qh[0]; ah[1] = qh[8 * QP32]; ah[2] = qh[4]; ah[3] = qh[8 * QP32 + 4];
                al[0] = ql[0]; al[1] = ql[8 * QP32]; al[2] = ql[4]; al[3] = ql[8 * QP32 + 4];
#pragma unroll
                for (int j = 0; j < 8; j++) {
                    const uint32_t* kh = Kh32 + (j * 8 + rl) * KP32 + base;
                    const uint32_t* kl = Kl32 + (j * 8 + rl) * KP32 + base;
                    uint32_t b0h = kh[0], b1h = kh[4];
                    uint32_t b0l = kl[0], b1l = kl[4];
                    mma_bf16(sacc[j], ah, b0h, b1h);
                    mma_bf16(sacc[j], al, b0h, b1h);
                    mma_bf16(sacc[j], ah, b0l, b1l);
                }
            }
        }

        if (t + 1 < nkt) {
            flash_load_k(kH[(t + 1) & 1], kL[(t + 1) & 1],
                         kbh + (size_t)(t + 1) * FBN * DHd,
                         kbl + (size_t)(t + 1) * FBN * DHd);
            CP_COMMIT();
            CP_WAIT1();        // V_t ready
        } else {
            CP_WAIT0();
        }
        __syncthreads();

        if (active) {
            const int R_lo = rowbase + rl;
            const int R_hi = R_lo + 8;
            const bool needmask = (k0 + FBN - 1) > rowbase;
            float tl = -1e30f, th = -1e30f;
#pragma unroll
            for (int j = 0; j < 8; j++) {
#pragma unroll
                for (int r = 0; r < 4; r++) sacc[j][r] *= SCALE;
                if (needmask) {
                    const int C = k0 + j * 8 + 2 * q4;
                    if (C > R_lo)     sacc[j][0] = -1e30f;
                    if (C + 1 > R_lo) sacc[j][1] = -1e30f;
                    if (C > R_hi)     sacc[j][2] = -1e30f;
                    if (C + 1 > R_hi) sacc[j][3] = -1e30f;
                }
                tl = fmaxf(tl, fmaxf(sacc[j][0], sacc[j][1]));
                th = fmaxf(th, fmaxf(sacc[j][2], sacc[j][3]));
            }
            tl = fmaxf(tl, __shfl_xor_sync(0xffffffffu, tl, 1));
            tl = fmaxf(tl, __shfl_xor_sync(0xffffffffu, tl, 2));
            th = fmaxf(th, __shfl_xor_sync(0xffffffffu, th, 1));
            th = fmaxf(th, __shfl_xor_sync(0xffffffffu, th, 2));

            const float mn_lo = fmaxf(m_lo, tl);
            const float mn_hi = fmaxf(m_hi, th);
            const float a_lo = __expf(m_lo - mn_lo);
            const float a_hi = __expf(m_hi - mn_hi);
            m_lo = mn_lo; m_hi = mn_hi;

            float sum_lo = 0.f, sum_hi = 0.f;
            uint32_t* prl_h = Ph32 + (w * 16 + rl) * PP32;
            uint32_t* prl_l = Pl32 + (w * 16 + rl) * PP32;
#pragma unroll
            for (int j = 0; j < 8; j++) {
                float p0 = __expf(sacc[j][0] - mn_lo);
                float p1 = __expf(sacc[j][1] - mn_lo);
                float p2 = __expf(sacc[j][2] - mn_hi);
                float p3 = __expf(sacc[j][3] - mn_hi);
                sum_lo += p0 + p1;
                sum_hi += p2 + p3;
                uint32_t hh, ll;
                bf16_split2(p0, p1, hh, ll);
                prl_h[j * 4 + q4] = hh;
                prl_l[j * 4 + q4] = ll;
                bf16_split2(p2, p3, hh, ll);
                prl_h[8 * PP32 + j * 4 + q4] = hh;
                prl_l[8 * PP32 + j * 4 + q4] = ll;
            }
            sum_lo += __shfl_xor_sync(0xffffffffu, sum_lo, 1);
            sum_lo += __shfl_xor_sync(0xffffffffu, sum_lo, 2);
            sum_hi += __shfl_xor_sync(0xffffffffu, sum_hi, 1);
            sum_hi += __shfl_xor_sync(0xffffffffu, sum_hi, 2);
            l_lo = l_lo * a_lo + sum_lo;
            l_hi = l_hi * a_hi + sum_hi;

#pragma unroll
            for (int nt = 0; nt < 16; nt++) {
                o[nt][0] *= a_lo; o[nt][1] *= a_lo;
                o[nt][2] *= a_hi; o[nt][3] *= a_hi;
            }
            __syncwarp();

            // O += P @ V  (3-pass bf16)
#pragma unroll
            for (int ks = 0; ks < 4; ks++) {
                const int base = ks * 8 + q4;
                const uint32_t* ph_ = Ph32 + (w * 16 + rl) * PP32 + base;
                const uint32_t* pl_ = Pl32 + (w * 16 + rl) * PP32 + base;
                uint32_t ph[4], pl[4];
                ph[0] = ph_[0]; ph[1] = ph_[8 * PP32]; ph[2] = ph_[4]; ph[3] = ph_[8 * PP32 + 4];
                pl[0] = pl_[0]; pl[1] = pl_[8 * PP32]; pl[2] = pl_[4]; pl[3] = pl_[8 * PP32 + 4];
#pragma unroll
                for (int nt = 0; nt < 16; nt++) {
                    const uint32_t* vh = Vh32 + (nt * 8 + rl) * VP32 + base;
                    const uint32_t* vl = Vl32 + (nt * 8 + rl) * VP32 + base;
                    uint32_t b0h = vh[0], b1h = vh[4];
                    uint32_t b0l = vl[0], b1l = vl[4];
                    mma_bf16(o[nt], ph, b0h, b1h);
                    mma_bf16(o[nt], pl, b0h, b1h);
                    mma_bf16(o[nt], ph, b0l, b1l);
                }
            }
        }
        __syncthreads();

        if (t + 1 < nkt) {
            flash_load_v(sb, vbh + (size_t)(t + 1) * FBN, vbl + (size_t)(t + 1) * FBN);
            CP_COMMIT();
        }
    }

    // Epilogue: divide by l, split, write att hi/lo [B,T,D]
    const float il_lo = 1.f / l_lo;
    const float il_hi = 1.f / l_hi;
    __nv_bfloat16* oh = g_atth + ((size_t)(b * Tt + rowbase)) * Dd + h * DHd;
    __nv_bfloat16* ol = g_attl + ((size_t)(b * Tt + rowbase)) * Dd + h * DHd;
#pragma unroll
    for (int nt = 0; nt < 16; nt++) {
        uint32_t hh, ll;
        size_t idx0 = (size_t)rl * Dd + nt * 8 + 2 * q4;
        bf16_split2(o[nt][0] * il_lo, o[nt][1] * il_lo, hh, ll);
        *(uint32_t*)(oh + idx0) = hh;
        *(uint32_t*)(ol + idx0) = ll;
        size_t idx1 = (size_t)(rl + 8) * Dd + nt * 8 + 2 * q4;
        bf16_split2(o[nt][2] * il_hi, o[nt][3] * il_hi, hh, ll);
        *(uint32_t*)(oh + idx1) = hh;
        *(uint32_t*)(ol + idx1) = ll;
    }
}

// ===========================================================================
extern "C" void kernel_launch(void* const* d_in, const int* in_sizes, int n_in,
                              void* d_out, int out_size)
{
    const float* x  = (const float*)d_in[0];
    const float* Wq = (const float*)d_in[1];
    const float* bq = (const float*)d_in[2];
    const float* Wk = (const float*)d_in[3];
    const float* bk = (const float*)d_in[4];
    const float* Wv = (const float*)d_in[5];
    const float* bv = (const float*)d_in[6];
    const float* Wo = (const float*)d_in[7];
    const float* bo = (const float*)d_in[8];
    float* out = (float*)d_out;

    __nv_bfloat16 *xh, *xl, *wth, *wtl, *atth, *attl;
    cudaGetSymbolAddress((void**)&xh,   g_xh);
    cudaGetSymbolAddress((void**)&xl,   g_xl);
    cudaGetSymbolAddress((void**)&wth,  g_wth);
    cudaGetSymbolAddress((void**)&wtl,  g_wtl);
    cudaGetSymbolAddress((void**)&atth, g_atth);
    cudaGetSymbolAddress((void**)&attl, g_attl);

    // 1) Convert inputs to bf16 hi/lo (x natural, W transposed)
    conv_x_kernel<<<(Mm * Dd) / 1024, 256>>>(x, xh, xl);
    dim3 tgrid(Dd / 32, Dd / 32), tblk(32, 8);
    conv_w_kernel<<<tgrid, tblk>>>(Wq, wth + 0 * (size_t)Dd * Dd, wtl + 0 * (size_t)Dd * Dd);
    conv_w_kernel<<<tgrid, tblk>>>(Wk, wth + 1 * (size_t)Dd * Dd, wtl + 1 * (size_t)Dd * Dd);
    conv_w_kernel<<<tgrid, tblk>>>(Wv, wth + 2 * (size_t)Dd * Dd, wtl + 2 * (size_t)Dd * Dd);
    conv_w_kernel<<<tgrid, tblk>>>(Wo, wth + 3 * (size_t)Dd * Dd, wtl + 3 * (size_t)Dd * Dd);

    cudaFuncSetAttribute(gemm_bf<0>, cudaFuncAttributeMaxDynamicSharedMemorySize, GEMM_SMEM);
    cudaFuncSetAttribute(gemm_bf<1>, cudaFuncAttributeMaxDynamicSharedMemorySize, GEMM_SMEM);
    cudaFuncSetAttribute(gemm_bf<2>, cudaFuncAttributeMaxDynamicSharedMemorySize, GEMM_SMEM);
    cudaFuncSetAttribute(gemm_bf<3>, cudaFuncAttributeMaxDynamicSharedMemorySize, GEMM_SMEM);

    // 2) QKV projections
    dim3 ggrid(Dd / GBN, Mm / GBM);   // (16, 64)
    gemm_bf<0><<<ggrid, 256, GEMM_SMEM>>>(xh, xl, wth + 0 * (size_t)Dd * Dd, wtl + 0 * (size_t)Dd * Dd, bq, nullptr);
    gemm_bf<1><<<ggrid, 256, GEMM_SMEM>>>(xh, xl, wth + 1 * (size_t)Dd * Dd, wtl + 1 * (size_t)Dd * Dd, bk, nullptr);
    gemm_bf<2><<<ggrid, 256, GEMM_SMEM>>>(xh, xl, wth + 2 * (size_t)Dd * Dd, wtl + 2 * (size_t)Dd * Dd, bv, nullptr);

    // 3) Flash attention
    cudaFuncSetAttribute(flash_tc, cudaFuncAttributeMaxDynamicSharedMemorySize, FLASH_SMEM);
    dim3 fgrid(Tt / FBM, Hh, Bq);     // (16, 16, 4)
    flash_tc<<<fgrid, 256, FLASH_SMEM>>>();

    // 4) Output projection (fp32 out)
    gemm_bf<3><<<ggrid, 256, GEMM_SMEM>>>(atth, attl, wth + 3 * (size_t)Dd * Dd, wtl + 3 * (size_t)Dd * Dd, bo, out);
}

// round 9
// speedup vs baseline: 3.3617x; 1.0452x over previous
#include <cuda_runtime.h>
#include <cuda_bf16.h>
#include <math_constants.h>
#include <cstdint>

#define Bq  4
#define Tt  2048
#define Dd  2048
#define Hh  16
#define DHd 128
#define Mm  (Bq * Tt)        // 8192
#define SCALE 0.08838834764831845f  // DH^-0.5

// ---------------------------------------------------------------------------
// Persistent bf16 hi/lo tensors (allocation-free rule: __device__ globals)
// ---------------------------------------------------------------------------
__device__ __align__(256) __nv_bfloat16 g_xh[Mm * Dd];
__device__ __align__(256) __nv_bfloat16 g_xl[Mm * Dd];
__device__ __align__(256) __nv_bfloat16 g_wth[4][Dd * Dd];   // W^T hi, [N][K]
__device__ __align__(256) __nv_bfloat16 g_wtl[4][Dd * Dd];   // W^T lo
__device__ __align__(256) __nv_bfloat16 g_qh[Bq * Hh * Tt * DHd];
__device__ __align__(256) __nv_bfloat16 g_ql[Bq * Hh * Tt * DHd];
__device__ __align__(256) __nv_bfloat16 g_kh[Bq * Hh * Tt * DHd];
__device__ __align__(256) __nv_bfloat16 g_kl[Bq * Hh * Tt * DHd];
__device__ __align__(256) __nv_bfloat16 g_vth[Bq * Hh * DHd * Tt];  // [b,h,d,t]
__device__ __align__(256) __nv_bfloat16 g_vtl[Bq * Hh * DHd * Tt];
__device__ __align__(256) __nv_bfloat16 g_atth[Bq * Tt * Dd];
__device__ __align__(256) __nv_bfloat16 g_attl[Bq * Tt * Dd];

// ===========================================================================
// Helpers
// ===========================================================================
__device__ __forceinline__ uint32_t smem_u32(const void* p) {
    uint32_t a;
    asm("{ .reg .u64 t; cvta.to.shared.u64 t, %1; cvt.u32.u64 %0, t; }" : "=r"(a) : "l"(p));
    return a;
}
__device__ __forceinline__ void cp16(uint32_t dst, const void* src) {
    asm volatile("cp.async.cg.shared.global [%0], [%1], 16;" :: "r"(dst), "l"(src));
}
#define CP_COMMIT() asm volatile("cp.async.commit_group;" ::: "memory")
#define CP_WAIT0()  asm volatile("cp.async.wait_group 0;" ::: "memory")
#define CP_WAIT1()  asm volatile("cp.async.wait_group 1;" ::: "memory")

__device__ __forceinline__ void mma_bf16(float* c, const uint32_t* a,
                                         uint32_t b0, uint32_t b1) {
    asm volatile(
        "mma.sync.aligned.m16n8k16.row.col.f32.bf16.bf16.f32 "
        "{%0,%1,%2,%3}, {%4,%5,%6,%7}, {%8,%9}, {%0,%1,%2,%3};"
        : "+f"(c[0]), "+f"(c[1]), "+f"(c[2]), "+f"(c[3])
        : "r"(a[0]), "r"(a[1]), "r"(a[2]), "r"(a[3]), "r"(b0), "r"(b1));
}
__device__ __forceinline__ void ldsm_x4(uint32_t* r, uint32_t addr) {
    asm volatile("ldmatrix.sync.aligned.m8n8.x4.shared.b16 {%0,%1,%2,%3}, [%4];"
        : "=r"(r[0]), "=r"(r[1]), "=r"(r[2]), "=r"(r[3]) : "r"(addr));
}
__device__ __forceinline__ void ldsm_x2(uint32_t& r0, uint32_t& r1, uint32_t addr) {
    asm volatile("ldmatrix.sync.aligned.m8n8.x2.shared.b16 {%0,%1}, [%2];"
        : "=r"(r0), "=r"(r1) : "r"(addr));
}
__device__ __forceinline__ uint32_t pack_bf16(float v0, float v1) {
    uint32_t h;
    asm("cvt.rn.bf16x2.f32 %0, %1, %2;" : "=r"(h) : "f"(v1), "f"(v0));
    return h;
}
// Split pair of fp32 into bf16x2 hi + bf16x2 residual (lower 16 bits = v0)
__device__ __forceinline__ void bf16_split2(float v0, float v1,
                                            uint32_t& hi, uint32_t& lo) {
    uint32_t h = pack_bf16(v0, v1);
    float f0 = __uint_as_float(h << 16);
    float f1 = __uint_as_float(h & 0xffff0000u);
    lo = pack_bf16(v0 - f0, v1 - f1);
    hi = h;
}

// ===========================================================================
// Conversion kernels
// ===========================================================================
__global__ __launch_bounds__(256)
void conv_x_kernel(const float* __restrict__ src,
                   __nv_bfloat16* __restrict__ hi, __nv_bfloat16* __restrict__ lo)
{
    const size_t i4 = ((size_t)blockIdx.x * 256 + threadIdx.x) * 4;
    float4 v = *(const float4*)(src + i4);
    uint32_t h0, l0, h1, l1;
    bf16_split2(v.x, v.y, h0, l0);
    bf16_split2(v.z, v.w, h1, l1);
    *(uint2*)(hi + i4) = make_uint2(h0, h1);
    *(uint2*)(lo + i4) = make_uint2(l0, l1);
}

// Transpose all 4 W [K][N] -> W^T [N][K], split to bf16 hi/lo. gridDim.z = 4.
__global__ __launch_bounds__(256)
void conv_w_all(const float* __restrict__ W0, const float* __restrict__ W1,
                const float* __restrict__ W2, const float* __restrict__ W3,
                __nv_bfloat16* __restrict__ Th, __nv_bfloat16* __restrict__ Tl)
{
    const int z = blockIdx.z;
    const float* W = (z == 0) ? W0 : (z == 1) ? W1 : (z == 2) ? W2 : W3;
    __nv_bfloat16* th = Th + (size_t)z * Dd * Dd;
    __nv_bfloat16* tl = Tl + (size_t)z * Dd * Dd;

    __shared__ float tile[32][33];
    int x = blockIdx.x * 32 + threadIdx.x;
    int y = blockIdx.y * 32 + threadIdx.y;
#pragma unroll
    for (int j = 0; j < 32; j += 8)
        tile[threadIdx.y + j][threadIdx.x] = W[(size_t)(y + j) * Dd + x];
    __syncthreads();
    int n = blockIdx.x * 32 + threadIdx.y;
    int k = blockIdx.y * 32 + threadIdx.x;
#pragma unroll
    for (int j = 0; j < 32; j += 8) {
        float v = tile[threadIdx.x][threadIdx.y + j];
        __nv_bfloat16 h = __float2bfloat16(v);
        __nv_bfloat16 l = __float2bfloat16(v - __bfloat162float(h));
        th[(size_t)(n + j) * Dd + k] = h;
        tl[(size_t)(n + j) * Dd + k] = l;
    }
}

// ===========================================================================
// bf16 hi/lo tensor-core GEMM core. BM=BN=128, BK=32, 8 warps (2x4),
// warp tile 64x32. 2-stage cp.async double buffer. ldmatrix fragment loads.
// ===========================================================================
#define GBM 128
#define GBN 128
#define GBK 32
#define GP32 20                       // u32 pitch of each tile row (40 bf16, 80B)
#define TILE_BYTES (128 * GP32 * 4)   // 10240
#define STAGE_BYTES (4 * TILE_BYTES)  // 40960: Ah|Al|Bh|Bl
#define GEMM_SMEM (2 * STAGE_BYTES)   // 81920  -> 2 CTAs/SM

__device__ __forceinline__ void load_stage(uint32_t sdst,
        const __nv_bfloat16* __restrict__ Ah, const __nv_bfloat16* __restrict__ Al,
        const __nv_bfloat16* __restrict__ Bh, const __nv_bfloat16* __restrict__ Bl,
        int m0, int n0, int k0)
{
    const int tid = threadIdx.x;
#pragma unroll
    for (int l = 0; l < 2; l++) {
        int e = tid + 256 * l;
        int r = e >> 2, c = e & 3;
        uint32_t doff = (uint32_t)(r * 80 + c * 16);
        size_t soff = (size_t)(m0 + r) * Dd + k0 + c * 8;
        cp16(sdst + doff, Ah + soff);
        cp16(sdst + TILE_BYTES + doff, Al + soff);
    }
#pragma unroll
    for (int l = 0; l < 2; l++) {
        int e = tid + 256 * l;
        int r = e >> 2, c = e & 3;
        uint32_t doff = (uint32_t)(r * 80 + c * 16);
        size_t soff = (size_t)(n0 + r) * Dd + k0 + c * 8;
        cp16(sdst + 2 * TILE_BYTES + doff, Bh + soff);
        cp16(sdst + 3 * TILE_BYTES + doff, Bl + soff);
    }
}

__device__ __forceinline__ void gemm_mainloop(
        uint32_t sbase,
        const __nv_bfloat16* __restrict__ Ah, const __nv_bfloat16* __restrict__ Al,
        const __nv_bfloat16* __restrict__ Bth, const __nv_bfloat16* __restrict__ Btl,
        int m0, int n0, float acc[4][4][4])
{
    const int lane = threadIdx.x & 31;
    const int wid  = threadIdx.x >> 5;
    const int wm = wid >> 2, wn = wid & 3;
    const int lr = lane & 7, g = lane >> 3;
    // ldmatrix per-thread row addresses (A: x4 over 16x16; B: x2 over 8x16)
    const uint32_t aoff = (uint32_t)((wm * 64 + (g & 1) * 8 + lr) * 80 + (g >> 1) * 16);
    const uint32_t boff = (uint32_t)((wn * 32 + lr) * 80 + (g & 1) * 16);

    load_stage(sbase, Ah, Al, Bth, Btl, m0, n0, 0);
    CP_COMMIT();

    const int NITER = Dd / GBK;   // 64
    for (int it = 0; it < NITER; it++) {
        CP_WAIT0();
        __syncthreads();
        const uint32_t Sb = sbase + (uint32_t)((it & 1) * STAGE_BYTES);
        if (it + 1 < NITER) {
            load_stage(sbase + (uint32_t)(((it + 1) & 1) * STAGE_BYTES),
                       Ah, Al, Bth, Btl, m0, n0, (it + 1) * GBK);
            CP_COMMIT();
        }
#pragma unroll
        for (int ks = 0; ks < 2; ks++) {
            uint32_t ah[4][4], al[4][4];
#pragma unroll
            for (int i = 0; i < 4; i++) {
                ldsm_x4(ah[i], Sb + aoff + i * 1280 + ks * 32);
                ldsm_x4(al[i], Sb + TILE_BYTES + aoff + i * 1280 + ks * 32);
            }
#pragma unroll
            for (int j = 0; j < 4; j++) {
                uint32_t b0h, b1h, b0l, b1l;
                ldsm_x2(b0h, b1h, Sb + 2 * TILE_BYTES + boff + j * 640 + ks * 32);
                ldsm_x2(b0l, b1l, Sb + 3 * TILE_BYTES + boff + j * 640 + ks * 32);
#pragma unroll
                for (int i = 0; i < 4; i++) {
                    mma_bf16(acc[i][j], ah[i], b0h, b1h);
                    mma_bf16(acc[i][j], al[i], b0h, b1h);
                    mma_bf16(acc[i][j], ah[i], b0l, b1l);
                }
            }
        }
    }
}

// Fused QKV projection: gridDim.z selects q/k/v weight + epilogue.
__global__ __launch_bounds__(256, 2)
void gemm_qkv(const __nv_bfloat16* __restrict__ xh, const __nv_bfloat16* __restrict__ xl,
              const __nv_bfloat16* __restrict__ wth, const __nv_bfloat16* __restrict__ wtl,
              const float* __restrict__ bq, const float* __restrict__ bk,
              const float* __restrict__ bv)
{
    extern __shared__ char smem[];
    const uint32_t sbase = smem_u32(smem);
    const int z = blockIdx.z;
    const __nv_bfloat16* Bth = wth + (size_t)z * Dd * Dd;
    const __nv_bfloat16* Btl = wtl + (size_t)z * Dd * Dd;
    const float* bias = (z == 0) ? bq : (z == 1) ? bk : bv;
    const int m0 = blockIdx.y * GBM;
    const int n0 = blockIdx.x * GBN;

    float acc[4][4][4];
#pragma unroll
    for (int i = 0; i < 4; i++)
#pragma unroll
        for (int j = 0; j < 4; j++)
#pragma unroll
            for (int r = 0; r < 4; r++) acc[i][j][r] = 0.f;

    gemm_mainloop(sbase, xh, xl, Bth, Btl, m0, n0, acc);

    const int lane = threadIdx.x & 31;
    const int wid  = threadIdx.x >> 5;
    const int q4 = lane & 3, g8 = lane >> 2;
    const int wm = wid >> 2, wn = wid & 3;
    const int mbase = m0 + wm * 64;
#pragma unroll
    for (int j = 0; j < 4; j++) {
        const int nc = wn * 32 + j * 8 + 2 * q4;
        const float bx = bias[n0 + nc];
        const float by = bias[n0 + nc + 1];
#pragma unroll
        for (int i = 0; i < 4; i++) {
#pragma unroll
            for (int half = 0; half < 2; half++) {
                const int m = mbase + i * 16 + g8 + half * 8;
                float vx = acc[i][j][half * 2]     + bx;
                float vy = acc[i][j][half * 2 + 1] + by;
                const int h = n0 >> 7;
                const int b = m >> 11;
                const int t = m & 2047;
                if (z == 2) {
                    // v: transposed [b,h,d,t] hi/lo
                    size_t base = ((size_t)(b * Hh + h) * DHd + nc) * Tt + t;
                    __nv_bfloat16 h0 = __float2bfloat16(vx);
                    __nv_bfloat16 h1 = __float2bfloat16(vy);
                    g_vth[base]       = h0;
                    g_vth[base + Tt]  = h1;
                    g_vtl[base]       = __float2bfloat16(vx - __bfloat162float(h0));
                    g_vtl[base + Tt]  = __float2bfloat16(vy - __bfloat162float(h1));
                } else {
                    __nv_bfloat16* dh = (z == 0) ? g_qh : g_kh;
                    __nv_bfloat16* dl = (z == 0) ? g_ql : g_kl;
                    size_t base = ((size_t)((b * Hh + h) * Tt) + t) * DHd + nc;
                    uint32_t hh, ll;
                    bf16_split2(vx, vy, hh, ll);
                    *(uint32_t*)(dh + base) = hh;
                    *(uint32_t*)(dl + base) = ll;
                }
            }
        }
    }
}

// Output projection: fp32 row-major result.
__global__ __launch_bounds__(256, 2)
void gemm_out(const __nv_bfloat16* __restrict__ Ah, const __nv_bfloat16* __restrict__ Al,
              const __nv_bfloat16* __restrict__ Bth, const __nv_bfloat16* __restrict__ Btl,
              const float* __restrict__ bias, float* __restrict__ Cout)
{
    extern __shared__ char smem[];
    const uint32_t sbase = smem_u32(smem);
    const int m0 = blockIdx.y * GBM;
    const int n0 = blockIdx.x * GBN;

    float acc[4][4][4];
#pragma unroll
    for (int i = 0; i < 4; i++)
#pragma unroll
        for (int j = 0; j < 4; j++)
#pragma unroll
            for (int r = 0; r < 4; r++) acc[i][j][r] = 0.f;

    gemm_mainloop(sbase, Ah, Al, Bth, Btl, m0, n0, acc);

    const int lane = threadIdx.x & 31;
    const int wid  = threadIdx.x >> 5;
    const int q4 = lane & 3, g8 = lane >> 2;
    const int wm = wid >> 2, wn = wid & 3;
    const int mbase = m0 + wm * 64;
#pragma unroll
    for (int j = 0; j < 4; j++) {
        const int nc = wn * 32 + j * 8 + 2 * q4;
        const float bx = bias[n0 + nc];
        const float by = bias[n0 + nc + 1];
#pragma unroll
        for (int i = 0; i < 4; i++) {
#pragma unroll
            for (int half = 0; half < 2; half++) {
                const int m = mbase + i * 16 + g8 + half * 8;
                *(float2*)(Cout + (size_t)m * Dd + n0 + nc) =
                    make_float2(acc[i][j][half * 2] + bx, acc[i][j][half * 2 + 1] + by);
            }
        }
    }
}

// ===========================================================================
// Flash attention (causal), bf16 hi/lo operands, 3-pass MMA, online softmax.
// BM=128 (8 warps x 16 rows), BN=64, DH=128. 256 threads. (unchanged)
// ===========================================================================
#define FBM 128
#define FBN 64
#define QP32 68     // u32 pitch (136 bf16, 272B)
#define KP32 68
#define VP32 36     // 72 bf16, 144B
#define PP32 36
#define F_QH  0u
#define F_QL  34816u
#define F_K0H 69632u
#define F_K0L 87040u
#define F_K1H 104448u
#define F_K1L 121856u
#define F_VH  139264u
#define F_VL  157696u
#define F_PH  176128u
#define F_PL  194560u
#define FLASH_SMEM 212992

__device__ __forceinline__ void flash_load_q(uint32_t sb,
        const __nv_bfloat16* __restrict__ qh, const __nv_bfloat16* __restrict__ ql) {
    const int tid = threadIdx.x;
#pragma unroll
    for (int l = 0; l < 8; l++) {
        int e = tid + l * 256;
        int r = e >> 4, c = e & 15;
        uint32_t doff = (uint32_t)(r * 272 + c * 16);
        cp16(sb + F_QH + doff, qh + r * 128 + c * 8);
        cp16(sb + F_QL + doff, ql + r * 128 + c * 8);
    }
}
__device__ __forceinline__ void flash_load_k(uint32_t dsth, uint32_t dstl,
        const __nv_bfloat16* __restrict__ kh, const __nv_bfloat16* __restrict__ kl) {
    const int tid = threadIdx.x;
#pragma unroll
    for (int l = 0; l < 4; l++) {
        int e = tid + l * 256;
        int r = e >> 4, c = e & 15;
        uint32_t doff = (uint32_t)(r * 272 + c * 16);
        cp16(dsth + doff, kh + r * 128 + c * 8);
        cp16(dstl + doff, kl + r * 128 + c * 8);
    }
}
__device__ __forceinline__ void flash_load_v(uint32_t sb,
        const __nv_bfloat16* __restrict__ vh, const __nv_bfloat16* __restrict__ vl) {
    const int tid = threadIdx.x;
#pragma unroll
    for (int l = 0; l < 4; l++) {
        int e = tid + l * 256;
        int r = e >> 3, c = e & 7;
        uint32_t doff = (uint32_t)(r * 144 + c * 16);
        cp16(sb + F_VH + doff, vh + (size_t)r * Tt + c * 8);
        cp16(sb + F_VL + doff, vl + (size_t)r * Tt + c * 8);
    }
}

__global__ __launch_bounds__(256, 1)
void flash_tc()
{
    extern __shared__ char smc[];
    const uint32_t sb = smem_u32(smc);
    const int qb = blockIdx.x;
    const int h  = blockIdx.y;
    const int b  = blockIdx.z;
    const int q0 = qb * FBM;
    const int tid  = threadIdx.x;
    const int w    = tid >> 5;
    const int lane = tid & 31;
    const int q4   = lane & 3;
    const int rl   = lane >> 2;

    const uint32_t* Qh32 = (const uint32_t*)(smc + F_QH);
    const uint32_t* Ql32 = (const uint32_t*)(smc + F_QL);
    const uint32_t* Vh32 = (const uint32_t*)(smc + F_VH);
    const uint32_t* Vl32 = (const uint32_t*)(smc + F_VL);
    uint32_t* Ph32 = (uint32_t*)(smc + F_PH);
    uint32_t* Pl32 = (uint32_t*)(smc + F_PL);
    const uint32_t kH[2] = {sb + F_K0H, sb + F_K1H};
    const uint32_t kL[2] = {sb + F_K0L, sb + F_K1L};

    const size_t bh = (size_t)(b * Hh + h) * Tt;
    const __nv_bfloat16* kbh = g_kh + bh * DHd;
    const __nv_bfloat16* kbl = g_kl + bh * DHd;
    const __nv_bfloat16* vbh = g_vth + (size_t)(b * Hh + h) * DHd * Tt;
    const __nv_bfloat16* vbl = g_vtl + (size_t)(b * Hh + h) * DHd * Tt;

    flash_load_q(sb, g_qh + (bh + q0) * DHd, g_ql + (bh + q0) * DHd);
    flash_load_k(kH[0], kL[0], kbh, kbl);
    CP_COMMIT();
    flash_load_v(sb, vbh, vbl);
    CP_COMMIT();

    float m_lo = -1e30f, m_hi = -1e30f, l_lo = 0.f, l_hi = 0.f;
    float o[16][4];
#pragma unroll
    for (int nt = 0; nt < 16; nt++)
#pragma unroll
        for (int r = 0; r < 4; r++) o[nt][r] = 0.f;

    const int rowbase = q0 + w * 16;
    const int nkt = 2 * qb + 2;

    for (int t = 0; t < nkt; t++) {
        const int k0 = t * FBN;
        const bool active = (k0 <= rowbase + 15);
        CP_WAIT1();            // Q + K_t ready
        __syncthreads();

        float sacc[8][4];
        if (active) {
            const uint32_t* Kh32 = (const uint32_t*)(smc + (kH[t & 1] - sb));
            const uint32_t* Kl32 = (const uint32_t*)(smc + (kL[t & 1] - sb));
#pragma unroll
            for (int j = 0; j < 8; j++)
#pragma unroll
                for (int r = 0; r < 4; r++) sacc[j][r] = 0.f;

#pragma unroll
            for (int ks = 0; ks < 8; ks++) {
                const int base = ks * 8 + q4;
                const uint32_t* qh = Qh32 + (w * 16 + rl) * QP32 + base;
                const uint32_t* ql = Ql32 + (w * 16 + rl) * QP32 + base;
                uint32_t ah[4], al[4];
                ah[0] = qh[0]; ah[1] = qh[8 * QP32]; ah[2] = qh[4]; ah[3] = qh[8 * QP32 + 4];
                al[0] = ql[0]; al[1] = ql[8 * QP32]; al[2] = ql[4]; al[3] = ql[8 * QP32 + 4];
#pragma unroll
                for (int j = 0; j < 8; j++) {
                    const uint32_t* kh = Kh32 + (j * 8 + rl) * KP32 + base;
                    const uint32_t* kl = Kl32 + (j * 8 + rl) * KP32 + base;
                    uint32_t b0h = kh[0], b1h = kh[4];
                    uint32_t b0l = kl[0], b1l = kl[4];
                    mma_bf16(sacc[j], ah, b0h, b1h);
                    mma_bf16(sacc[j], al, b0h, b1h);
                    mma_bf16(sacc[j], ah, b0l, b1l);
                }
            }
        }

        if (t + 1 < nkt) {
            flash_load_k(kH[(t + 1) & 1], kL[(t + 1) & 1],
                         kbh + (size_t)(t + 1) * FBN * DHd,
                         kbl + (size_t)(t + 1) * FBN * DHd);
            CP_COMMIT();
            CP_WAIT1();        // V_t ready
        } else {
            CP_WAIT0();
        }
        __syncthreads();

        if (active) {
            const int R_lo = rowbase + rl;
            const int R_hi = R_lo + 8;
            const bool needmask = (k0 + FBN - 1) > rowbase;
            float tl = -1e30f, th = -1e30f;
#pragma unroll
            for (int j = 0; j < 8; j++) {
#pragma unroll
                for (int r = 0; r < 4; r++) sacc[j][r] *= SCALE;
                if (needmask) {
                    const int C = k0 + j * 8 + 2 * q4;
                    if (C > R_lo)     sacc[j][0] = -1e30f;
                    if (C + 1 > R_lo) sacc[j][1] = -1e30f;
                    if (C > R_hi)     sacc[j][2] = -1e30f;
                    if (C + 1 > R_hi) sacc[j][3] = -1e30f;
                }
                tl = fmaxf(tl, fmaxf(sacc[j][0], sacc[j][1]));
                th = fmaxf(th, fmaxf(sacc[j][2], sacc[j][3]));
            }
            tl = fmaxf(tl, __shfl_xor_sync(0xffffffffu, tl, 1));
            tl = fmaxf(tl, __shfl_xor_sync(0xffffffffu, tl, 2));
            th = fmaxf(th, __shfl_xor_sync(0xffffffffu, th, 1));
            th = fmaxf(th, __shfl_xor_sync(0xffffffffu, th, 2));

            const float mn_lo = fmaxf(m_lo, tl);
            const float mn_hi = fmaxf(m_hi, th);
            const float a_lo = __expf(m_lo - mn_lo);
            const float a_hi = __expf(m_hi - mn_hi);
            m_lo = mn_lo; m_hi = mn_hi;

            float sum_lo = 0.f, sum_hi = 0.f;
            uint32_t* prl_h = Ph32 + (w * 16 + rl) * PP32;
            uint32_t* prl_l = Pl32 + (w * 16 + rl) * PP32;
#pragma unroll
            for (int j = 0; j < 8; j++) {
                float p0 = __expf(sacc[j][0] - mn_lo);
                float p1 = __expf(sacc[j][1] - mn_lo);
                float p2 = __expf(sacc[j][2] - mn_hi);
                float p3 = __expf(sacc[j][3] - mn_hi);
                sum_lo += p0 + p1;
                sum_hi += p2 + p3;
                uint32_t hh, ll;
                bf16_split2(p0, p1, hh, ll);
                prl_h[j * 4 + q4] = hh;
                prl_l[j * 4 + q4] = ll;
                bf16_split2(p2, p3, hh, ll);
                prl_h[8 * PP32 + j * 4 + q4] = hh;
                prl_l[8 * PP32 + j * 4 + q4] = ll;
            }
            sum_lo += __shfl_xor_sync(0xffffffffu, sum_lo, 1);
            sum_lo += __shfl_xor_sync(0xffffffffu, sum_lo, 2);
            sum_hi += __shfl_xor_sync(0xffffffffu, sum_hi, 1);
            sum_hi += __shfl_xor_sync(0xffffffffu, sum_hi, 2);
            l_lo = l_lo * a_lo + sum_lo;
            l_hi = l_hi * a_hi + sum_hi;

#pragma unroll
            for (int nt = 0; nt < 16; nt++) {
                o[nt][0] *= a_lo; o[nt][1] *= a_lo;
                o[nt][2] *= a_hi; o[nt][3] *= a_hi;
            }
            __syncwarp();

            // O += P @ V  (3-pass bf16)
#pragma unroll
            for (int ks = 0; ks < 4; ks++) {
                const int base = ks * 8 + q4;
                const uint32_t* ph_ = Ph32 + (w * 16 + rl) * PP32 + base;
                const uint32_t* pl_ = Pl32 + (w * 16 + rl) * PP32 + base;
                uint32_t ph[4], pl[4];
                ph[0] = ph_[0]; ph[1] = ph_[8 * PP32]; ph[2] = ph_[4]; ph[3] = ph_[8 * PP32 + 4];
                pl[0] = pl_[0]; pl[1] = pl_[8 * PP32]; pl[2] = pl_[4]; pl[3] = pl_[8 * PP32 + 4];
#pragma unroll
                for (int nt = 0; nt < 16; nt++) {
                    const uint32_t* vh = Vh32 + (nt * 8 + rl) * VP32 + base;
                    const uint32_t* vl = Vl32 + (nt * 8 + rl) * VP32 + base;
                    uint32_t b0h = vh[0], b1h = vh[4];
                    uint32_t b0l = vl[0], b1l = vl[4];
                    mma_bf16(o[nt], ph, b0h, b1h);
                    mma_bf16(o[nt], pl, b0h, b1h);
                    mma_bf16(o[nt], ph, b0l, b1l);
                }
            }
        }
        __syncthreads();

        if (t + 1 < nkt) {
            flash_load_v(sb, vbh + (size_t)(t + 1) * FBN, vbl + (size_t)(t + 1) * FBN);
            CP_COMMIT();
        }
    }

    // Epilogue: divide by l, split, write att hi/lo [B,T,D]
    const float il_lo = 1.f / l_lo;
    const float il_hi = 1.f / l_hi;
    __nv_bfloat16* oh = g_atth + ((size_t)(b * Tt + rowbase)) * Dd + h * DHd;
    __nv_bfloat16* ol = g_attl + ((size_t)(b * Tt + rowbase)) * Dd + h * DHd;
#pragma unroll
    for (int nt = 0; nt < 16; nt++) {
        uint32_t hh, ll;
        size_t idx0 = (size_t)rl * Dd + nt * 8 + 2 * q4;
        bf16_split2(o[nt][0] * il_lo, o[nt][1] * il_lo, hh, ll);
        *(uint32_t*)(oh + idx0) = hh;
        *(uint32_t*)(ol + idx0) = ll;
        size_t idx1 = (size_t)(rl + 8) * Dd + nt * 8 + 2 * q4;
        bf16_split2(o[nt][2] * il_hi, o[nt][3] * il_hi, hh, ll);
        *(uint32_t*)(oh + idx1) = hh;
        *(uint32_t*)(ol + idx1) = ll;
    }
}

// ===========================================================================
extern "C" void kernel_launch(void* const* d_in, const int* in_sizes, int n_in,
                              void* d_out, int out_size)
{
    const float* x  = (const float*)d_in[0];
    const float* Wq = (const float*)d_in[1];
    const float* bq = (const float*)d_in[2];
    const float* Wk = (const float*)d_in[3];
    const float* bk = (const float*)d_in[4];
    const float* Wv = (const float*)d_in[5];
    const float* bv = (const float*)d_in[6];
    const float* Wo = (const float*)d_in[7];
    const float* bo = (const float*)d_in[8];
    float* out = (float*)d_out;

    __nv_bfloat16 *xh, *xl, *wth, *wtl, *atth, *attl;
    cudaGetSymbolAddress((void**)&xh,   g_xh);
    cudaGetSymbolAddress((void**)&xl,   g_xl);
    cudaGetSymbolAddress((void**)&wth,  g_wth);
    cudaGetSymbolAddress((void**)&wtl,  g_wtl);
    cudaGetSymbolAddress((void**)&atth, g_atth);
    cudaGetSymbolAddress((void**)&attl, g_attl);

    // 1) Convert inputs to bf16 hi/lo (x natural, all 4 W transposed, fused)
    conv_x_kernel<<<(Mm * Dd) / 1024, 256>>>(x, xh, xl);
    dim3 wgrid(Dd / 32, Dd / 32, 4);
    conv_w_all<<<wgrid, dim3(32, 8)>>>(Wq, Wk, Wv, Wo, wth, wtl);

    cudaFuncSetAttribute(gemm_qkv, cudaFuncAttributeMaxDynamicSharedMemorySize, GEMM_SMEM);
    cudaFuncSetAttribute(gemm_out, cudaFuncAttributeMaxDynamicSharedMemorySize, GEMM_SMEM);

    // 2) Fused QKV projections (one launch, one tail)
    dim3 qkvgrid(Dd / GBN, Mm / GBM, 3);   // (16, 64, 3)
    gemm_qkv<<<qkvgrid, 256, GEMM_SMEM>>>(xh, xl, wth, wtl, bq, bk, bv);

    // 3) Flash attention
    cudaFuncSetAttribute(flash_tc, cudaFuncAttributeMaxDynamicSharedMemorySize, FLASH_SMEM);
    dim3 fgrid(Tt / FBM, Hh, Bq);          // (16, 16, 4)
    flash_tc<<<fgrid, 256, FLASH_SMEM>>>();

    // 4) Output projection (fp32 out)
    dim3 ogrid(Dd / GBN, Mm / GBM);        // (16, 64)
    gemm_out<<<ogrid, 256, GEMM_SMEM>>>(atth, attl, wth + 3 * (size_t)Dd * Dd,
                                        wtl + 3 * (size_t)Dd * Dd, bo, out);
}

// round 10
// speedup vs baseline: 3.7856x; 1.1261x over previous
#include <cuda_runtime.h>
#include <cuda_bf16.h>
#include <math_constants.h>
#include <cstdint>

#define Bq  4
#define Tt  2048
#define Dd  2048
#define Hh  16
#define DHd 128
#define Mm  (Bq * Tt)        // 8192
#define SCALE 0.08838834764831845f  // DH^-0.5

// ---------------------------------------------------------------------------
// Persistent bf16 hi/lo tensors (allocation-free rule: __device__ globals)
// ---------------------------------------------------------------------------
__device__ __align__(256) __nv_bfloat16 g_xh[Mm * Dd];
__device__ __align__(256) __nv_bfloat16 g_xl[Mm * Dd];
__device__ __align__(256) __nv_bfloat16 g_wth[4][Dd * Dd];   // W^T hi, [N][K]
__device__ __align__(256) __nv_bfloat16 g_wtl[4][Dd * Dd];   // W^T lo
__device__ __align__(256) __nv_bfloat16 g_qh[Bq * Hh * Tt * DHd];
__device__ __align__(256) __nv_bfloat16 g_ql[Bq * Hh * Tt * DHd];
__device__ __align__(256) __nv_bfloat16 g_kh[Bq * Hh * Tt * DHd];
__device__ __align__(256) __nv_bfloat16 g_kl[Bq * Hh * Tt * DHd];
__device__ __align__(256) __nv_bfloat16 g_vth[Bq * Hh * DHd * Tt];  // [b,h,d,t]
__device__ __align__(256) __nv_bfloat16 g_vtl[Bq * Hh * DHd * Tt];
__device__ __align__(256) __nv_bfloat16 g_atth[Bq * Tt * Dd];
__device__ __align__(256) __nv_bfloat16 g_attl[Bq * Tt * Dd];

// ===========================================================================
// Helpers
// ===========================================================================
__device__ __forceinline__ uint32_t smem_u32(const void* p) {
    uint32_t a;
    asm("{ .reg .u64 t; cvta.to.shared.u64 t, %1; cvt.u32.u64 %0, t; }" : "=r"(a) : "l"(p));
    return a;
}
__device__ __forceinline__ void cp16(uint32_t dst, const void* src) {
    asm volatile("cp.async.cg.shared.global [%0], [%1], 16;" :: "r"(dst), "l"(src));
}
#define CP_COMMIT() asm volatile("cp.async.commit_group;" ::: "memory")
#define CP_WAIT0()  asm volatile("cp.async.wait_group 0;" ::: "memory")
#define CP_WAIT1()  asm volatile("cp.async.wait_group 1;" ::: "memory")

__device__ __forceinline__ void mma_bf16(float* c, const uint32_t* a,
                                         uint32_t b0, uint32_t b1) {
    asm volatile(
        "mma.sync.aligned.m16n8k16.row.col.f32.bf16.bf16.f32 "
        "{%0,%1,%2,%3}, {%4,%5,%6,%7}, {%8,%9}, {%0,%1,%2,%3};"
        : "+f"(c[0]), "+f"(c[1]), "+f"(c[2]), "+f"(c[3])
        : "r"(a[0]), "r"(a[1]), "r"(a[2]), "r"(a[3]), "r"(b0), "r"(b1));
}
__device__ __forceinline__ void ldsm_x4(uint32_t* r, uint32_t addr) {
    asm volatile("ldmatrix.sync.aligned.m8n8.x4.shared.b16 {%0,%1,%2,%3}, [%4];"
        : "=r"(r[0]), "=r"(r[1]), "=r"(r[2]), "=r"(r[3]) : "r"(addr));
}
__device__ __forceinline__ void ldsm_x2(uint32_t& r0, uint32_t& r1, uint32_t addr) {
    asm volatile("ldmatrix.sync.aligned.m8n8.x2.shared.b16 {%0,%1}, [%2];"
        : "=r"(r0), "=r"(r1) : "r"(addr));
}
__device__ __forceinline__ uint32_t pack_bf16(float v0, float v1) {
    uint32_t h;
    asm("cvt.rn.bf16x2.f32 %0, %1, %2;" : "=r"(h) : "f"(v1), "f"(v0));
    return h;
}
// Split pair of fp32 into bf16x2 hi + bf16x2 residual (lower 16 bits = v0)
__device__ __forceinline__ void bf16_split2(float v0, float v1,
                                            uint32_t& hi, uint32_t& lo) {
    uint32_t h = pack_bf16(v0, v1);
    float f0 = __uint_as_float(h << 16);
    float f1 = __uint_as_float(h & 0xffff0000u);
    lo = pack_bf16(v0 - f0, v1 - f1);
    hi = h;
}

// ===========================================================================
// Conversion kernels
// ===========================================================================
__global__ __launch_bounds__(256)
void conv_x_kernel(const float* __restrict__ src,
                   __nv_bfloat16* __restrict__ hi, __nv_bfloat16* __restrict__ lo)
{
    const size_t i4 = ((size_t)blockIdx.x * 256 + threadIdx.x) * 4;
    float4 v = *(const float4*)(src + i4);
    uint32_t h0, l0, h1, l1;
    bf16_split2(v.x, v.y, h0, l0);
    bf16_split2(v.z, v.w, h1, l1);
    *(uint2*)(hi + i4) = make_uint2(h0, h1);
    *(uint2*)(lo + i4) = make_uint2(l0, l1);
}

// Transpose all 4 W [K][N] -> W^T [N][K], split to bf16 hi/lo. gridDim.z = 4.
__global__ __launch_bounds__(256)
void conv_w_all(const float* __restrict__ W0, const float* __restrict__ W1,
                const float* __restrict__ W2, const float* __restrict__ W3,
                __nv_bfloat16* __restrict__ Th, __nv_bfloat16* __restrict__ Tl)
{
    const int z = blockIdx.z;
    const float* W = (z == 0) ? W0 : (z == 1) ? W1 : (z == 2) ? W2 : W3;
    __nv_bfloat16* th = Th + (size_t)z * Dd * Dd;
    __nv_bfloat16* tl = Tl + (size_t)z * Dd * Dd;

    __shared__ float tile[32][33];
    int x = blockIdx.x * 32 + threadIdx.x;
    int y = blockIdx.y * 32 + threadIdx.y;
#pragma unroll
    for (int j = 0; j < 32; j += 8)
        tile[threadIdx.y + j][threadIdx.x] = W[(size_t)(y + j) * Dd + x];
    __syncthreads();
    int n = blockIdx.x * 32 + threadIdx.y;
    int k = blockIdx.y * 32 + threadIdx.x;
#pragma unroll
    for (int j = 0; j < 32; j += 8) {
        float v = tile[threadIdx.x][threadIdx.y + j];
        __nv_bfloat16 h = __float2bfloat16(v);
        __nv_bfloat16 l = __float2bfloat16(v - __bfloat162float(h));
        th[(size_t)(n + j) * Dd + k] = h;
        tl[(size_t)(n + j) * Dd + k] = l;
    }
}

// ===========================================================================
// bf16 hi/lo tensor-core GEMM core. BM=BN=128, BK=32, 8 warps (2x4),
// warp tile 64x32. 3-stage cp.async ring (96KB) at 2 CTAs/SM.
// Dense 64B rows with 16B-chunk XOR swizzle (chunk ^= (row>>1)&3) for
// conflict-free ldmatrix AND 16B-aligned cp.async.
// ===========================================================================
#define GBM 128
#define GBN 128
#define GBK 32
#define TILEB 8192                    // 128 rows * 64B
#define STAGEB (4 * TILEB)            // 32768: Ah|Al|Bh|Bl
#define GEMM_SMEM (3 * STAGEB)        // 98304 -> 2 CTAs/SM

__device__ __forceinline__ void load_stage(uint32_t sdst,
        const __nv_bfloat16* __restrict__ Ah, const __nv_bfloat16* __restrict__ Al,
        const __nv_bfloat16* __restrict__ Bh, const __nv_bfloat16* __restrict__ Bl,
        int m0, int n0, int k0)
{
    const int tid = threadIdx.x;
#pragma unroll
    for (int l = 0; l < 2; l++) {
        int e = tid + 256 * l;
        int r = e >> 2, c = e & 3;
        int cp_ = c ^ ((r >> 1) & 3);
        uint32_t doff = (uint32_t)(r * 64 + cp_ * 16);
        size_t soff = (size_t)(m0 + r) * Dd + k0 + c * 8;
        cp16(sdst + doff, Ah + soff);
        cp16(sdst + TILEB + doff, Al + soff);
    }
#pragma unroll
    for (int l = 0; l < 2; l++) {
        int e = tid + 256 * l;
        int r = e >> 2, c = e & 3;
        int cp_ = c ^ ((r >> 1) & 3);
        uint32_t doff = (uint32_t)(r * 64 + cp_ * 16);
        size_t soff = (size_t)(n0 + r) * Dd + k0 + c * 8;
        cp16(sdst + 2 * TILEB + doff, Bh + soff);
        cp16(sdst + 3 * TILEB + doff, Bl + soff);
    }
}

__device__ __forceinline__ void gemm_mainloop(
        uint32_t sbase,
        const __nv_bfloat16* __restrict__ Ah, const __nv_bfloat16* __restrict__ Al,
        const __nv_bfloat16* __restrict__ Bth, const __nv_bfloat16* __restrict__ Btl,
        int m0, int n0, float acc[4][4][4])
{
    const int lane = threadIdx.x & 31;
    const int wid  = threadIdx.x >> 5;
    const int wm = wid >> 2, wn = wid & 3;
    const int lr = lane & 7, g = lane >> 3;
    const int swz = (lr >> 1) & 3;
    const uint32_t arow = (uint32_t)((wm * 64 + (g & 1) * 8 + lr) * 64);
    const uint32_t brow = (uint32_t)((wn * 32 + lr) * 64);
    const int akh = g >> 1;      // A k-half lane group
    const int bkh = g & 1;       // B k-half lane group

    load_stage(sbase, Ah, Al, Bth, Btl, m0, n0, 0);
    CP_COMMIT();
    load_stage(sbase + STAGEB, Ah, Al, Bth, Btl, m0, n0, GBK);
    CP_COMMIT();

    const int NITER = Dd / GBK;   // 64
    int cur = 0;
    for (int it = 0; it < NITER; it++) {
        CP_WAIT1();
        __syncthreads();
        const uint32_t Sb = sbase + (uint32_t)cur * STAGEB;
        if (it + 2 < NITER) {
            int pf = cur + 2; if (pf >= 3) pf -= 3;
            load_stage(sbase + (uint32_t)pf * STAGEB, Ah, Al, Bth, Btl,
                       m0, n0, (it + 2) * GBK);
            CP_COMMIT();
        }
#pragma unroll
        for (int ks = 0; ks < 2; ks++) {
            const uint32_t ca = (uint32_t)(((ks * 2 + akh) ^ swz) * 16);
            const uint32_t cb = (uint32_t)(((ks * 2 + bkh) ^ swz) * 16);
            uint32_t ah[4][4], al[4][4];
#pragma unroll
            for (int i = 0; i < 4; i++) {
                ldsm_x4(ah[i], Sb + arow + (uint32_t)(i * 1024) + ca);
                ldsm_x4(al[i], Sb + TILEB + arow + (uint32_t)(i * 1024) + ca);
            }
#pragma unroll
            for (int j = 0; j < 4; j++) {
                uint32_t b0h, b1h, b0l, b1l;
                ldsm_x2(b0h, b1h, Sb + 2 * TILEB + brow + (uint32_t)(j * 512) + cb);
                ldsm_x2(b0l, b1l, Sb + 3 * TILEB + brow + (uint32_t)(j * 512) + cb);
#pragma unroll
                for (int i = 0; i < 4; i++) {
                    mma_bf16(acc[i][j], ah[i], b0h, b1h);
                    mma_bf16(acc[i][j], al[i], b0h, b1h);
                    mma_bf16(acc[i][j], ah[i], b0l, b1l);
                }
            }
        }
        cur++; if (cur >= 3) cur = 0;
    }
}

// Fused QKV projection: gridDim.z selects q/k/v weight + epilogue.
__global__ __launch_bounds__(256, 2)
void gemm_qkv(const __nv_bfloat16* __restrict__ xh, const __nv_bfloat16* __restrict__ xl,
              const __nv_bfloat16* __restrict__ wth, const __nv_bfloat16* __restrict__ wtl,
              const float* __restrict__ bq, const float* __restrict__ bk,
              const float* __restrict__ bv)
{
    extern __shared__ char smem[];
    const uint32_t sbase = smem_u32(smem);
    const int z = blockIdx.z;
    const __nv_bfloat16* Bth = wth + (size_t)z * Dd * Dd;
    const __nv_bfloat16* Btl = wtl + (size_t)z * Dd * Dd;
    const float* bias = (z == 0) ? bq : (z == 1) ? bk : bv;
    const int m0 = blockIdx.y * GBM;
    const int n0 = blockIdx.x * GBN;

    float acc[4][4][4];
#pragma unroll
    for (int i = 0; i < 4; i++)
#pragma unroll
        for (int j = 0; j < 4; j++)
#pragma unroll
            for (int r = 0; r < 4; r++) acc[i][j][r] = 0.f;

    gemm_mainloop(sbase, xh, xl, Bth, Btl, m0, n0, acc);

    const int lane = threadIdx.x & 31;
    const int wid  = threadIdx.x >> 5;
    const int q4 = lane & 3, g8 = lane >> 2;
    const int wm = wid >> 2, wn = wid & 3;
    const int mbase = m0 + wm * 64;
#pragma unroll
    for (int j = 0; j < 4; j++) {
        const int nc = wn * 32 + j * 8 + 2 * q4;
        const float bx = bias[n0 + nc];
        const float by = bias[n0 + nc + 1];
#pragma unroll
        for (int i = 0; i < 4; i++) {
#pragma unroll
            for (int half = 0; half < 2; half++) {
                const int m = mbase + i * 16 + g8 + half * 8;
                float vx = acc[i][j][half * 2]     + bx;
                float vy = acc[i][j][half * 2 + 1] + by;
                const int h = n0 >> 7;
                const int b = m >> 11;
                const int t = m & 2047;
                if (z == 2) {
                    // v: transposed [b,h,d,t] hi/lo
                    size_t base = ((size_t)(b * Hh + h) * DHd + nc) * Tt + t;
                    __nv_bfloat16 h0 = __float2bfloat16(vx);
                    __nv_bfloat16 h1 = __float2bfloat16(vy);
                    g_vth[base]       = h0;
                    g_vth[base + Tt]  = h1;
                    g_vtl[base]       = __float2bfloat16(vx - __bfloat162float(h0));
                    g_vtl[base + Tt]  = __float2bfloat16(vy - __bfloat162float(h1));
                } else {
                    __nv_bfloat16* dh = (z == 0) ? g_qh : g_kh;
                    __nv_bfloat16* dl = (z == 0) ? g_ql : g_kl;
                    size_t base = ((size_t)((b * Hh + h) * Tt) + t) * DHd + nc;
                    uint32_t hh, ll;
                    bf16_split2(vx, vy, hh, ll);
                    *(uint32_t*)(dh + base) = hh;
                    *(uint32_t*)(dl + base) = ll;
                }
            }
        }
    }
}

// Output projection: fp32 row-major result.
__global__ __launch_bounds__(256, 2)
void gemm_out(const __nv_bfloat16* __restrict__ Ah, const __nv_bfloat16* __restrict__ Al,
              const __nv_bfloat16* __restrict__ Bth, const __nv_bfloat16* __restrict__ Btl,
              const float* __restrict__ bias, float* __restrict__ Cout)
{
    extern __shared__ char smem[];
    const uint32_t sbase = smem_u32(smem);
    const int m0 = blockIdx.y * GBM;
    const int n0 = blockIdx.x * GBN;

    float acc[4][4][4];
#pragma unroll
    for (int i = 0; i < 4; i++)
#pragma unroll
        for (int j = 0; j < 4; j++)
#pragma unroll
            for (int r = 0; r < 4; r++) acc[i][j][r] = 0.f;

    gemm_mainloop(sbase, Ah, Al, Bth, Btl, m0, n0, acc);

    const int lane = threadIdx.x & 31;
    const int wid  = threadIdx.x >> 5;
    const int q4 = lane & 3, g8 = lane >> 2;
    const int wm = wid >> 2, wn = wid & 3;
    const int mbase = m0 + wm * 64;
#pragma unroll
    for (int j = 0; j < 4; j++) {
        const int nc = wn * 32 + j * 8 + 2 * q4;
        const float bx = bias[n0 + nc];
        const float by = bias[n0 + nc + 1];
#pragma unroll
        for (int i = 0; i < 4; i++) {
#pragma unroll
            for (int half = 0; half < 2; half++) {
                const int m = mbase + i * 16 + g8 + half * 8;
                *(float2*)(Cout + (size_t)m * Dd + n0 + nc) =
                    make_float2(acc[i][j][half * 2] + bx, acc[i][j][half * 2 + 1] + by);
            }
        }
    }
}

// ===========================================================================
// Flash attention (causal), bf16 hi/lo, 3-pass MMA, online softmax.
// BM=128 (8 warps x 16 rows), BN=64, DH=128, 256 threads.
// V double-buffered, K single-buffered; loads prefetched with >=1/2 iter slack.
// ===========================================================================
#define FBM 128
#define FBN 64
#define QP32 68     // u32 pitch (136 bf16, 272B)
#define KP32 68
#define VP32 36     // 72 bf16, 144B
#define PP32 36
#define F_QH   0u
#define F_QL   34816u
#define F_KH   69632u
#define F_KL   87040u
#define F_V0H  104448u
#define F_VLO  18432u      // lo offset within a V buffer
#define F_VSTR 36864u      // stride between V buffers
#define F_PH   178176u
#define F_PL   196608u
#define FLASH_SMEM 215040

__device__ __forceinline__ void flash_load_q(uint32_t sb,
        const __nv_bfloat16* __restrict__ qh, const __nv_bfloat16* __restrict__ ql) {
    const int tid = threadIdx.x;
#pragma unroll
    for (int l = 0; l < 8; l++) {
        int e = tid + l * 256;
        int r = e >> 4, c = e & 15;
        uint32_t doff = (uint32_t)(r * 272 + c * 16);
        cp16(sb + F_QH + doff, qh + r * 128 + c * 8);
        cp16(sb + F_QL + doff, ql + r * 128 + c * 8);
    }
}
__device__ __forceinline__ void flash_load_k(uint32_t sb,
        const __nv_bfloat16* __restrict__ kh, const __nv_bfloat16* __restrict__ kl) {
    const int tid = threadIdx.x;
#pragma unroll
    for (int l = 0; l < 4; l++) {
        int e = tid + l * 256;
        int r = e >> 4, c = e & 15;
        uint32_t doff = (uint32_t)(r * 272 + c * 16);
        cp16(sb + F_KH + doff, kh + r * 128 + c * 8);
        cp16(sb + F_KL + doff, kl + r * 128 + c * 8);
    }
}
__device__ __forceinline__ void flash_load_v(uint32_t dsth,
        const __nv_bfloat16* __restrict__ vh, const __nv_bfloat16* __restrict__ vl) {
    const int tid = threadIdx.x;
#pragma unroll
    for (int l = 0; l < 4; l++) {
        int e = tid + l * 256;
        int r = e >> 3, c = e & 7;
        uint32_t doff = (uint32_t)(r * 144 + c * 16);
        cp16(dsth + doff, vh + (size_t)r * Tt + c * 8);
        cp16(dsth + F_VLO + doff, vl + (size_t)r * Tt + c * 8);
    }
}

__global__ __launch_bounds__(256, 1)
void flash_tc()
{
    extern __shared__ char smc[];
    const uint32_t sb = smem_u32(smc);
    const int qb = (gridDim.x - 1) - blockIdx.x;    // longest-job-first
    const int h  = blockIdx.y;
    const int b  = blockIdx.z;
    const int q0 = qb * FBM;
    const int tid  = threadIdx.x;
    const int w    = tid >> 5;
    const int lane = tid & 31;
    const int q4   = lane & 3;
    const int rl   = lane >> 2;

    const uint32_t* Qh32 = (const uint32_t*)(smc + F_QH);
    const uint32_t* Ql32 = (const uint32_t*)(smc + F_QL);
    const uint32_t* Kh32 = (const uint32_t*)(smc + F_KH);
    const uint32_t* Kl32 = (const uint32_t*)(smc + F_KL);
    uint32_t* Ph32 = (uint32_t*)(smc + F_PH);
    uint32_t* Pl32 = (uint32_t*)(smc + F_PL);

    const size_t bh = (size_t)(b * Hh + h) * Tt;
    const __nv_bfloat16* kbh = g_kh + bh * DHd;
    const __nv_bfloat16* kbl = g_kl + bh * DHd;
    const __nv_bfloat16* vbh = g_vth + (size_t)(b * Hh + h) * DHd * Tt;
    const __nv_bfloat16* vbl = g_vtl + (size_t)(b * Hh + h) * DHd * Tt;

    flash_load_q(sb, g_qh + (bh + q0) * DHd, g_ql + (bh + q0) * DHd);
    flash_load_k(sb, kbh, kbl);
    flash_load_v(sb + F_V0H, vbh, vbl);
    CP_COMMIT();

    float m_lo = -1e30f, m_hi = -1e30f, l_lo = 0.f, l_hi = 0.f;
    float o[16][4];
#pragma unroll
    for (int nt = 0; nt < 16; nt++)
#pragma unroll
        for (int r = 0; r < 4; r++) o[nt][r] = 0.f;

    const int rowbase = q0 + w * 16;
    const int nkt = 2 * qb + 2;

    for (int t = 0; t < nkt; t++) {
        const int k0 = t * FBN;
        const bool active = (k0 <= rowbase + 15);
        CP_WAIT0();            // K_t and V_t ready
        __syncthreads();

        // Prefetch V_{t+1} into the other V buffer (read 2 iters ago; safe)
        if (t + 1 < nkt) {
            flash_load_v(sb + F_V0H + (uint32_t)((t + 1) & 1) * F_VSTR,
                         vbh + (size_t)(t + 1) * FBN, vbl + (size_t)(t + 1) * FBN);
            CP_COMMIT();
        }

        float sacc[8][4];
        if (active) {
#pragma unroll
            for (int j = 0; j < 8; j++)
#pragma unroll
                for (int r = 0; r < 4; r++) sacc[j][r] = 0.f;

#pragma unroll
            for (int ks = 0; ks < 8; ks++) {
                const int base = ks * 8 + q4;
                const uint32_t* qh = Qh32 + (w * 16 + rl) * QP32 + base;
                const uint32_t* ql = Ql32 + (w * 16 + rl) * QP32 + base;
                uint32_t ah[4], al[4];
                ah[0] = qh[0]; ah[1] = qh[8 * QP32]; ah[2] = qh[4]; ah[3] = qh[8 * QP32 + 4];
                al[0] = ql[0]; al[1] = ql[8 * QP32]; al[2] = ql[4]; al[3] = ql[8 * QP32 + 4];
#pragma unroll
                for (int j = 0; j < 8; j++) {
                    const uint32_t* kh = Kh32 + (j * 8 + rl) * KP32 + base;
                    const uint32_t* kl = Kl32 + (j * 8 + rl) * KP32 + base;
                    uint32_t b0h = kh[0], b1h = kh[4];
                    uint32_t b0l = kl[0], b1l = kl[4];
                    mma_bf16(sacc[j], ah, b0h, b1h);
                    mma_bf16(sacc[j], al, b0h, b1h);
                    mma_bf16(sacc[j], ah, b0l, b1l);
                }
            }
        }

        __syncthreads();       // all warps done reading K_t
        if (t + 1 < nkt) {
            flash_load_k(sb, kbh + (size_t)(t + 1) * FBN * DHd,
                         kbl + (size_t)(t + 1) * FBN * DHd);
            CP_COMMIT();
        }

        if (active) {
            const int R_lo = rowbase + rl;
            const int R_hi = R_lo + 8;
            const bool needmask = (k0 + FBN - 1) > rowbase;
            float tl = -1e30f, th = -1e30f;
#pragma unroll
            for (int j = 0; j < 8; j++) {
#pragma unroll
                for (int r = 0; r < 4; r++) sacc[j][r] *= SCALE;
                if (needmask) {
                    const int C = k0 + j * 8 + 2 * q4;
                    if (C > R_lo)     sacc[j][0] = -1e30f;
                    if (C + 1 > R_lo) sacc[j][1] = -1e30f;
                    if (C > R_hi)     sacc[j][2] = -1e30f;
                    if (C + 1 > R_hi) sacc[j][3] = -1e30f;
                }
                tl = fmaxf(tl, fmaxf(sacc[j][0], sacc[j][1]));
                th = fmaxf(th, fmaxf(sacc[j][2], sacc[j][3]));
            }
            tl = fmaxf(tl, __shfl_xor_sync(0xffffffffu, tl, 1));
            tl = fmaxf(tl, __shfl_xor_sync(0xffffffffu, tl, 2));
            th = fmaxf(th, __shfl_xor_sync(0xffffffffu, th, 1));
            th = fmaxf(th, __shfl_xor_sync(0xffffffffu, th, 2));

            const float mn_lo = fmaxf(m_lo, tl);
            const float mn_hi = fmaxf(m_hi, th);
            const float a_lo = __expf(m_lo - mn_lo);
            const float a_hi = __expf(m_hi - mn_hi);
            m_lo = mn_lo; m_hi = mn_hi;

            float sum_lo = 0.f, sum_hi = 0.f;
            uint32_t* prl_h = Ph32 + (w * 16 + rl) * PP32;
            uint32_t* prl_l = Pl32 + (w * 16 + rl) * PP32;
#pragma unroll
            for (int j = 0; j < 8; j++) {
                float p0 = __expf(sacc[j][0] - mn_lo);
                float p1 = __expf(sacc[j][1] - mn_lo);
                float p2 = __expf(sacc[j][2] - mn_hi);
                float p3 = __expf(sacc[j][3] - mn_hi);
                sum_lo += p0 + p1;
                sum_hi += p2 + p3;
                uint32_t hh, ll;
                bf16_split2(p0, p1, hh, ll);
                prl_h[j * 4 + q4] = hh;
                prl_l[j * 4 + q4] = ll;
                bf16_split2(p2, p3, hh, ll);
                prl_h[8 * PP32 + j * 4 + q4] = hh;
                prl_l[8 * PP32 + j * 4 + q4] = ll;
            }
            sum_lo += __shfl_xor_sync(0xffffffffu, sum_lo, 1);
            sum_lo += __shfl_xor_sync(0xffffffffu, sum_lo, 2);
            sum_hi += __shfl_xor_sync(0xffffffffu, sum_hi, 1);
            sum_hi += __shfl_xor_sync(0xffffffffu, sum_hi, 2);
            l_lo = l_lo * a_lo + sum_lo;
            l_hi = l_hi * a_hi + sum_hi;

#pragma unroll
            for (int nt = 0; nt < 16; nt++) {
                o[nt][0] *= a_lo; o[nt][1] *= a_lo;
                o[nt][2] *= a_hi; o[nt][3] *= a_hi;
            }
            __syncwarp();

            // O += P @ V  (3-pass bf16), V buffer t&1
            const uint32_t* Vh32 = (const uint32_t*)(smc + F_V0H + (uint32_t)(t & 1) * F_VSTR);
            const uint32_t* Vl32 = (const uint32_t*)((const char*)Vh32 + F_VLO);
#pragma unroll
            for (int ks = 0; ks < 4; ks++) {
                const int base = ks * 8 + q4;
                const uint32_t* ph_ = Ph32 + (w * 16 + rl) * PP32 + base;
                const uint32_t* pl_ = Pl32 + (w * 16 + rl) * PP32 + base;
                uint32_t ph[4], pl[4];
                ph[0] = ph_[0]; ph[1] = ph_[8 * PP32]; ph[2] = ph_[4]; ph[3] = ph_[8 * PP32 + 4];
                pl[0] = pl_[0]; pl[1] = pl_[8 * PP32]; pl[2] = pl_[4]; pl[3] = pl_[8 * PP32 + 4];
#pragma unroll
                for (int nt = 0; nt < 16; nt++) {
                    const uint32_t* vh = Vh32 + (nt * 8 + rl) * VP32 + base;
                    const uint32_t* vl = Vl32 + (nt * 8 + rl) * VP32 + base;
                    uint32_t b0h = vh[0], b1h = vh[4];
                    uint32_t b0l = vl[0], b1l = vl[4];
                    mma_bf16(o[nt], ph, b0h, b1h);
                    mma_bf16(o[nt], pl, b0h, b1h);
                    mma_bf16(o[nt], ph, b0l, b1l);
                }
            }
        }
    }

    // Epilogue: divide by l, split, write att hi/lo [B,T,D]
    const float il_lo = 1.f / l_lo;
    const float il_hi = 1.f / l_hi;
    __nv_bfloat16* oh = g_atth + ((size_t)(b * Tt + rowbase)) * Dd + h * DHd;
    __nv_bfloat16* ol = g_attl + ((size_t)(b * Tt + rowbase)) * Dd + h * DHd;
#pragma unroll
    for (int nt = 0; nt < 16; nt++) {
        uint32_t hh, ll;
        size_t idx0 = (size_t)rl * Dd + nt * 8 + 2 * q4;
        bf16_split2(o[nt][0] * il_lo, o[nt][1] * il_lo, hh, ll);
        *(uint32_t*)(oh + idx0) = hh;
        *(uint32_t*)(ol + idx0) = ll;
        size_t idx1 = (size_t)(rl + 8) * Dd + nt * 8 + 2 * q4;
        bf16_split2(o[nt][2] * il_hi, o[nt][3] * il_hi, hh, ll);
        *(uint32_t*)(oh + idx1) = hh;
        *(uint32_t*)(ol + idx1) = ll;
    }
}

// ===========================================================================
extern "C" void kernel_launch(void* const* d_in, const int* in_sizes, int n_in,
                              void* d_out, int out_size)
{
    const float* x  = (const float*)d_in[0];
    const float* Wq = (const float*)d_in[1];
    const float* bq = (const float*)d_in[2];
    const float* Wk = (const float*)d_in[3];
    const float* bk = (const float*)d_in[4];
    const float* Wv = (const float*)d_in[5];
    const float* bv = (const float*)d_in[6];
    const float* Wo = (const float*)d_in[7];
    const float* bo = (const float*)d_in[8];
    float* out = (float*)d_out;

    __nv_bfloat16 *xh, *xl, *wth, *wtl, *atth, *attl;
    cudaGetSymbolAddress((void**)&xh,   g_xh);
    cudaGetSymbolAddress((void**)&xl,   g_xl);
    cudaGetSymbolAddress((void**)&wth,  g_wth);
    cudaGetSymbolAddress((void**)&wtl,  g_wtl);
    cudaGetSymbolAddress((void**)&atth, g_atth);
    cudaGetSymbolAddress((void**)&attl, g_attl);

    // 1) Convert inputs to bf16 hi/lo (x natural, all 4 W transposed, fused)
    conv_x_kernel<<<(Mm * Dd) / 1024, 256>>>(x, xh, xl);
    dim3 wgrid(Dd / 32, Dd / 32, 4);
    conv_w_all<<<wgrid, dim3(32, 8)>>>(Wq, Wk, Wv, Wo, wth, wtl);

    cudaFuncSetAttribute(gemm_qkv, cudaFuncAttributeMaxDynamicSharedMemorySize, GEMM_SMEM);
    cudaFuncSetAttribute(gemm_out, cudaFuncAttributeMaxDynamicSharedMemorySize, GEMM_SMEM);

    // 2) Fused QKV projections (one launch, one tail)
    dim3 qkvgrid(Dd / GBN, Mm / GBM, 3);   // (16, 64, 3)
    gemm_qkv<<<qkvgrid, 256, GEMM_SMEM>>>(xh, xl, wth, wtl, bq, bk, bv);

    // 3) Flash attention
    cudaFuncSetAttribute(flash_tc, cudaFuncAttributeMaxDynamicSharedMemorySize, FLASH_SMEM);
    dim3 fgrid(Tt / FBM, Hh, Bq);          // (16, 16, 4)
    flash_tc<<<fgrid, 256, FLASH_SMEM>>>();

    // 4) Output projection (fp32 out)
    dim3 ogrid(Dd / GBN, Mm / GBM);        // (16, 64)
    gemm_out<<<ogrid, 256, GEMM_SMEM>>>(atth, attl, wth + 3 * (size_t)Dd * Dd,
                                        wtl + 3 * (size_t)Dd * Dd, bo, out);
}

// round 11
// speedup vs baseline: 3.8266x; 1.0108x over previous
#include <cuda_runtime.h>
#include <cuda_bf16.h>
#include <math_constants.h>
#include <cstdint>

#define Bq  4
#define Tt  2048
#define Dd  2048
#define Hh  16
#define DHd 128
#define Mm  (Bq * Tt)        // 8192
#define SCALE 0.08838834764831845f  // DH^-0.5

// ---------------------------------------------------------------------------
// Persistent bf16 hi/lo tensors (allocation-free rule: __device__ globals)
// ---------------------------------------------------------------------------
__device__ __align__(256) __nv_bfloat16 g_xh[Mm * Dd];
__device__ __align__(256) __nv_bfloat16 g_xl[Mm * Dd];
__device__ __align__(256) __nv_bfloat16 g_wth[4][Dd * Dd];   // W^T hi, [N][K]
__device__ __align__(256) __nv_bfloat16 g_wtl[4][Dd * Dd];   // W^T lo
__device__ __align__(256) __nv_bfloat16 g_qh[Bq * Hh * Tt * DHd];
__device__ __align__(256) __nv_bfloat16 g_ql[Bq * Hh * Tt * DHd];
__device__ __align__(256) __nv_bfloat16 g_kh[Bq * Hh * Tt * DHd];
__device__ __align__(256) __nv_bfloat16 g_kl[Bq * Hh * Tt * DHd];
__device__ __align__(256) __nv_bfloat16 g_vth[Bq * Hh * DHd * Tt];  // [b,h,d,t]
__device__ __align__(256) __nv_bfloat16 g_vtl[Bq * Hh * DHd * Tt];
__device__ __align__(256) __nv_bfloat16 g_atth[Bq * Tt * Dd];
__device__ __align__(256) __nv_bfloat16 g_attl[Bq * Tt * Dd];

// ===========================================================================
// Helpers
// ===========================================================================
__device__ __forceinline__ uint32_t smem_u32(const void* p) {
    uint32_t a;
    asm("{ .reg .u64 t; cvta.to.shared.u64 t, %1; cvt.u32.u64 %0, t; }" : "=r"(a) : "l"(p));
    return a;
}
__device__ __forceinline__ void cp16(uint32_t dst, const void* src) {
    asm volatile("cp.async.cg.shared.global [%0], [%1], 16;" :: "r"(dst), "l"(src));
}
#define CP_COMMIT() asm volatile("cp.async.commit_group;" ::: "memory")
#define CP_WAIT0()  asm volatile("cp.async.wait_group 0;" ::: "memory")
#define CP_WAIT1()  asm volatile("cp.async.wait_group 1;" ::: "memory")

__device__ __forceinline__ void mma_bf16(float* c, const uint32_t* a,
                                         uint32_t b0, uint32_t b1) {
    asm volatile(
        "mma.sync.aligned.m16n8k16.row.col.f32.bf16.bf16.f32 "
        "{%0,%1,%2,%3}, {%4,%5,%6,%7}, {%8,%9}, {%0,%1,%2,%3};"
        : "+f"(c[0]), "+f"(c[1]), "+f"(c[2]), "+f"(c[3])
        : "r"(a[0]), "r"(a[1]), "r"(a[2]), "r"(a[3]), "r"(b0), "r"(b1));
}
__device__ __forceinline__ void ldsm_x4(uint32_t* r, uint32_t addr) {
    asm volatile("ldmatrix.sync.aligned.m8n8.x4.shared.b16 {%0,%1,%2,%3}, [%4];"
        : "=r"(r[0]), "=r"(r[1]), "=r"(r[2]), "=r"(r[3]) : "r"(addr));
}
__device__ __forceinline__ uint32_t pack_bf16(float v0, float v1) {
    uint32_t h;
    asm("cvt.rn.bf16x2.f32 %0, %1, %2;" : "=r"(h) : "f"(v1), "f"(v0));
    return h;
}
// Split pair of fp32 into bf16x2 hi + bf16x2 residual (lower 16 bits = v0)
__device__ __forceinline__ void bf16_split2(float v0, float v1,
                                            uint32_t& hi, uint32_t& lo) {
    uint32_t h = pack_bf16(v0, v1);
    float f0 = __uint_as_float(h << 16);
    float f1 = __uint_as_float(h & 0xffff0000u);
    lo = pack_bf16(v0 - f0, v1 - f1);
    hi = h;
}

// ===========================================================================
// Conversion kernels
// ===========================================================================
__global__ __launch_bounds__(256)
void conv_x_kernel(const float* __restrict__ src,
                   __nv_bfloat16* __restrict__ hi, __nv_bfloat16* __restrict__ lo)
{
    const size_t i4 = ((size_t)blockIdx.x * 256 + threadIdx.x) * 4;
    float4 v = *(const float4*)(src + i4);
    uint32_t h0, l0, h1, l1;
    bf16_split2(v.x, v.y, h0, l0);
    bf16_split2(v.z, v.w, h1, l1);
    *(uint2*)(hi + i4) = make_uint2(h0, h1);
    *(uint2*)(lo + i4) = make_uint2(l0, l1);
}

// Transpose all 4 W [K][N] -> W^T [N][K], split to bf16 hi/lo. gridDim.z = 4.
__global__ __launch_bounds__(256)
void conv_w_all(const float* __restrict__ W0, const float* __restrict__ W1,
                const float* __restrict__ W2, const float* __restrict__ W3,
                __nv_bfloat16* __restrict__ Th, __nv_bfloat16* __restrict__ Tl)
{
    const int z = blockIdx.z;
    const float* W = (z == 0) ? W0 : (z == 1) ? W1 : (z == 2) ? W2 : W3;
    __nv_bfloat16* th = Th + (size_t)z * Dd * Dd;
    __nv_bfloat16* tl = Tl + (size_t)z * Dd * Dd;

    __shared__ float tile[32][33];
    int x = blockIdx.x * 32 + threadIdx.x;
    int y = blockIdx.y * 32 + threadIdx.y;
#pragma unroll
    for (int j = 0; j < 32; j += 8)
        tile[threadIdx.y + j][threadIdx.x] = W[(size_t)(y + j) * Dd + x];
    __syncthreads();
    int n = blockIdx.x * 32 + threadIdx.y;
    int k = blockIdx.y * 32 + threadIdx.x;
#pragma unroll
    for (int j = 0; j < 32; j += 8) {
        float v = tile[threadIdx.x][threadIdx.y + j];
        __nv_bfloat16 h = __float2bfloat16(v);
        __nv_bfloat16 l = __float2bfloat16(v - __bfloat162float(h));
        th[(size_t)(n + j) * Dd + k] = h;
        tl[(size_t)(n + j) * Dd + k] = l;
    }
}

// ===========================================================================
// bf16 hi/lo tensor-core GEMM core. BM=BN=128, BK=32, 8 warps (2x4),
// warp tile 64x32. 3-stage cp.async ring (96KB) at 2 CTAs/SM.
// Dense 64B rows + 16B-chunk XOR swizzle; all fragments via ldmatrix x4.
// ===========================================================================
#define GBM 128
#define GBN 128
#define GBK 32
#define TILEB 8192                    // 128 rows * 64B
#define STAGEB (4 * TILEB)            // 32768: Ah|Al|Bh|Bl
#define GEMM_SMEM (3 * STAGEB)        // 98304 -> 2 CTAs/SM

__device__ __forceinline__ void load_stage(uint32_t sdst,
        const __nv_bfloat16* __restrict__ Ah, const __nv_bfloat16* __restrict__ Al,
        const __nv_bfloat16* __restrict__ Bh, const __nv_bfloat16* __restrict__ Bl,
        int m0, int n0, int k0)
{
    const int tid = threadIdx.x;
#pragma unroll
    for (int l = 0; l < 2; l++) {
        int e = tid + 256 * l;
        int r = e >> 2, c = e & 3;
        int cp_ = c ^ ((r >> 1) & 3);
        uint32_t doff = (uint32_t)(r * 64 + cp_ * 16);
        size_t soff = (size_t)(m0 + r) * Dd + k0 + c * 8;
        cp16(sdst + doff, Ah + soff);
        cp16(sdst + TILEB + doff, Al + soff);
    }
#pragma unroll
    for (int l = 0; l < 2; l++) {
        int e = tid + 256 * l;
        int r = e >> 2, c = e & 3;
        int cp_ = c ^ ((r >> 1) & 3);
        uint32_t doff = (uint32_t)(r * 64 + cp_ * 16);
        size_t soff = (size_t)(n0 + r) * Dd + k0 + c * 8;
        cp16(sdst + 2 * TILEB + doff, Bh + soff);
        cp16(sdst + 3 * TILEB + doff, Bl + soff);
    }
}

__device__ __forceinline__ void gemm_mainloop(
        uint32_t sbase,
        const __nv_bfloat16* __restrict__ Ah, const __nv_bfloat16* __restrict__ Al,
        const __nv_bfloat16* __restrict__ Bth, const __nv_bfloat16* __restrict__ Btl,
        int m0, int n0, float acc[4][4][4])
{
    const int lane = threadIdx.x & 31;
    const int wid  = threadIdx.x >> 5;
    const int wm = wid >> 2, wn = wid & 3;
    const int lr = lane & 7, g = lane >> 3;
    const int swz = (lr >> 1) & 3;
    // A x4: m0=rows g&1? mapping: m0 rows 0-7, m1 rows 8-15, m2 rows 0-7 col+,
    // m3 rows 8-15 col+ -> row = (g&1)*8+lr, colhalf = g>>1
    const uint32_t arow = (uint32_t)((wm * 64 + (g & 1) * 8 + lr) * 64);
    const int akh = g >> 1;
    // B x4 (pairs of j): m0,m1 = (b0,b1) of j-even; m2,m3 of j-odd
    // row = (g>>1)*8+lr, colhalf = g&1
    const uint32_t brow = (uint32_t)((wn * 32 + (g >> 1) * 8 + lr) * 64);
    const int bkh = g & 1;

    load_stage(sbase, Ah, Al, Bth, Btl, m0, n0, 0);
    CP_COMMIT();
    load_stage(sbase + STAGEB, Ah, Al, Bth, Btl, m0, n0, GBK);
    CP_COMMIT();

    const int NITER = Dd / GBK;   // 64
    int cur = 0;
    for (int it = 0; it < NITER; it++) {
        CP_WAIT1();
        __syncthreads();
        const uint32_t Sb = sbase + (uint32_t)cur * STAGEB;
        if (it + 2 < NITER) {
            int pf = cur + 2; if (pf >= 3) pf -= 3;
            load_stage(sbase + (uint32_t)pf * STAGEB, Ah, Al, Bth, Btl,
                       m0, n0, (it + 2) * GBK);
            CP_COMMIT();
        }
#pragma unroll
        for (int ks = 0; ks < 2; ks++) {
            const uint32_t ca = (uint32_t)(((ks * 2 + akh) ^ swz) * 16);
            const uint32_t cb = (uint32_t)(((ks * 2 + bkh) ^ swz) * 16);
            uint32_t ah[4][4], al[4][4];
#pragma unroll
            for (int i = 0; i < 4; i++) {
                ldsm_x4(ah[i], Sb + arow + (uint32_t)(i * 1024) + ca);
                ldsm_x4(al[i], Sb + TILEB + arow + (uint32_t)(i * 1024) + ca);
            }
#pragma unroll
            for (int jj = 0; jj < 2; jj++) {
                uint32_t bh4[4], bl4[4];
                ldsm_x4(bh4, Sb + 2 * TILEB + brow + (uint32_t)(jj * 1024) + cb);
                ldsm_x4(bl4, Sb + 3 * TILEB + brow + (uint32_t)(jj * 1024) + cb);
#pragma unroll
                for (int i = 0; i < 4; i++) {
                    mma_bf16(acc[i][2 * jj], ah[i], bh4[0], bh4[1]);
                    mma_bf16(acc[i][2 * jj], al[i], bh4[0], bh4[1]);
                    mma_bf16(acc[i][2 * jj], ah[i], bl4[0], bl4[1]);
                    mma_bf16(acc[i][2 * jj + 1], ah[i], bh4[2], bh4[3]);
                    mma_bf16(acc[i][2 * jj + 1], al[i], bh4[2], bh4[3]);
                    mma_bf16(acc[i][2 * jj + 1], ah[i], bl4[2], bl4[3]);
                }
            }
        }
        cur++; if (cur >= 3) cur = 0;
    }
}

// Fused QKV projection: gridDim.z selects q/k/v weight + epilogue.
__global__ __launch_bounds__(256, 2)
void gemm_qkv(const __nv_bfloat16* __restrict__ xh, const __nv_bfloat16* __restrict__ xl,
              const __nv_bfloat16* __restrict__ wth, const __nv_bfloat16* __restrict__ wtl,
              const float* __restrict__ bq, const float* __restrict__ bk,
              const float* __restrict__ bv)
{
    extern __shared__ char smem[];
    const uint32_t sbase = smem_u32(smem);
    const int z = blockIdx.z;
    const __nv_bfloat16* Bth = wth + (size_t)z * Dd * Dd;
    const __nv_bfloat16* Btl = wtl + (size_t)z * Dd * Dd;
    const float* bias = (z == 0) ? bq : (z == 1) ? bk : bv;
    const int m0 = blockIdx.y * GBM;
    const int n0 = blockIdx.x * GBN;

    float acc[4][4][4];
#pragma unroll
    for (int i = 0; i < 4; i++)
#pragma unroll
        for (int j = 0; j < 4; j++)
#pragma unroll
            for (int r = 0; r < 4; r++) acc[i][j][r] = 0.f;

    gemm_mainloop(sbase, xh, xl, Bth, Btl, m0, n0, acc);

    const int lane = threadIdx.x & 31;
    const int wid  = threadIdx.x >> 5;
    const int q4 = lane & 3, g8 = lane >> 2;
    const int wm = wid >> 2, wn = wid & 3;
    const int mbase = m0 + wm * 64;
#pragma unroll
    for (int j = 0; j < 4; j++) {
        const int nc = wn * 32 + j * 8 + 2 * q4;
        const float bx = bias[n0 + nc];
        const float by = bias[n0 + nc + 1];
#pragma unroll
        for (int i = 0; i < 4; i++) {
#pragma unroll
            for (int half = 0; half < 2; half++) {
                const int m = mbase + i * 16 + g8 + half * 8;
                float vx = acc[i][j][half * 2]     + bx;
                float vy = acc[i][j][half * 2 + 1] + by;
                const int h = n0 >> 7;
                const int b = m >> 11;
                const int t = m & 2047;
                if (z == 2) {
                    size_t base = ((size_t)(b * Hh + h) * DHd + nc) * Tt + t;
                    __nv_bfloat16 h0 = __float2bfloat16(vx);
                    __nv_bfloat16 h1 = __float2bfloat16(vy);
                    g_vth[base]       = h0;
                    g_vth[base + Tt]  = h1;
                    g_vtl[base]       = __float2bfloat16(vx - __bfloat162float(h0));
                    g_vtl[base + Tt]  = __float2bfloat16(vy - __bfloat162float(h1));
                } else {
                    __nv_bfloat16* dh = (z == 0) ? g_qh : g_kh;
                    __nv_bfloat16* dl = (z == 0) ? g_ql : g_kl;
                    size_t base = ((size_t)((b * Hh + h) * Tt) + t) * DHd + nc;
                    uint32_t hh, ll;
                    bf16_split2(vx, vy, hh, ll);
                    *(uint32_t*)(dh + base) = hh;
                    *(uint32_t*)(dl + base) = ll;
                }
            }
        }
    }
}

// Output projection: fp32 row-major result.
__global__ __launch_bounds__(256, 2)
void gemm_out(const __nv_bfloat16* __restrict__ Ah, const __nv_bfloat16* __restrict__ Al,
              const __nv_bfloat16* __restrict__ Bth, const __nv_bfloat16* __restrict__ Btl,
              const float* __restrict__ bias, float* __restrict__ Cout)
{
    extern __shared__ char smem[];
    const uint32_t sbase = smem_u32(smem);
    const int m0 = blockIdx.y * GBM;
    const int n0 = blockIdx.x * GBN;

    float acc[4][4][4];
#pragma unroll
    for (int i = 0; i < 4; i++)
#pragma unroll
        for (int j = 0; j < 4; j++)
#pragma unroll
            for (int r = 0; r < 4; r++) acc[i][j][r] = 0.f;

    gemm_mainloop(sbase, Ah, Al, Bth, Btl, m0, n0, acc);

    const int lane = threadIdx.x & 31;
    const int wid  = threadIdx.x >> 5;
    const int q4 = lane & 3, g8 = lane >> 2;
    const int wm = wid >> 2, wn = wid & 3;
    const int mbase = m0 + wm * 64;
#pragma unroll
    for (int j = 0; j < 4; j++) {
        const int nc = wn * 32 + j * 8 + 2 * q4;
        const float bx = bias[n0 + nc];
        const float by = bias[n0 + nc + 1];
#pragma unroll
        for (int i = 0; i < 4; i++) {
#pragma unroll
            for (int half = 0; half < 2; half++) {
                const int m = mbase + i * 16 + g8 + half * 8;
                *(float2*)(Cout + (size_t)m * Dd + n0 + nc) =
                    make_float2(acc[i][j][half * 2] + bx, acc[i][j][half * 2 + 1] + by);
            }
        }
    }
}

// ===========================================================================
// Flash attention (causal), bf16 hi/lo, 3-pass MMA, online softmax.
// BM=128 (8 warps x 16 rows), BN=64, DH=128, 256 threads.
// V double-buffered, K single-buffered. All fragments via ldmatrix x4
// (pitches 272B / 144B == 16 mod 128 -> conflict-free).
// ===========================================================================
#define FBM 128
#define FBN 64
#define QP32 68     // u32 pitch (136 bf16, 272B)
#define KP32 68
#define VP32 36     // 72 bf16, 144B
#define PP32 36
#define F_QH   0u
#define F_QL   34816u
#define F_KH   69632u
#define F_KL   87040u
#define F_V0H  104448u
#define F_VLO  18432u      // lo offset within a V buffer
#define F_VSTR 36864u      // stride between V buffers
#define F_PH   178176u
#define F_PL   196608u
#define FLASH_SMEM 215040

__device__ __forceinline__ void flash_load_q(uint32_t sb,
        const __nv_bfloat16* __restrict__ qh, const __nv_bfloat16* __restrict__ ql) {
    const int tid = threadIdx.x;
#pragma unroll
    for (int l = 0; l < 8; l++) {
        int e = tid + l * 256;
        int r = e >> 4, c = e & 15;
        uint32_t doff = (uint32_t)(r * 272 + c * 16);
        cp16(sb + F_QH + doff, qh + r * 128 + c * 8);
        cp16(sb + F_QL + doff, ql + r * 128 + c * 8);
    }
}
__device__ __forceinline__ void flash_load_k(uint32_t sb,
        const __nv_bfloat16* __restrict__ kh, const __nv_bfloat16* __restrict__ kl) {
    const int tid = threadIdx.x;
#pragma unroll
    for (int l = 0; l < 4; l++) {
        int e = tid + l * 256;
        int r = e >> 4, c = e & 15;
        uint32_t doff = (uint32_t)(r * 272 + c * 16);
        cp16(sb + F_KH + doff, kh + r * 128 + c * 8);
        cp16(sb + F_KL + doff, kl + r * 128 + c * 8);
    }
}
__device__ __forceinline__ void flash_load_v(uint32_t dsth,
        const __nv_bfloat16* __restrict__ vh, const __nv_bfloat16* __restrict__ vl) {
    const int tid = threadIdx.x;
#pragma unroll
    for (int l = 0; l < 4; l++) {
        int e = tid + l * 256;
        int r = e >> 3, c = e & 7;
        uint32_t doff = (uint32_t)(r * 144 + c * 16);
        cp16(dsth + doff, vh + (size_t)r * Tt + c * 8);
        cp16(dsth + F_VLO + doff, vl + (size_t)r * Tt + c * 8);
    }
}

__global__ __launch_bounds__(256, 1)
void flash_tc()
{
    extern __shared__ char smc[];
    const uint32_t sb = smem_u32(smc);
    const int qb = (gridDim.x - 1) - blockIdx.x;    // longest-job-first
    const int h  = blockIdx.y;
    const int b  = blockIdx.z;
    const int q0 = qb * FBM;
    const int tid  = threadIdx.x;
    const int w    = tid >> 5;
    const int lane = tid & 31;
    const int q4   = lane & 3;
    const int rl   = lane >> 2;
    const int lr   = lane & 7;
    const int g    = lane >> 3;

    uint32_t* Ph32 = (uint32_t*)(smc + F_PH);
    uint32_t* Pl32 = (uint32_t*)(smc + F_PL);

    // ldmatrix base addresses
    const uint32_t qAddr = sb + F_QH + (uint32_t)((w * 16 + (g & 1) * 8 + lr) * 272 + (g >> 1) * 16);
    const uint32_t kAddr = sb + F_KH + (uint32_t)(((g >> 1) * 8 + lr) * 272 + (g & 1) * 16);
    const uint32_t pAddr = sb + F_PH + (uint32_t)((w * 16 + (g & 1) * 8 + lr) * 144 + (g >> 1) * 16);
    const uint32_t vAddrOff = (uint32_t)(((g >> 1) * 8 + lr) * 144 + (g & 1) * 16);

    const size_t bh = (size_t)(b * Hh + h) * Tt;
    const __nv_bfloat16* kbh = g_kh + bh * DHd;
    const __nv_bfloat16* kbl = g_kl + bh * DHd;
    const __nv_bfloat16* vbh = g_vth + (size_t)(b * Hh + h) * DHd * Tt;
    const __nv_bfloat16* vbl = g_vtl + (size_t)(b * Hh + h) * DHd * Tt;

    flash_load_q(sb, g_qh + (bh + q0) * DHd, g_ql + (bh + q0) * DHd);
    flash_load_k(sb, kbh, kbl);
    flash_load_v(sb + F_V0H, vbh, vbl);
    CP_COMMIT();

    float m_lo = -1e30f, m_hi = -1e30f, l_lo = 0.f, l_hi = 0.f;
    float o[16][4];
#pragma unroll
    for (int nt = 0; nt < 16; nt++)
#pragma unroll
        for (int r = 0; r < 4; r++) o[nt][r] = 0.f;

    const int rowbase = q0 + w * 16;
    const int nkt = 2 * qb + 2;

    for (int t = 0; t < nkt; t++) {
        const int k0 = t * FBN;
        const bool active = (k0 <= rowbase + 15);
        CP_WAIT0();            // K_t and V_t ready
        __syncthreads();

        if (t + 1 < nkt) {
            flash_load_v(sb + F_V0H + (uint32_t)((t + 1) & 1) * F_VSTR,
                         vbh + (size_t)(t + 1) * FBN, vbl + (size_t)(t + 1) * FBN);
            CP_COMMIT();
        }

        float sacc[8][4];
        if (active) {
#pragma unroll
            for (int j = 0; j < 8; j++)
#pragma unroll
                for (int r = 0; r < 4; r++) sacc[j][r] = 0.f;

#pragma unroll
            for (int ks = 0; ks < 8; ks++) {
                uint32_t ah[4], al[4];
                ldsm_x4(ah, qAddr + (uint32_t)(ks * 32));
                ldsm_x4(al, qAddr + (F_QL - F_QH) + (uint32_t)(ks * 32));
#pragma unroll
                for (int jj = 0; jj < 4; jj++) {
                    uint32_t bh4[4], bl4[4];
                    ldsm_x4(bh4, kAddr + (uint32_t)(jj * 16 * 272 + ks * 32));
                    ldsm_x4(bl4, kAddr + (F_KL - F_KH) + (uint32_t)(jj * 16 * 272 + ks * 32));
                    mma_bf16(sacc[2 * jj], ah, bh4[0], bh4[1]);
                    mma_bf16(sacc[2 * jj], al, bh4[0], bh4[1]);
                    mma_bf16(sacc[2 * jj], ah, bl4[0], bl4[1]);
                    mma_bf16(sacc[2 * jj + 1], ah, bh4[2], bh4[3]);
                    mma_bf16(sacc[2 * jj + 1], al, bh4[2], bh4[3]);
                    mma_bf16(sacc[2 * jj + 1], ah, bl4[2], bl4[3]);
                }
            }
        }

        __syncthreads();       // all warps done reading K_t
        if (t + 1 < nkt) {
            flash_load_k(sb, kbh + (size_t)(t + 1) * FBN * DHd,
                         kbl + (size_t)(t + 1) * FBN * DHd);
            CP_COMMIT();
        }

        if (active) {
            const int R_lo = rowbase + rl;
            const int R_hi = R_lo + 8;
            const bool needmask = (k0 + FBN - 1) > rowbase;
            float tl = -1e30f, th = -1e30f;
#pragma unroll
            for (int j = 0; j < 8; j++) {
#pragma unroll
                for (int r = 0; r < 4; r++) sacc[j][r] *= SCALE;
                if (needmask) {
                    const int C = k0 + j * 8 + 2 * q4;
                    if (C > R_lo)     sacc[j][0] = -1e30f;
                    if (C + 1 > R_lo) sacc[j][1] = -1e30f;
                    if (C > R_hi)     sacc[j][2] = -1e30f;
                    if (C + 1 > R_hi) sacc[j][3] = -1e30f;
                }
                tl = fmaxf(tl, fmaxf(sacc[j][0], sacc[j][1]));
                th = fmaxf(th, fmaxf(sacc[j][2], sacc[j][3]));
            }
            tl = fmaxf(tl, __shfl_xor_sync(0xffffffffu, tl, 1));
            tl = fmaxf(tl, __shfl_xor_sync(0xffffffffu, tl, 2));
            th = fmaxf(th, __shfl_xor_sync(0xffffffffu, th, 1));
            th = fmaxf(th, __shfl_xor_sync(0xffffffffu, th, 2));

            const float mn_lo = fmaxf(m_lo, tl);
            const float mn_hi = fmaxf(m_hi, th);
            const float a_lo = __expf(m_lo - mn_lo);
            const float a_hi = __expf(m_hi - mn_hi);
            m_lo = mn_lo; m_hi = mn_hi;

            float sum_lo = 0.f, sum_hi = 0.f;
            uint32_t* prl_h = Ph32 + (w * 16 + rl) * PP32;
            uint32_t* prl_l = Pl32 + (w * 16 + rl) * PP32;
#pragma unroll
            for (int j = 0; j < 8; j++) {
                float p0 = __expf(sacc[j][0] - mn_lo);
                float p1 = __expf(sacc[j][1] - mn_lo);
                float p2 = __expf(sacc[j][2] - mn_hi);
                float p3 = __expf(sacc[j][3] - mn_hi);
                sum_lo += p0 + p1;
                sum_hi += p2 + p3;
                uint32_t hh, ll;
                bf16_split2(p0, p1, hh, ll);
                prl_h[j * 4 + q4] = hh;
                prl_l[j * 4 + q4] = ll;
                bf16_split2(p2, p3, hh, ll);
                prl_h[8 * PP32 + j * 4 + q4] = hh;
                prl_l[8 * PP32 + j * 4 + q4] = ll;
            }
            sum_lo += __shfl_xor_sync(0xffffffffu, sum_lo, 1);
            sum_lo += __shfl_xor_sync(0xffffffffu, sum_lo, 2);
            sum_hi += __shfl_xor_sync(0xffffffffu, sum_hi, 1);
            sum_hi += __shfl_xor_sync(0xffffffffu, sum_hi, 2);
            l_lo = l_lo * a_lo + sum_lo;
            l_hi = l_hi * a_hi + sum_hi;

#pragma unroll
            for (int nt = 0; nt < 16; nt++) {
                o[nt][0] *= a_lo; o[nt][1] *= a_lo;
                o[nt][2] *= a_hi; o[nt][3] *= a_hi;
            }
            __syncwarp();

            // O += P @ V  (3-pass bf16), V buffer t&1, all ldmatrix
            const uint32_t vAddr = sb + F_V0H + (uint32_t)(t & 1) * F_VSTR + vAddrOff;
#pragma unroll
            for (int ks = 0; ks < 4; ks++) {
                uint32_t ph4[4], pl4[4];
                ldsm_x4(ph4, pAddr + (uint32_t)(ks * 32));
                ldsm_x4(pl4, pAddr + (F_PL - F_PH) + (uint32_t)(ks * 32));
#pragma unroll
                for (int ntp = 0; ntp < 8; ntp++) {
                    uint32_t vh4[4], vl4[4];
                    ldsm_x4(vh4, vAddr + (uint32_t)(ntp * 16 * 144 + ks * 32));
                    ldsm_x4(vl4, vAddr + F_VLO + (uint32_t)(ntp * 16 * 144 + ks * 32));
                    mma_bf16(o[2 * ntp], ph4, vh4[0], vh4[1]);
                    mma_bf16(o[2 * ntp], pl4, vh4[0], vh4[1]);
                    mma_bf16(o[2 * ntp], ph4, vl4[0], vl4[1]);
                    mma_bf16(o[2 * ntp + 1], ph4, vh4[2], vh4[3]);
                    mma_bf16(o[2 * ntp + 1], pl4, vh4[2], vh4[3]);
                    mma_bf16(o[2 * ntp + 1], ph4, vl4[2], vl4[3]);
                }
            }
        }
    }

    // Epilogue: divide by l, split, write att hi/lo [B,T,D]
    const float il_lo = 1.f / l_lo;
    const float il_hi = 1.f / l_hi;
    __nv_bfloat16* oh = g_atth + ((size_t)(b * Tt + rowbase)) * Dd + h * DHd;
    __nv_bfloat16* ol = g_attl + ((size_t)(b * Tt + rowbase)) * Dd + h * DHd;
#pragma unroll
    for (int nt = 0; nt < 16; nt++) {
        uint32_t hh, ll;
        size_t idx0 = (size_t)rl * Dd + nt * 8 + 2 * q4;
        bf16_split2(o[nt][0] * il_lo, o[nt][1] * il_lo, hh, ll);
        *(uint32_t*)(oh + idx0) = hh;
        *(uint32_t*)(ol + idx0) = ll;
        size_t idx1 = (size_t)(rl + 8) * Dd + nt * 8 + 2 * q4;
        bf16_split2(o[nt][2] * il_hi, o[nt][3] * il_hi, hh, ll);
        *(uint32_t*)(oh + idx1) = hh;
        *(uint32_t*)(ol + idx1) = ll;
    }
}

// ===========================================================================
extern "C" void kernel_launch(void* const* d_in, const int* in_sizes, int n_in,
                              void* d_out, int out_size)
{
    const float* x  = (const float*)d_in[0];
    const float* Wq = (const float*)d_in[1];
    const float* bq = (const float*)d_in[2];
    const float* Wk = (const float*)d_in[3];
    const float* bk = (const float*)d_in[4];
    const float* Wv = (const float*)d_in[5];
    const float* bv = (const float*)d_in[6];
    const float* Wo = (const float*)d_in[7];
    const float* bo = (const float*)d_in[8];
    float* out = (float*)d_out;

    __nv_bfloat16 *xh, *xl, *wth, *wtl, *atth, *attl;
    cudaGetSymbolAddress((void**)&xh,   g_xh);
    cudaGetSymbolAddress((void**)&xl,   g_xl);
    cudaGetSymbolAddress((void**)&wth,  g_wth);
    cudaGetSymbolAddress((void**)&wtl,  g_wtl);
    cudaGetSymbolAddress((void**)&atth, g_atth);
    cudaGetSymbolAddress((void**)&attl, g_attl);

    // 1) Convert inputs to bf16 hi/lo (x natural, all 4 W transposed, fused)
    conv_x_kernel<<<(Mm * Dd) / 1024, 256>>>(x, xh, xl);
    dim3 wgrid(Dd / 32, Dd / 32, 4);
    conv_w_all<<<wgrid, dim3(32, 8)>>>(Wq, Wk, Wv, Wo, wth, wtl);

    cudaFuncSetAttribute(gemm_qkv, cudaFuncAttributeMaxDynamicSharedMemorySize, GEMM_SMEM);
    cudaFuncSetAttribute(gemm_out, cudaFuncAttributeMaxDynamicSharedMemorySize, GEMM_SMEM);

    // 2) Fused QKV projections (one launch, one tail)
    dim3 qkvgrid(Dd / GBN, Mm / GBM, 3);   // (16, 64, 3)
    gemm_qkv<<<qkvgrid, 256, GEMM_SMEM>>>(xh, xl, wth, wtl, bq, bk, bv);

    // 3) Flash attention
    cudaFuncSetAttribute(flash_tc, cudaFuncAttributeMaxDynamicSharedMemorySize, FLASH_SMEM);
    dim3 fgrid(Tt / FBM, Hh, Bq);          // (16, 16, 4)
    flash_tc<<<fgrid, 256, FLASH_SMEM>>>();

    // 4) Output projection (fp32 out)
    dim3 ogrid(Dd / GBN, Mm / GBM);        // (16, 64)
    gemm_out<<<ogrid, 256, GEMM_SMEM>>>(atth, attl, wth + 3 * (size_t)Dd * Dd,
                                        wtl + 3 * (size_t)Dd * Dd, bo, out);
}